// round 8
// baseline (speedup 1.0000x reference)
#include <cuda_runtime.h>
#include <cuda_bf16.h>
#include <cstdint>

#define NNODES 20000
#define NPAD   20096            // 157 * 128
#define MCOLS  1024
#define NEDGE  640000
#define DD     256
#define NB     79               // ceil(20000/256)
#define EB     2500             // ceil(640000/256)

// ---------------- scratch (__device__ globals; zero-initialized bss) ----------------
__device__ float g_colemb[MCOLS * DD];
__device__ float g_h0[NPAD * 768];              // batched layer-0 output (3 branches)
__device__ float g_hh[3 * NPAD * DD];           // per-branch GEMM outputs
__device__ float g_br0[NPAD * DD];
__device__ float g_br1[NPAD * DD];
__device__ float g_br2[NPAD * DD];
__device__ float g_deg[3 * NNODES];
__device__ float g_dinv[3 * NNODES];
__device__ int   g_hist[3 * NNODES];
__device__ int   g_cur[3 * NNODES];
__device__ int   g_start[3 * (NNODES + 1)];
__device__ int   g_src[3 * NEDGE];
__device__ float g_nrm[3 * NEDGE];
// x0-as-GEMM operands
__device__ __nv_bfloat16 g_mask[NPAD * MCOLS];  // bf16 0/1 mask (padded rows stay 0)
__device__ float g_rcnt[NPAD];                  // 1/max(cnt,1) (padded rows 0)
__device__ __nv_bfloat16 g_colTh[DD * MCOLS];
__device__ __nv_bfloat16 g_colTl[DD * MCOLS];
// packed bf16 hi/lo planes
__device__ __nv_bfloat16 g_x0h[NPAD * DD];
__device__ __nv_bfloat16 g_x0l[NPAD * DD];
__device__ __nv_bfloat16 g_xhb[3 * NPAD * DD];  // per-branch
__device__ __nv_bfloat16 g_xlb[3 * NPAD * DD];
// transposed bf16 hi/lo weights, l-major: index w' = l*3+b, each [n=256][k=256]
__device__ __nv_bfloat16 g_Wh[9 * DD * DD];
__device__ __nv_bfloat16 g_Wl[9 * DD * DD];

// ================= shared MMA helpers =================
#define KC 64
#define PITCH 36      // uint32 words per smem row (32 kpairs + 4 pad)

__device__ __forceinline__ void mma_bf16(float* c, const uint32_t* a, const uint32_t* b) {
    asm volatile(
        "mma.sync.aligned.m16n8k16.row.col.f32.bf16.bf16.f32 "
        "{%0,%1,%2,%3}, {%4,%5,%6,%7}, {%8,%9}, {%0,%1,%2,%3};"
        : "+f"(c[0]), "+f"(c[1]), "+f"(c[2]), "+f"(c[3])
        : "r"(a[0]), "r"(a[1]), "r"(a[2]), "r"(a[3]), "r"(b[0]), "r"(b[1]));
}
__device__ __forceinline__ void ldsm4(uint32_t* r, uint32_t addr) {
    asm volatile("ldmatrix.sync.aligned.m8n8.x4.shared.b16 {%0,%1,%2,%3}, [%4];"
        : "=r"(r[0]), "=r"(r[1]), "=r"(r[2]), "=r"(r[3]) : "r"(addr));
}
__device__ __forceinline__ void cp16(uint32_t smem_dst, const void* gsrc) {
    asm volatile("cp.async.cg.shared.global [%0], [%1], 16;" :: "r"(smem_dst), "l"(gsrc));
}
__device__ __forceinline__ uint32_t packsplit(float v0, float v1, uint32_t& lo) {
    __nv_bfloat162 h, l;
    h.x = __float2bfloat16(v0); h.y = __float2bfloat16(v1);
    l.x = __float2bfloat16(v0 - __bfloat162float(h.x));
    l.y = __float2bfloat16(v1 - __bfloat162float(h.y));
    lo = *reinterpret_cast<uint32_t*>(&l);
    return *reinterpret_cast<uint32_t*>(&h);
}

// ================= device fn: split-bf16 HMMA GEMM (128x128 tile) =================
__device__ void dev_gemm(const __nv_bfloat16* __restrict__ Ah_g,
                         const __nv_bfloat16* __restrict__ Al_g,
                         const __nv_bfloat16* __restrict__ Bh_g,
                         const __nv_bfloat16* __restrict__ Bl_g,
                         float* __restrict__ C, int cstride,
                         int bmIdx, int bnIdx, uint32_t* smem) {
    uint32_t* sAh = smem;
    uint32_t* sAl = smem + 128 * PITCH;
    uint32_t* sBh = smem + 2 * 128 * PITCH;
    uint32_t* sBl = smem + 3 * 128 * PITCH;

    int tid = threadIdx.x;
    int lane = tid & 31, wid = tid >> 5;
    int g = lane >> 2, tig = lane & 3;
    int wm = wid & 1, wn = wid >> 1;
    int bm = bmIdx * 128;
    int bn = bnIdx * 128;

    uint32_t sAh_a = (uint32_t)__cvta_generic_to_shared(sAh);
    uint32_t sAl_a = (uint32_t)__cvta_generic_to_shared(sAl);
    uint32_t sBh_a = (uint32_t)__cvta_generic_to_shared(sBh);
    uint32_t sBl_a = (uint32_t)__cvta_generic_to_shared(sBl);

    int lane15 = lane & 15;
    int khalf = lane >> 4;
    uint32_t A_loff = (uint32_t)((wm * 64 + lane15) * PITCH) * 4u + (uint32_t)khalf * 16u;
    int bnrow = wn * 32 + (lane >> 4) * 8 + (lane & 7);
    uint32_t B_loff = (uint32_t)(bnrow * PITCH) * 4u + (uint32_t)((lane >> 3) & 1) * 16u;

    float acc[4][4][4];
#pragma unroll
    for (int mt = 0; mt < 4; mt++)
#pragma unroll
        for (int nt = 0; nt < 4; nt++)
#pragma unroll
            for (int q = 0; q < 4; q++) acc[mt][nt][q] = 0.f;

    for (int k0 = 0; k0 < DD; k0 += KC) {
#pragma unroll
        for (int i = 0; i < 4; i++) {
            int sl = tid + i * 256;
            int row = sl >> 3;
            int s = sl & 7;
            uint32_t so = (uint32_t)(row * PITCH + s * 4) * 4u;
            size_t ga = (size_t)(bm + row) * DD + k0 + s * 8;
            size_t gb = (size_t)(bn + row) * DD + k0 + s * 8;
            cp16(sAh_a + so, Ah_g + ga);
            cp16(sAl_a + so, Al_g + ga);
            cp16(sBh_a + so, Bh_g + gb);
            cp16(sBl_a + so, Bl_g + gb);
        }
        asm volatile("cp.async.commit_group;");
        asm volatile("cp.async.wait_group 0;");
        __syncthreads();

#pragma unroll
        for (int ks = 0; ks < 4; ks++) {
            uint32_t koff = (uint32_t)ks * 32u;
            uint32_t Bh[4][2], Bl[4][2];
#pragma unroll
            for (int ntp = 0; ntp < 2; ntp++) {
                uint32_t r[4];
                uint32_t off = B_loff + (uint32_t)(ntp * 16 * PITCH) * 4u + koff;
                ldsm4(r, sBh_a + off);
                Bh[2 * ntp][0] = r[0]; Bh[2 * ntp][1] = r[1];
                Bh[2 * ntp + 1][0] = r[2]; Bh[2 * ntp + 1][1] = r[3];
                ldsm4(r, sBl_a + off);
                Bl[2 * ntp][0] = r[0]; Bl[2 * ntp][1] = r[1];
                Bl[2 * ntp + 1][0] = r[2]; Bl[2 * ntp + 1][1] = r[3];
            }
#pragma unroll
            for (int mt = 0; mt < 4; mt++) {
                uint32_t off = A_loff + (uint32_t)(mt * 16 * PITCH) * 4u + koff;
                uint32_t Ah[4], Al[4];
                ldsm4(Ah, sAh_a + off);
                ldsm4(Al, sAl_a + off);
#pragma unroll
                for (int nt = 0; nt < 4; nt++) {
                    mma_bf16(acc[mt][nt], Ah, Bh[nt]);
                    mma_bf16(acc[mt][nt], Al, Bh[nt]);
                    mma_bf16(acc[mt][nt], Ah, Bl[nt]);
                }
            }
        }
        __syncthreads();
    }

#pragma unroll
    for (int mt = 0; mt < 4; mt++) {
        int row = bm + wm * 64 + mt * 16 + g;
#pragma unroll
        for (int nt = 0; nt < 4; nt++) {
            int col = bn + wn * 32 + nt * 8 + tig * 2;
            *(float2*)&C[(size_t)row * cstride + col] = make_float2(acc[mt][nt][0], acc[mt][nt][1]);
            *(float2*)&C[(size_t)(row + 8) * cstride + col] = make_float2(acc[mt][nt][2], acc[mt][nt][3]);
        }
    }
}

__global__ void __launch_bounds__(256, 2) gemm_mma2(
    const __nv_bfloat16* __restrict__ Ah_g, const __nv_bfloat16* __restrict__ Al_g,
    const __nv_bfloat16* __restrict__ Bh_g, const __nv_bfloat16* __restrict__ Bl_g,
    float* __restrict__ C, int cstride) {
    extern __shared__ uint32_t smem[];
    dev_gemm(Ah_g, Al_g, Bh_g, Bl_g, C, cstride, blockIdx.x, blockIdx.y, smem);
}

// ================= device fn: x0 GEMM (mask @ colembT, 2 passes) =================
__device__ void dev_x0gemm(const __nv_bfloat16* __restrict__ Am,
                           const __nv_bfloat16* __restrict__ Bh_g,
                           const __nv_bfloat16* __restrict__ Bl_g,
                           const float* __restrict__ rcnt,
                           __nv_bfloat16* __restrict__ xh, __nv_bfloat16* __restrict__ xl,
                           int bmIdx, int bnIdx, uint32_t* smem) {
    uint32_t* sA  = smem;
    uint32_t* sBh = smem + 128 * PITCH;
    uint32_t* sBl = smem + 2 * 128 * PITCH;

    int tid = threadIdx.x;
    int lane = tid & 31, wid = tid >> 5;
    int g = lane >> 2, tig = lane & 3;
    int wm = wid & 1, wn = wid >> 1;
    int bm = bmIdx * 128;
    int bn = bnIdx * 128;

    uint32_t sA_a  = (uint32_t)__cvta_generic_to_shared(sA);
    uint32_t sBh_a = (uint32_t)__cvta_generic_to_shared(sBh);
    uint32_t sBl_a = (uint32_t)__cvta_generic_to_shared(sBl);

    int lane15 = lane & 15;
    int khalf = lane >> 4;
    uint32_t A_loff = (uint32_t)((wm * 64 + lane15) * PITCH) * 4u + (uint32_t)khalf * 16u;
    int bnrow = wn * 32 + (lane >> 4) * 8 + (lane & 7);
    uint32_t B_loff = (uint32_t)(bnrow * PITCH) * 4u + (uint32_t)((lane >> 3) & 1) * 16u;

    float acc[4][4][4];
#pragma unroll
    for (int mt = 0; mt < 4; mt++)
#pragma unroll
        for (int nt = 0; nt < 4; nt++)
#pragma unroll
            for (int q = 0; q < 4; q++) acc[mt][nt][q] = 0.f;

    for (int k0 = 0; k0 < MCOLS; k0 += KC) {
#pragma unroll
        for (int i = 0; i < 4; i++) {
            int sl = tid + i * 256;
            int row = sl >> 3;
            int s = sl & 7;
            uint32_t so = (uint32_t)(row * PITCH + s * 4) * 4u;
            size_t ga = (size_t)(bm + row) * MCOLS + k0 + s * 8;
            size_t gb = (size_t)(bn + row) * MCOLS + k0 + s * 8;
            cp16(sA_a + so, Am + ga);
            cp16(sBh_a + so, Bh_g + gb);
            cp16(sBl_a + so, Bl_g + gb);
        }
        asm volatile("cp.async.commit_group;");
        asm volatile("cp.async.wait_group 0;");
        __syncthreads();

#pragma unroll
        for (int ks = 0; ks < 4; ks++) {
            uint32_t koff = (uint32_t)ks * 32u;
            uint32_t Bh[4][2], Bl[4][2];
#pragma unroll
            for (int ntp = 0; ntp < 2; ntp++) {
                uint32_t r[4];
                uint32_t off = B_loff + (uint32_t)(ntp * 16 * PITCH) * 4u + koff;
                ldsm4(r, sBh_a + off);
                Bh[2 * ntp][0] = r[0]; Bh[2 * ntp][1] = r[1];
                Bh[2 * ntp + 1][0] = r[2]; Bh[2 * ntp + 1][1] = r[3];
                ldsm4(r, sBl_a + off);
                Bl[2 * ntp][0] = r[0]; Bl[2 * ntp][1] = r[1];
                Bl[2 * ntp + 1][0] = r[2]; Bl[2 * ntp + 1][1] = r[3];
            }
#pragma unroll
            for (int mt = 0; mt < 4; mt++) {
                uint32_t off = A_loff + (uint32_t)(mt * 16 * PITCH) * 4u + koff;
                uint32_t Af[4];
                ldsm4(Af, sA_a + off);
#pragma unroll
                for (int nt = 0; nt < 4; nt++) {
                    mma_bf16(acc[mt][nt], Af, Bh[nt]);
                    mma_bf16(acc[mt][nt], Af, Bl[nt]);
                }
            }
        }
        __syncthreads();
    }

#pragma unroll
    for (int mt = 0; mt < 4; mt++) {
        int row = bm + wm * 64 + mt * 16 + g;
        float rc0 = rcnt[row];
        float rc1 = rcnt[row + 8];
#pragma unroll
        for (int nt = 0; nt < 4; nt++) {
            int col = bn + wn * 32 + nt * 8 + tig * 2;
            uint32_t lo;
            uint32_t hi = packsplit(acc[mt][nt][0] * rc0, acc[mt][nt][1] * rc0, lo);
            *reinterpret_cast<uint32_t*>(&xh[(size_t)row * DD + col]) = hi;
            *reinterpret_cast<uint32_t*>(&xl[(size_t)row * DD + col]) = lo;
            hi = packsplit(acc[mt][nt][2] * rc1, acc[mt][nt][3] * rc1, lo);
            *reinterpret_cast<uint32_t*>(&xh[(size_t)(row + 8) * DD + col]) = hi;
            *reinterpret_cast<uint32_t*>(&xl[(size_t)(row + 8) * DD + col]) = lo;
        }
    }
}

// ================= device fn: aggregation, 4 nodes per 256-thread block =================
__device__ void dev_agg4(const float* __restrict__ h, int hstride,
                         const int* __restrict__ src, const float* __restrict__ nrm,
                         const int* __restrict__ start, const float* __restrict__ dinv,
                         const float* __restrict__ bias, float* __restrict__ out,
                         __nv_bfloat16* __restrict__ xh, __nv_bfloat16* __restrict__ xl,
                         int pack, int wf32, int nodeBase) {
    int sub = threadIdx.x >> 6;
    int t = threadIdx.x & 63;
    int i = nodeBase + sub;
    if (i >= NNODES) return;
    int s = start[i];
    int e = start[i + 1];
    float4 a0 = make_float4(0.f, 0.f, 0.f, 0.f);
    float4 a1 = make_float4(0.f, 0.f, 0.f, 0.f);
    float4 a2 = make_float4(0.f, 0.f, 0.f, 0.f);
    float4 a3 = make_float4(0.f, 0.f, 0.f, 0.f);
    int k = s;
    for (; k + 7 < e; k += 8) {
        int r0 = src[k], r1 = src[k + 1], r2 = src[k + 2], r3 = src[k + 3];
        int r4 = src[k + 4], r5 = src[k + 5], r6 = src[k + 6], r7 = src[k + 7];
        float w0 = nrm[k], w1 = nrm[k + 1], w2 = nrm[k + 2], w3 = nrm[k + 3];
        float w4 = nrm[k + 4], w5 = nrm[k + 5], w6 = nrm[k + 6], w7 = nrm[k + 7];
        float4 v0 = *(const float4*)&h[(size_t)r0 * hstride + t * 4];
        float4 v1 = *(const float4*)&h[(size_t)r1 * hstride + t * 4];
        float4 v2 = *(const float4*)&h[(size_t)r2 * hstride + t * 4];
        float4 v3 = *(const float4*)&h[(size_t)r3 * hstride + t * 4];
        float4 v4 = *(const float4*)&h[(size_t)r4 * hstride + t * 4];
        float4 v5 = *(const float4*)&h[(size_t)r5 * hstride + t * 4];
        float4 v6 = *(const float4*)&h[(size_t)r6 * hstride + t * 4];
        float4 v7 = *(const float4*)&h[(size_t)r7 * hstride + t * 4];
        a0.x += w0 * v0.x; a0.y += w0 * v0.y; a0.z += w0 * v0.z; a0.w += w0 * v0.w;
        a1.x += w1 * v1.x; a1.y += w1 * v1.y; a1.z += w1 * v1.z; a1.w += w1 * v1.w;
        a2.x += w2 * v2.x; a2.y += w2 * v2.y; a2.z += w2 * v2.z; a2.w += w2 * v2.w;
        a3.x += w3 * v3.x; a3.y += w3 * v3.y; a3.z += w3 * v3.z; a3.w += w3 * v3.w;
        a0.x += w4 * v4.x; a0.y += w4 * v4.y; a0.z += w4 * v4.z; a0.w += w4 * v4.w;
        a1.x += w5 * v5.x; a1.y += w5 * v5.y; a1.z += w5 * v5.z; a1.w += w5 * v5.w;
        a2.x += w6 * v6.x; a2.y += w6 * v6.y; a2.z += w6 * v6.z; a2.w += w6 * v6.w;
        a3.x += w7 * v7.x; a3.y += w7 * v7.y; a3.z += w7 * v7.z; a3.w += w7 * v7.w;
    }
    for (; k < e; k++) {
        int r = src[k];
        float w = nrm[k];
        float4 v = *(const float4*)&h[(size_t)r * hstride + t * 4];
        a0.x += w * v.x; a0.y += w * v.y; a0.z += w * v.z; a0.w += w * v.w;
    }
    float di = dinv[i];
    float sn = di * di;
    float4 hv = *(const float4*)&h[(size_t)i * hstride + t * 4];
    float4 bv = *(const float4*)&bias[t * 4];
    float4 acc;
    acc.x = a0.x + a1.x + a2.x + a3.x + sn * hv.x + bv.x;
    acc.y = a0.y + a1.y + a2.y + a3.y + sn * hv.y + bv.y;
    acc.z = a0.z + a1.z + a2.z + a3.z + sn * hv.z + bv.z;
    acc.w = a0.w + a1.w + a2.w + a3.w + sn * hv.w + bv.w;
    if (wf32) *(float4*)&out[(size_t)i * DD + t * 4] = acc;
    if (pack) {
        float r0 = fmaxf(acc.x, 0.f), r1 = fmaxf(acc.y, 0.f);
        float r2 = fmaxf(acc.z, 0.f), r3 = fmaxf(acc.w, 0.f);
        uint32_t lo0, lo1;
        uint32_t hi0 = packsplit(r0, r1, lo0);
        uint32_t hi1 = packsplit(r2, r3, lo1);
        uint2 hp, lp;
        hp.x = hi0; hp.y = hi1;
        lp.x = lo0; lp.y = lo1;
        reinterpret_cast<uint2*>(xh)[(size_t)i * 64 + t] = hp;
        reinterpret_cast<uint2*>(xl)[(size_t)i * 64 + t] = lp;
    }
}

// ================= pipeline step: agg(b,l) [+ gemm(b',l')] =================
__global__ void __launch_bounds__(256, 2) step_kernel(
    const float* __restrict__ h, int hstride, const int* __restrict__ src,
    const float* __restrict__ nrm, const int* __restrict__ start,
    const float* __restrict__ dinv, const float* __restrict__ bias,
    float* __restrict__ out, __nv_bfloat16* __restrict__ xh, __nv_bfloat16* __restrict__ xl,
    int pack, int wf32,
    const __nv_bfloat16* gAh, const __nv_bfloat16* gAl,
    const __nv_bfloat16* gBh, const __nv_bfloat16* gBl, float* gC) {
    if (blockIdx.x < 5000) {
        dev_agg4(h, hstride, src, nrm, start, dinv, bias, out, xh, xl, pack, wf32,
                 blockIdx.x * 4);
    } else {
        extern __shared__ uint32_t smem[];
        int gx = blockIdx.x - 5000;
        dev_gemm(gAh, gAl, gBh, gBl, gC, DD, gx >> 1, gx & 1, smem);
    }
}

// ================= fused front-end kernels =================
// F1: colemb (1024 blocks) + branch_init (237 blocks)
__global__ void f1_kernel(const float* __restrict__ pW1, const float* __restrict__ pb1,
                          const float* __restrict__ pW2, const float* __restrict__ pb2,
                          float* __restrict__ colemb,
                          float* __restrict__ deg, int* __restrict__ hist) {
    int tid = threadIdx.x;
    if (blockIdx.x < 1024) {
        int j = blockIdx.x;
        float jf = (float)j;
        float acc = pb2[tid];
#pragma unroll
        for (int k = 0; k < 16; k++) {
            float hk = fmaxf(jf * pW1[k] + pb1[k], 0.f);
            acc += hk * pW2[k * DD + tid];
        }
        colemb[j * DD + tid] = acc;
    } else {
        int idx = blockIdx.x - 1024;
        int b = idx / NB;
        int i = (idx % NB) * 256 + tid;
        if (i < NNODES) { deg[b * NNODES + i] = 1.0f; hist[b * NNODES + i] = 0; }
    }
}

// F2: maskbuild (20000 blocks) + edge_count (7500 blocks)
__global__ void f2_kernel(const float* __restrict__ init,
                          __nv_bfloat16* __restrict__ mask, float* __restrict__ rcnt,
                          const int* __restrict__ ei0, const int* __restrict__ ei1,
                          const int* __restrict__ ei2,
                          const float* __restrict__ ea0, const float* __restrict__ ea1,
                          const float* __restrict__ ea2,
                          float* __restrict__ deg, int* __restrict__ hist) {
    int t = threadIdx.x;
    if (blockIdx.x < NNODES) {
        int i = blockIdx.x;
        __shared__ int scnt;
        if (t == 0) scnt = 0;
        __syncthreads();
        float4 v = *(const float4*)&init[(size_t)i * MCOLS + t * 4];
        float m0 = (v.x != 0.f) ? 1.f : 0.f;
        float m1 = (v.y != 0.f) ? 1.f : 0.f;
        float m2 = (v.z != 0.f) ? 1.f : 0.f;
        float m3 = (v.w != 0.f) ? 1.f : 0.f;
        int c = (int)(m0 + m1 + m2 + m3);
#pragma unroll
        for (int o = 16; o; o >>= 1) c += __shfl_xor_sync(0xffffffffu, c, o);
        if ((t & 31) == 0) atomicAdd(&scnt, c);
        __nv_bfloat162 p01, p23;
        p01.x = __float2bfloat16(m0); p01.y = __float2bfloat16(m1);
        p23.x = __float2bfloat16(m2); p23.y = __float2bfloat16(m3);
        uint2 pk;
        pk.x = *reinterpret_cast<uint32_t*>(&p01);
        pk.y = *reinterpret_cast<uint32_t*>(&p23);
        *reinterpret_cast<uint2*>(&mask[(size_t)i * MCOLS + t * 4]) = pk;
        __syncthreads();
        if (t == 0) rcnt[i] = 1.f / (float)max(scnt, 1);
    } else {
        int idx = blockIdx.x - NNODES;
        int b = idx / EB;
        int e = (idx % EB) * 256 + t;
        const int* ei = (b == 0) ? ei0 : (b == 1) ? ei1 : ei2;
        const float* ea = (b == 0) ? ea0 : (b == 1) ? ea1 : ea2;
        if (e < NEDGE) {
            int c = ei[NEDGE + e];
            atomicAdd(&deg[b * NNODES + c], ea[e]);
            atomicAdd(&hist[b * NNODES + c], 1);
        }
    }
}

// F3: colembT (256) + wconv (576) + dinv (237)
__global__ void f3_kernel(const float* __restrict__ colemb,
                          __nv_bfloat16* __restrict__ Th, __nv_bfloat16* __restrict__ Tl,
                          const float* __restrict__ W0, const float* __restrict__ W1,
                          const float* __restrict__ W2,
                          __nv_bfloat16* __restrict__ Wh, __nv_bfloat16* __restrict__ Wl,
                          const float* __restrict__ deg, float* __restrict__ dinv) {
    int tid = threadIdx.x;
    int tx = tid & 31, ty = tid >> 5;   // 32 x 8
    __shared__ float tile[32][33];
    if (blockIdx.x < 256) {
        int idx = blockIdx.x;
        int j0 = (idx & 31) * 32, d0 = (idx >> 5) * 32;
#pragma unroll
        for (int i = 0; i < 32; i += 8)
            tile[ty + i][tx] = colemb[(size_t)(j0 + ty + i) * DD + d0 + tx];
        __syncthreads();
#pragma unroll
        for (int i = 0; i < 32; i += 8) {
            float v = tile[tx][ty + i];
            __nv_bfloat16 h = __float2bfloat16(v);
            size_t o = (size_t)(d0 + ty + i) * MCOLS + j0 + tx;
            Th[o] = h;
            Tl[o] = __float2bfloat16(v - __bfloat162float(h));
        }
    } else if (blockIdx.x < 256 + 576) {
        int idx = blockIdx.x - 256;
        int z = idx / 64;              // b*3 + l
        int r = idx % 64;
        int b = z / 3, l = z % 3;
        const float* W = (b == 0) ? W0 : (b == 1) ? W1 : W2;
        W += (size_t)l * DD * DD;
        size_t dbase = (size_t)(l * 3 + b) * DD * DD;
        int n0 = (r & 7) * 32, k0 = (r >> 3) * 32;
#pragma unroll
        for (int i = 0; i < 32; i += 8)
            tile[ty + i][tx] = W[(size_t)(k0 + ty + i) * DD + n0 + tx];
        __syncthreads();
#pragma unroll
        for (int i = 0; i < 32; i += 8) {
            float v = tile[tx][ty + i];
            __nv_bfloat16 h = __float2bfloat16(v);
            size_t o = dbase + (size_t)(n0 + ty + i) * DD + k0 + tx;
            Wh[o] = h;
            Wl[o] = __float2bfloat16(v - __bfloat162float(h));
        }
    } else {
        int idx = blockIdx.x - 832;
        int b = idx / NB;
        int i = (idx % NB) * 256 + tid;
        if (i < NNODES) dinv[b * NNODES + i] = rsqrtf(deg[b * NNODES + i]);
    }
}

// scan (standalone, 1024 threads, one block per branch)
__global__ void scan_kernel(const int* __restrict__ hist_g, int* __restrict__ start_g,
                            int* __restrict__ cur_g) {
    __shared__ int sm[1024];
    __shared__ int carry_s;
    int b = blockIdx.x;
    const int* hist = hist_g + b * NNODES;
    int* start = start_g + b * (NNODES + 1);
    int* cur = cur_g + b * NNODES;
    int t = threadIdx.x;
    if (t == 0) carry_s = 0;
    __syncthreads();
    for (int c0 = 0; c0 < NNODES; c0 += 1024) {
        int idx = c0 + t;
        int v = (idx < NNODES) ? hist[idx] : 0;
        sm[t] = v;
        __syncthreads();
        for (int off = 1; off < 1024; off <<= 1) {
            int x = (t >= off) ? sm[t - off] : 0;
            __syncthreads();
            sm[t] += x;
            __syncthreads();
        }
        int incl = sm[t];
        int base = carry_s;
        __syncthreads();
        if (t == 1023) carry_s = base + incl;
        int excl = base + incl - v;
        if (idx < NNODES) { start[idx] = excl; cur[idx] = excl; }
        __syncthreads();
    }
    if (t == 0) start[NNODES] = carry_s;
}

// F5: x0gemm (314) + scatter (7500)
__global__ void __launch_bounds__(256, 2) f5_kernel(
    const __nv_bfloat16* __restrict__ Am, const __nv_bfloat16* __restrict__ Bh_g,
    const __nv_bfloat16* __restrict__ Bl_g, const float* __restrict__ rcnt,
    __nv_bfloat16* __restrict__ xh, __nv_bfloat16* __restrict__ xl,
    const int* __restrict__ ei0, const int* __restrict__ ei1, const int* __restrict__ ei2,
    const float* __restrict__ ea0, const float* __restrict__ ea1, const float* __restrict__ ea2,
    const float* __restrict__ dinv, int* __restrict__ cur,
    int* __restrict__ src, float* __restrict__ nrm) {
    if (blockIdx.x < 314) {
        extern __shared__ uint32_t smem[];
        dev_x0gemm(Am, Bh_g, Bl_g, rcnt, xh, xl, blockIdx.x >> 1, blockIdx.x & 1, smem);
    } else {
        int idx = blockIdx.x - 314;
        int b = idx / EB;
        int e = (idx % EB) * 256 + threadIdx.x;
        const int* ei = (b == 0) ? ei0 : (b == 1) ? ei1 : ei2;
        const float* ea = (b == 0) ? ea0 : (b == 1) ? ea1 : ea2;
        if (e < NEDGE) {
            int r = ei[e];
            int c = ei[NEDGE + e];
            float n = dinv[b * NNODES + r] * ea[e] * dinv[b * NNODES + c];
            int p = atomicAdd(&cur[b * NNODES + c], 1);
            src[b * NEDGE + p] = r;
            nrm[b * NEDGE + p] = n;
        }
    }
}

// ---------------- meta-path attention ----------------
__global__ void attn_kernel(const float* __restrict__ b0, const float* __restrict__ b1,
                            const float* __restrict__ b2, const float* __restrict__ watt,
                            float* __restrict__ out) {
    int i = blockIdx.x;
    int t = threadIdx.x;  // 256
    size_t off = (size_t)i * DD + t;
    float x0v = fmaxf(b0[off], 0.f);
    float x1v = fmaxf(b1[off], 0.f);
    float x2v = fmaxf(b2[off], 0.f);
    float w = watt[t];
    float s0 = x0v * w, s1 = x1v * w, s2 = x2v * w;
#pragma unroll
    for (int o = 16; o; o >>= 1) {
        s0 += __shfl_xor_sync(0xffffffffu, s0, o);
        s1 += __shfl_xor_sync(0xffffffffu, s1, o);
        s2 += __shfl_xor_sync(0xffffffffu, s2, o);
    }
    __shared__ float sm[3][8];
    __shared__ float sw[3];
    int wid = t >> 5, ln = t & 31;
    if (ln == 0) { sm[0][wid] = s0; sm[1][wid] = s1; sm[2][wid] = s2; }
    __syncthreads();
    if (t == 0) {
        float t0 = 0.f, t1 = 0.f, t2 = 0.f;
#pragma unroll
        for (int kk = 0; kk < 8; kk++) { t0 += sm[0][kk]; t1 += sm[1][kk]; t2 += sm[2][kk]; }
        float mx = fmaxf(t0, fmaxf(t1, t2));
        float e0 = expf(t0 - mx), e1 = expf(t1 - mx), e2 = expf(t2 - mx);
        float inv = 1.f / (e0 + e1 + e2);
        sw[0] = e0 * inv; sw[1] = e1 * inv; sw[2] = e2 * inv;
    }
    __syncthreads();
    out[off] = sw[0] * x0v + sw[1] * x1v + sw[2] * x2v;
}

// ---------------- launcher ----------------
extern "C" void kernel_launch(void* const* d_in, const int* in_sizes, int n_in,
                              void* d_out, int out_size) {
    const float* init = (const float*)d_in[0];
    const int*   ei[3] = {(const int*)d_in[1], (const int*)d_in[2], (const int*)d_in[3]};
    const float* ea[3] = {(const float*)d_in[4], (const float*)d_in[5], (const float*)d_in[6]};
    const float* pW1 = (const float*)d_in[7];
    const float* pb1 = (const float*)d_in[8];
    const float* pW2 = (const float*)d_in[9];
    const float* pb2 = (const float*)d_in[10];
    const float* Wb[3] = {(const float*)d_in[11], (const float*)d_in[13], (const float*)d_in[15]};
    const float* bb[3] = {(const float*)d_in[12], (const float*)d_in[14], (const float*)d_in[16]};
    const float* watt = (const float*)d_in[17];
    float* out = (float*)d_out;

    float *colemb, *h0, *hh, *deg, *dinv, *nrm, *rcnt;
    float *br[3];
    int *hist, *cur, *start, *src;
    __nv_bfloat16 *x0h, *x0l, *xhb, *xlb, *Wh, *Wl, *mask, *colTh, *colTl;
    cudaGetSymbolAddress((void**)&colemb, g_colemb);
    cudaGetSymbolAddress((void**)&h0,     g_h0);
    cudaGetSymbolAddress((void**)&hh,     g_hh);
    cudaGetSymbolAddress((void**)&br[0],  g_br0);
    cudaGetSymbolAddress((void**)&br[1],  g_br1);
    cudaGetSymbolAddress((void**)&br[2],  g_br2);
    cudaGetSymbolAddress((void**)&deg,    g_deg);
    cudaGetSymbolAddress((void**)&dinv,   g_dinv);
    cudaGetSymbolAddress((void**)&hist,   g_hist);
    cudaGetSymbolAddress((void**)&cur,    g_cur);
    cudaGetSymbolAddress((void**)&start,  g_start);
    cudaGetSymbolAddress((void**)&src,    g_src);
    cudaGetSymbolAddress((void**)&nrm,    g_nrm);
    cudaGetSymbolAddress((void**)&rcnt,   g_rcnt);
    cudaGetSymbolAddress((void**)&mask,   g_mask);
    cudaGetSymbolAddress((void**)&colTh,  g_colTh);
    cudaGetSymbolAddress((void**)&colTl,  g_colTl);
    cudaGetSymbolAddress((void**)&x0h,    g_x0h);
    cudaGetSymbolAddress((void**)&x0l,    g_x0l);
    cudaGetSymbolAddress((void**)&xhb,    g_xhb);
    cudaGetSymbolAddress((void**)&xlb,    g_xlb);
    cudaGetSymbolAddress((void**)&Wh,     g_Wh);
    cudaGetSymbolAddress((void**)&Wl,     g_Wl);

    static int attr_set = 0;
    if (!attr_set) {
        cudaFuncSetAttribute(gemm_mma2, cudaFuncAttributeMaxDynamicSharedMemorySize, 73728);
        cudaFuncSetAttribute(step_kernel, cudaFuncAttributeMaxDynamicSharedMemorySize, 73728);
        cudaFuncSetAttribute(f5_kernel, cudaFuncAttributeMaxDynamicSharedMemorySize, 55296);
        attr_set = 1;
    }

    // front end
    f1_kernel<<<1024 + 3 * NB, 256>>>(pW1, pb1, pW2, pb2, colemb, deg, hist);
    f2_kernel<<<NNODES + 3 * EB, 256>>>(init, mask, rcnt, ei[0], ei[1], ei[2],
                                        ea[0], ea[1], ea[2], deg, hist);
    f3_kernel<<<256 + 576 + 3 * NB, 256>>>(colemb, colTh, colTl, Wb[0], Wb[1], Wb[2],
                                           Wh, Wl, deg, dinv);
    scan_kernel<<<3, 1024>>>(hist, start, cur);
    f5_kernel<<<314 + 3 * EB, 256, 55296>>>(mask, colTh, colTl, rcnt, x0h, x0l,
                                            ei[0], ei[1], ei[2], ea[0], ea[1], ea[2],
                                            dinv, cur, src, nrm);

    // layer-0 GEMM batched across branches (Wh l-major: w'=0,1,2 contiguous [768][256])
    gemm_mma2<<<dim3(157, 6), 256, 73728>>>(x0h, x0l, Wh, Wl, h0, 768);

    // pipeline: agg(b,l) fused with gemm(b',l') of another branch
    // {aggB, aggL, gemmB, gemmL}
    const int sched[9][4] = {
        {0, 0, -1, -1}, {1, 0, 0, 1}, {2, 0, 1, 1},
        {0, 1, 2, 1},   {1, 1, 0, 2}, {2, 1, 1, 2},
        {0, 2, 2, 2},   {1, 2, -1, -1}, {2, 2, -1, -1}};
    for (int s = 0; s < 9; s++) {
        int ab = sched[s][0], al = sched[s][1];
        int gb = sched[s][2], gl = sched[s][3];
        const float* ah = (al == 0) ? (h0 + ab * DD) : (hh + (size_t)ab * NPAD * DD);
        int hstride = (al == 0) ? 768 : DD;
        int pack = (al < 2), wf32 = (al == 2);
        const __nv_bfloat16 *gAh = nullptr, *gAl = nullptr, *gBh = nullptr, *gBl = nullptr;
        float* gC = nullptr;
        int nblk = 5000, smem = 0;
        if (gb >= 0) {
            gAh = xhb + (size_t)gb * NPAD * DD;
            gAl = xlb + (size_t)gb * NPAD * DD;
            gBh = Wh + (size_t)(gl * 3 + gb) * DD * DD;
            gBl = Wl + (size_t)(gl * 3 + gb) * DD * DD;
            gC = hh + (size_t)gb * NPAD * DD;
            nblk = 5000 + 314;
            smem = 73728;
        }
        step_kernel<<<nblk, 256, smem>>>(
            ah, hstride, src + ab * NEDGE, nrm + ab * NEDGE, start + ab * (NNODES + 1),
            dinv + ab * NNODES, bb[ab] + al * DD, br[ab],
            xhb + (size_t)ab * NPAD * DD, xlb + (size_t)ab * NPAD * DD, pack, wf32,
            gAh, gAl, gBh, gBl, gC);
    }

    attn_kernel<<<NNODES, 256>>>(br[0], br[1], br[2], watt, out);
}

// round 9
// speedup vs baseline: 1.4178x; 1.4178x over previous
#include <cuda_runtime.h>
#include <cuda_bf16.h>
#include <cstdint>

#define NNODES 20000
#define NPAD   20096            // 157 * 128
#define MCOLS  1024
#define NEDGE  640000
#define DD     256
#define NB     79               // ceil(20000/256)
#define EB     2500             // ceil(640000/256)

// ---------------- scratch (__device__ globals; zero-initialized bss) ----------------
__device__ float g_colemb[MCOLS * DD];
__device__ float g_h0[NPAD * 768];              // batched layer-0 output (3 branches)
__device__ float g_hh[3 * NPAD * DD];           // per-branch GEMM outputs
__device__ float g_br0[NPAD * DD];
__device__ float g_br1[NPAD * DD];
__device__ float g_br2[NPAD * DD];
__device__ float g_deg[3 * NNODES];
__device__ float g_dinv[3 * NNODES];
__device__ int   g_hist[3 * NNODES];
__device__ int   g_cur[3 * NNODES];
__device__ int   g_start[3 * (NNODES + 1)];
__device__ int   g_bsum[3 * NB];
__device__ int   g_bbase[3 * NB];
__device__ int   g_src[3 * NEDGE];
__device__ float g_nrm[3 * NEDGE];
// x0-as-GEMM operands
__device__ __nv_bfloat16 g_mask[NPAD * MCOLS];
__device__ float g_rcnt[NPAD];
__device__ __nv_bfloat16 g_colTh[DD * MCOLS];
__device__ __nv_bfloat16 g_colTl[DD * MCOLS];
// packed bf16 hi/lo planes
__device__ __nv_bfloat16 g_x0h[NPAD * DD];
__device__ __nv_bfloat16 g_x0l[NPAD * DD];
__device__ __nv_bfloat16 g_xhb[3 * NPAD * DD];  // per-branch
__device__ __nv_bfloat16 g_xlb[3 * NPAD * DD];
// transposed bf16 hi/lo weights, l-major: index w' = l*3+b, each [n=256][k=256]
__device__ __nv_bfloat16 g_Wh[9 * DD * DD];
__device__ __nv_bfloat16 g_Wl[9 * DD * DD];

// ================= shared MMA helpers =================
#define KC 64
#define PITCH 36      // uint32 words per smem row (32 kpairs + 4 pad)

__device__ __forceinline__ void mma_bf16(float* c, const uint32_t* a, const uint32_t* b) {
    asm volatile(
        "mma.sync.aligned.m16n8k16.row.col.f32.bf16.bf16.f32 "
        "{%0,%1,%2,%3}, {%4,%5,%6,%7}, {%8,%9}, {%0,%1,%2,%3};"
        : "+f"(c[0]), "+f"(c[1]), "+f"(c[2]), "+f"(c[3])
        : "r"(a[0]), "r"(a[1]), "r"(a[2]), "r"(a[3]), "r"(b[0]), "r"(b[1]));
}
__device__ __forceinline__ void ldsm4(uint32_t* r, uint32_t addr) {
    asm volatile("ldmatrix.sync.aligned.m8n8.x4.shared.b16 {%0,%1,%2,%3}, [%4];"
        : "=r"(r[0]), "=r"(r[1]), "=r"(r[2]), "=r"(r[3]) : "r"(addr));
}
__device__ __forceinline__ void cp16(uint32_t smem_dst, const void* gsrc) {
    asm volatile("cp.async.cg.shared.global [%0], [%1], 16;" :: "r"(smem_dst), "l"(gsrc));
}
__device__ __forceinline__ uint32_t packsplit(float v0, float v1, uint32_t& lo) {
    __nv_bfloat162 h, l;
    h.x = __float2bfloat16(v0); h.y = __float2bfloat16(v1);
    l.x = __float2bfloat16(v0 - __bfloat162float(h.x));
    l.y = __float2bfloat16(v1 - __bfloat162float(h.y));
    lo = *reinterpret_cast<uint32_t*>(&l);
    return *reinterpret_cast<uint32_t*>(&h);
}

// ---------------- front-end kernels ----------------
__global__ void colemb_kernel(const float* __restrict__ pW1, const float* __restrict__ pb1,
                              const float* __restrict__ pW2, const float* __restrict__ pb2,
                              float* __restrict__ colemb) {
    int j = blockIdx.x;
    int d = threadIdx.x;
    float jf = (float)j;
    float acc = pb2[d];
#pragma unroll
    for (int k = 0; k < 16; k++) {
        float hk = fmaxf(jf * pW1[k] + pb1[k], 0.f);
        acc += hk * pW2[k * DD + d];
    }
    colemb[j * DD + d] = acc;
}

__global__ void maskbuild_kernel(const float* __restrict__ init,
                                 __nv_bfloat16* __restrict__ mask, float* __restrict__ rcnt) {
    int i = blockIdx.x;
    int t = threadIdx.x;  // 256, 4 cols each
    __shared__ int scnt;
    if (t == 0) scnt = 0;
    __syncthreads();
    float4 v = *(const float4*)&init[(size_t)i * MCOLS + t * 4];
    float m0 = (v.x != 0.f) ? 1.f : 0.f;
    float m1 = (v.y != 0.f) ? 1.f : 0.f;
    float m2 = (v.z != 0.f) ? 1.f : 0.f;
    float m3 = (v.w != 0.f) ? 1.f : 0.f;
    int c = (int)(m0 + m1 + m2 + m3);
#pragma unroll
    for (int o = 16; o; o >>= 1) c += __shfl_xor_sync(0xffffffffu, c, o);
    if ((t & 31) == 0) atomicAdd(&scnt, c);
    __nv_bfloat162 p01, p23;
    p01.x = __float2bfloat16(m0); p01.y = __float2bfloat16(m1);
    p23.x = __float2bfloat16(m2); p23.y = __float2bfloat16(m3);
    uint2 pk;
    pk.x = *reinterpret_cast<uint32_t*>(&p01);
    pk.y = *reinterpret_cast<uint32_t*>(&p23);
    *reinterpret_cast<uint2*>(&mask[(size_t)i * MCOLS + t * 4]) = pk;
    __syncthreads();
    if (t == 0) rcnt[i] = 1.f / (float)max(scnt, 1);
}

__global__ void colembT_kernel(const float* __restrict__ colemb,
                               __nv_bfloat16* __restrict__ Th, __nv_bfloat16* __restrict__ Tl) {
    __shared__ float tile[32][33];
    int j0 = blockIdx.x * 32, d0 = blockIdx.y * 32;
    int tx = threadIdx.x, ty = threadIdx.y;  // 32 x 8
#pragma unroll
    for (int i = 0; i < 32; i += 8)
        tile[ty + i][tx] = colemb[(size_t)(j0 + ty + i) * DD + d0 + tx];
    __syncthreads();
#pragma unroll
    for (int i = 0; i < 32; i += 8) {
        float v = tile[tx][ty + i];
        __nv_bfloat16 h = __float2bfloat16(v);
        size_t o = (size_t)(d0 + ty + i) * MCOLS + j0 + tx;
        Th[o] = h;
        Tl[o] = __float2bfloat16(v - __bfloat162float(h));
    }
}

__global__ void wconv_kernel(const float* __restrict__ W0, const float* __restrict__ W1,
                             const float* __restrict__ W2,
                             __nv_bfloat16* __restrict__ Ht, __nv_bfloat16* __restrict__ Lt) {
    __shared__ float tile[32][33];
    int z = blockIdx.z;           // b*3 + l
    int b = z / 3, l = z % 3;
    const float* W = (b == 0) ? W0 : (b == 1) ? W1 : W2;
    W += (size_t)l * DD * DD;
    size_t dbase = (size_t)(l * 3 + b) * DD * DD;
    int n0 = blockIdx.x * 32, k0 = blockIdx.y * 32;
    int tx = threadIdx.x, ty = threadIdx.y;  // 32 x 8
#pragma unroll
    for (int i = 0; i < 32; i += 8)
        tile[ty + i][tx] = W[(size_t)(k0 + ty + i) * DD + n0 + tx];
    __syncthreads();
#pragma unroll
    for (int i = 0; i < 32; i += 8) {
        float v = tile[tx][ty + i];
        __nv_bfloat16 h = __float2bfloat16(v);
        size_t o = dbase + (size_t)(n0 + ty + i) * DD + k0 + tx;
        Ht[o] = h;
        Lt[o] = __float2bfloat16(v - __bfloat162float(h));
    }
}

// ---------------- graph prep (grid.z = branch) ----------------
__global__ void branch_init(float* __restrict__ deg, int* __restrict__ hist) {
    int i = blockIdx.x * blockDim.x + threadIdx.x;
    int b = blockIdx.z;
    if (i < NNODES) { deg[b * NNODES + i] = 1.0f; hist[b * NNODES + i] = 0; }
}

__global__ void edge_count(const int* __restrict__ ei0, const int* __restrict__ ei1,
                           const int* __restrict__ ei2,
                           const float* __restrict__ ea0, const float* __restrict__ ea1,
                           const float* __restrict__ ea2,
                           float* __restrict__ deg, int* __restrict__ hist) {
    int e = blockIdx.x * blockDim.x + threadIdx.x;
    int b = blockIdx.z;
    const int* ei = (b == 0) ? ei0 : (b == 1) ? ei1 : ei2;
    const float* ea = (b == 0) ? ea0 : (b == 1) ? ea1 : ea2;
    if (e < NEDGE) {
        int c = ei[NEDGE + e];
        atomicAdd(&deg[b * NNODES + c], ea[e]);
        atomicAdd(&hist[b * NNODES + c], 1);
    }
}

__global__ void dinv_kernel(const float* __restrict__ deg, float* __restrict__ dinv) {
    int i = blockIdx.x * blockDim.x + threadIdx.x;
    int b = blockIdx.z;
    if (i < NNODES) dinv[b * NNODES + i] = rsqrtf(deg[b * NNODES + i]);
}

// ---- 3-phase exclusive scan over hist (per branch) ----
__global__ void scanP1(const int* __restrict__ hist, int* __restrict__ bsum) {
    int bid = blockIdx.x;        // 3*NB
    int b = bid / NB, blk = bid % NB;
    int t = threadIdx.x;         // 256
    int gi = blk * 256 + t;
    int v = (gi < NNODES) ? hist[b * NNODES + gi] : 0;
#pragma unroll
    for (int o = 16; o; o >>= 1) v += __shfl_xor_sync(0xffffffffu, v, o);
    __shared__ int ws[8];
    if ((t & 31) == 0) ws[t >> 5] = v;
    __syncthreads();
    if (t == 0) {
        int s = 0;
#pragma unroll
        for (int w = 0; w < 8; w++) s += ws[w];
        bsum[b * NB + blk] = s;
    }
}
__global__ void scanP2(const int* __restrict__ bsum, int* __restrict__ bbase,
                       int* __restrict__ start) {
    int t = threadIdx.x;
    if (t < 3) {
        int s = 0;
        for (int i = 0; i < NB; i++) {
            bbase[t * NB + i] = s;
            s += bsum[t * NB + i];
        }
        start[t * (NNODES + 1) + NNODES] = s;
    }
}
__global__ void scanP3(const int* __restrict__ hist, const int* __restrict__ bbase,
                       int* __restrict__ start, int* __restrict__ cur) {
    int bid = blockIdx.x;
    int b = bid / NB, blk = bid % NB;
    int t = threadIdx.x;
    int lane = t & 31, w = t >> 5;
    int gi = blk * 256 + t;
    int v = (gi < NNODES) ? hist[b * NNODES + gi] : 0;
    int s = v;
#pragma unroll
    for (int o = 1; o < 32; o <<= 1) {
        int x = __shfl_up_sync(0xffffffffu, s, o);
        if (lane >= o) s += x;
    }
    __shared__ int ws[8];
    if (lane == 31) ws[w] = s;
    __syncthreads();
    if (t == 0) {
        int acc = 0;
#pragma unroll
        for (int i = 0; i < 8; i++) { int x = ws[i]; ws[i] = acc; acc += x; }
    }
    __syncthreads();
    int excl = s - v + ws[w] + bbase[b * NB + blk];
    if (gi < NNODES) {
        start[b * (NNODES + 1) + gi] = excl;
        cur[b * NNODES + gi] = excl;
    }
}

__global__ void scatter_kernel(const int* __restrict__ ei0, const int* __restrict__ ei1,
                               const int* __restrict__ ei2,
                               const float* __restrict__ ea0, const float* __restrict__ ea1,
                               const float* __restrict__ ea2,
                               const float* __restrict__ dinv, int* __restrict__ cur,
                               int* __restrict__ src, float* __restrict__ nrm) {
    int e = blockIdx.x * blockDim.x + threadIdx.x;
    int b = blockIdx.z;
    const int* ei = (b == 0) ? ei0 : (b == 1) ? ei1 : ei2;
    const float* ea = (b == 0) ? ea0 : (b == 1) ? ea1 : ea2;
    if (e < NEDGE) {
        int r = ei[e];
        int c = ei[NEDGE + e];
        float n = dinv[b * NNODES + r] * ea[e] * dinv[b * NNODES + c];
        int p = atomicAdd(&cur[b * NNODES + c], 1);
        src[b * NEDGE + p] = r;
        nrm[b * NEDGE + p] = n;
    }
}

// ================= x0 GEMM: x0 = (mask @ colembT) * rcnt -> bf16 hi/lo ==========
__global__ void __launch_bounds__(256, 2) x0gemm(
    const __nv_bfloat16* __restrict__ Am, const __nv_bfloat16* __restrict__ Bh_g,
    const __nv_bfloat16* __restrict__ Bl_g, const float* __restrict__ rcnt,
    __nv_bfloat16* __restrict__ xh, __nv_bfloat16* __restrict__ xl) {
    extern __shared__ uint32_t smem[];
    uint32_t* sA  = smem;
    uint32_t* sBh = smem + 128 * PITCH;
    uint32_t* sBl = smem + 2 * 128 * PITCH;

    int tid = threadIdx.x;
    int lane = tid & 31, wid = tid >> 5;
    int g = lane >> 2, tig = lane & 3;
    int wm = wid & 1, wn = wid >> 1;
    int bm = blockIdx.x * 128;
    int bn = blockIdx.y * 128;

    uint32_t sA_a  = (uint32_t)__cvta_generic_to_shared(sA);
    uint32_t sBh_a = (uint32_t)__cvta_generic_to_shared(sBh);
    uint32_t sBl_a = (uint32_t)__cvta_generic_to_shared(sBl);

    int lane15 = lane & 15;
    int khalf = lane >> 4;
    uint32_t A_loff = (uint32_t)((wm * 64 + lane15) * PITCH) * 4u + (uint32_t)khalf * 16u;
    int bnrow = wn * 32 + (lane >> 4) * 8 + (lane & 7);
    uint32_t B_loff = (uint32_t)(bnrow * PITCH) * 4u + (uint32_t)((lane >> 3) & 1) * 16u;

    float acc[4][4][4];
#pragma unroll
    for (int mt = 0; mt < 4; mt++)
#pragma unroll
        for (int nt = 0; nt < 4; nt++)
#pragma unroll
            for (int q = 0; q < 4; q++) acc[mt][nt][q] = 0.f;

    for (int k0 = 0; k0 < MCOLS; k0 += KC) {
#pragma unroll
        for (int i = 0; i < 4; i++) {
            int sl = tid + i * 256;
            int row = sl >> 3;
            int s = sl & 7;
            uint32_t so = (uint32_t)(row * PITCH + s * 4) * 4u;
            size_t ga = (size_t)(bm + row) * MCOLS + k0 + s * 8;
            size_t gb = (size_t)(bn + row) * MCOLS + k0 + s * 8;
            cp16(sA_a + so, Am + ga);
            cp16(sBh_a + so, Bh_g + gb);
            cp16(sBl_a + so, Bl_g + gb);
        }
        asm volatile("cp.async.commit_group;");
        asm volatile("cp.async.wait_group 0;");
        __syncthreads();

#pragma unroll
        for (int ks = 0; ks < 4; ks++) {
            uint32_t koff = (uint32_t)ks * 32u;
            uint32_t Bh[4][2], Bl[4][2];
#pragma unroll
            for (int ntp = 0; ntp < 2; ntp++) {
                uint32_t r[4];
                uint32_t off = B_loff + (uint32_t)(ntp * 16 * PITCH) * 4u + koff;
                ldsm4(r, sBh_a + off);
                Bh[2 * ntp][0] = r[0]; Bh[2 * ntp][1] = r[1];
                Bh[2 * ntp + 1][0] = r[2]; Bh[2 * ntp + 1][1] = r[3];
                ldsm4(r, sBl_a + off);
                Bl[2 * ntp][0] = r[0]; Bl[2 * ntp][1] = r[1];
                Bl[2 * ntp + 1][0] = r[2]; Bl[2 * ntp + 1][1] = r[3];
            }
#pragma unroll
            for (int mt = 0; mt < 4; mt++) {
                uint32_t off = A_loff + (uint32_t)(mt * 16 * PITCH) * 4u + koff;
                uint32_t Af[4];
                ldsm4(Af, sA_a + off);
#pragma unroll
                for (int nt = 0; nt < 4; nt++) {
                    mma_bf16(acc[mt][nt], Af, Bh[nt]);
                    mma_bf16(acc[mt][nt], Af, Bl[nt]);
                }
            }
        }
        __syncthreads();
    }

#pragma unroll
    for (int mt = 0; mt < 4; mt++) {
        int row = bm + wm * 64 + mt * 16 + g;
        float rc0 = rcnt[row];
        float rc1 = rcnt[row + 8];
#pragma unroll
        for (int nt = 0; nt < 4; nt++) {
            int col = bn + wn * 32 + nt * 8 + tig * 2;
            uint32_t lo;
            uint32_t hi = packsplit(acc[mt][nt][0] * rc0, acc[mt][nt][1] * rc0, lo);
            *reinterpret_cast<uint32_t*>(&xh[(size_t)row * DD + col]) = hi;
            *reinterpret_cast<uint32_t*>(&xl[(size_t)row * DD + col]) = lo;
            hi = packsplit(acc[mt][nt][2] * rc1, acc[mt][nt][3] * rc1, lo);
            *reinterpret_cast<uint32_t*>(&xh[(size_t)(row + 8) * DD + col]) = hi;
            *reinterpret_cast<uint32_t*>(&xl[(size_t)(row + 8) * DD + col]) = lo;
        }
    }
}

// ================= split-bf16 HMMA GEMM =================
__global__ void __launch_bounds__(256, 2) gemm_mma2(
    const __nv_bfloat16* __restrict__ Ah_g, const __nv_bfloat16* __restrict__ Al_g,
    const __nv_bfloat16* __restrict__ Bh_g, const __nv_bfloat16* __restrict__ Bl_g,
    float* __restrict__ C, int cstride) {
    extern __shared__ uint32_t smem[];
    uint32_t* sAh = smem;
    uint32_t* sAl = smem + 128 * PITCH;
    uint32_t* sBh = smem + 2 * 128 * PITCH;
    uint32_t* sBl = smem + 3 * 128 * PITCH;

    int tid = threadIdx.x;
    int lane = tid & 31, wid = tid >> 5;
    int g = lane >> 2, tig = lane & 3;
    int wm = wid & 1, wn = wid >> 1;
    int bm = blockIdx.x * 128;
    int bn = blockIdx.y * 128;

    uint32_t sAh_a = (uint32_t)__cvta_generic_to_shared(sAh);
    uint32_t sAl_a = (uint32_t)__cvta_generic_to_shared(sAl);
    uint32_t sBh_a = (uint32_t)__cvta_generic_to_shared(sBh);
    uint32_t sBl_a = (uint32_t)__cvta_generic_to_shared(sBl);

    int lane15 = lane & 15;
    int khalf = lane >> 4;
    uint32_t A_loff = (uint32_t)((wm * 64 + lane15) * PITCH) * 4u + (uint32_t)khalf * 16u;
    int bnrow = wn * 32 + (lane >> 4) * 8 + (lane & 7);
    uint32_t B_loff = (uint32_t)(bnrow * PITCH) * 4u + (uint32_t)((lane >> 3) & 1) * 16u;

    float acc[4][4][4];
#pragma unroll
    for (int mt = 0; mt < 4; mt++)
#pragma unroll
        for (int nt = 0; nt < 4; nt++)
#pragma unroll
            for (int q = 0; q < 4; q++) acc[mt][nt][q] = 0.f;

    for (int k0 = 0; k0 < DD; k0 += KC) {
#pragma unroll
        for (int i = 0; i < 4; i++) {
            int sl = tid + i * 256;
            int row = sl >> 3;
            int s = sl & 7;
            uint32_t so = (uint32_t)(row * PITCH + s * 4) * 4u;
            size_t ga = (size_t)(bm + row) * DD + k0 + s * 8;
            size_t gb = (size_t)(bn + row) * DD + k0 + s * 8;
            cp16(sAh_a + so, Ah_g + ga);
            cp16(sAl_a + so, Al_g + ga);
            cp16(sBh_a + so, Bh_g + gb);
            cp16(sBl_a + so, Bl_g + gb);
        }
        asm volatile("cp.async.commit_group;");
        asm volatile("cp.async.wait_group 0;");
        __syncthreads();

#pragma unroll
        for (int ks = 0; ks < 4; ks++) {
            uint32_t koff = (uint32_t)ks * 32u;
            uint32_t Bh[4][2], Bl[4][2];
#pragma unroll
            for (int ntp = 0; ntp < 2; ntp++) {
                uint32_t r[4];
                uint32_t off = B_loff + (uint32_t)(ntp * 16 * PITCH) * 4u + koff;
                ldsm4(r, sBh_a + off);
                Bh[2 * ntp][0] = r[0]; Bh[2 * ntp][1] = r[1];
                Bh[2 * ntp + 1][0] = r[2]; Bh[2 * ntp + 1][1] = r[3];
                ldsm4(r, sBl_a + off);
                Bl[2 * ntp][0] = r[0]; Bl[2 * ntp][1] = r[1];
                Bl[2 * ntp + 1][0] = r[2]; Bl[2 * ntp + 1][1] = r[3];
            }
#pragma unroll
            for (int mt = 0; mt < 4; mt++) {
                uint32_t off = A_loff + (uint32_t)(mt * 16 * PITCH) * 4u + koff;
                uint32_t Ah[4], Al[4];
                ldsm4(Ah, sAh_a + off);
                ldsm4(Al, sAl_a + off);
#pragma unroll
                for (int nt = 0; nt < 4; nt++) {
                    mma_bf16(acc[mt][nt], Ah, Bh[nt]);
                    mma_bf16(acc[mt][nt], Al, Bh[nt]);
                    mma_bf16(acc[mt][nt], Ah, Bl[nt]);
                }
            }
        }
        __syncthreads();
    }

#pragma unroll
    for (int mt = 0; mt < 4; mt++) {
        int row = bm + wm * 64 + mt * 16 + g;
#pragma unroll
        for (int nt = 0; nt < 4; nt++) {
            int col = bn + wn * 32 + nt * 8 + tig * 2;
            *(float2*)&C[(size_t)row * cstride + col] = make_float2(acc[mt][nt][0], acc[mt][nt][1]);
            *(float2*)&C[(size_t)(row + 8) * cstride + col] = make_float2(acc[mt][nt][2], acc[mt][nt][3]);
        }
    }
}

// ---------------- aggregation (R7 config: 1 node/block, 64 threads, no smem) --------
__global__ void __launch_bounds__(64) agg_kernel(const float* __restrict__ h, int hstride,
                           const int* __restrict__ src,
                           const float* __restrict__ nrm, const int* __restrict__ start,
                           const float* __restrict__ dinv, const float* __restrict__ bias,
                           float* __restrict__ out,
                           __nv_bfloat16* __restrict__ xh, __nv_bfloat16* __restrict__ xl,
                           int pack, int wf32) {
    int i = blockIdx.x;
    int t = threadIdx.x;
    int s = start[i];
    int e = start[i + 1];
    float4 a0 = make_float4(0.f, 0.f, 0.f, 0.f);
    float4 a1 = make_float4(0.f, 0.f, 0.f, 0.f);
    float4 a2 = make_float4(0.f, 0.f, 0.f, 0.f);
    float4 a3 = make_float4(0.f, 0.f, 0.f, 0.f);
    int k = s;
    for (; k + 7 < e; k += 8) {
        int r0 = src[k], r1 = src[k + 1], r2 = src[k + 2], r3 = src[k + 3];
        int r4 = src[k + 4], r5 = src[k + 5], r6 = src[k + 6], r7 = src[k + 7];
        float w0 = nrm[k], w1 = nrm[k + 1], w2 = nrm[k + 2], w3 = nrm[k + 3];
        float w4 = nrm[k + 4], w5 = nrm[k + 5], w6 = nrm[k + 6], w7 = nrm[k + 7];
        float4 v0 = *(const float4*)&h[(size_t)r0 * hstride + t * 4];
        float4 v1 = *(const float4*)&h[(size_t)r1 * hstride + t * 4];
        float4 v2 = *(const float4*)&h[(size_t)r2 * hstride + t * 4];
        float4 v3 = *(const float4*)&h[(size_t)r3 * hstride + t * 4];
        float4 v4 = *(const float4*)&h[(size_t)r4 * hstride + t * 4];
        float4 v5 = *(const float4*)&h[(size_t)r5 * hstride + t * 4];
        float4 v6 = *(const float4*)&h[(size_t)r6 * hstride + t * 4];
        float4 v7 = *(const float4*)&h[(size_t)r7 * hstride + t * 4];
        a0.x += w0 * v0.x; a0.y += w0 * v0.y; a0.z += w0 * v0.z; a0.w += w0 * v0.w;
        a1.x += w1 * v1.x; a1.y += w1 * v1.y; a1.z += w1 * v1.z; a1.w += w1 * v1.w;
        a2.x += w2 * v2.x; a2.y += w2 * v2.y; a2.z += w2 * v2.z; a2.w += w2 * v2.w;
        a3.x += w3 * v3.x; a3.y += w3 * v3.y; a3.z += w3 * v3.z; a3.w += w3 * v3.w;
        a0.x += w4 * v4.x; a0.y += w4 * v4.y; a0.z += w4 * v4.z; a0.w += w4 * v4.w;
        a1.x += w5 * v5.x; a1.y += w5 * v5.y; a1.z += w5 * v5.z; a1.w += w5 * v5.w;
        a2.x += w6 * v6.x; a2.y += w6 * v6.y; a2.z += w6 * v6.z; a2.w += w6 * v6.w;
        a3.x += w7 * v7.x; a3.y += w7 * v7.y; a3.z += w7 * v7.z; a3.w += w7 * v7.w;
    }
    for (; k < e; k++) {
        int r = src[k];
        float w = nrm[k];
        float4 v = *(const float4*)&h[(size_t)r * hstride + t * 4];
        a0.x += w * v.x; a0.y += w * v.y; a0.z += w * v.z; a0.w += w * v.w;
    }
    float di = dinv[i];
    float sn = di * di;
    float4 hv = *(const float4*)&h[(size_t)i * hstride + t * 4];
    float4 bv = *(const float4*)&bias[t * 4];
    float4 acc;
    acc.x = a0.x + a1.x + a2.x + a3.x + sn * hv.x + bv.x;
    acc.y = a0.y + a1.y + a2.y + a3.y + sn * hv.y + bv.y;
    acc.z = a0.z + a1.z + a2.z + a3.z + sn * hv.z + bv.z;
    acc.w = a0.w + a1.w + a2.w + a3.w + sn * hv.w + bv.w;
    if (wf32) *(float4*)&out[(size_t)i * DD + t * 4] = acc;
    if (pack) {
        float r0 = fmaxf(acc.x, 0.f), r1 = fmaxf(acc.y, 0.f);
        float r2 = fmaxf(acc.z, 0.f), r3 = fmaxf(acc.w, 0.f);
        uint32_t lo0, lo1;
        uint32_t hi0 = packsplit(r0, r1, lo0);
        uint32_t hi1 = packsplit(r2, r3, lo1);
        uint2 hp, lp;
        hp.x = hi0; hp.y = hi1;
        lp.x = lo0; lp.y = lo1;
        reinterpret_cast<uint2*>(xh)[(size_t)i * 64 + t] = hp;
        reinterpret_cast<uint2*>(xl)[(size_t)i * 64 + t] = lp;
    }
}

// ---------------- meta-path attention ----------------
__global__ void attn_kernel(const float* __restrict__ b0, const float* __restrict__ b1,
                            const float* __restrict__ b2, const float* __restrict__ watt,
                            float* __restrict__ out) {
    int i = blockIdx.x;
    int t = threadIdx.x;
    size_t off = (size_t)i * DD + t;
    float x0v = fmaxf(b0[off], 0.f);
    float x1v = fmaxf(b1[off], 0.f);
    float x2v = fmaxf(b2[off], 0.f);
    float w = watt[t];
    float s0 = x0v * w, s1 = x1v * w, s2 = x2v * w;
#pragma unroll
    for (int o = 16; o; o >>= 1) {
        s0 += __shfl_xor_sync(0xffffffffu, s0, o);
        s1 += __shfl_xor_sync(0xffffffffu, s1, o);
        s2 += __shfl_xor_sync(0xffffffffu, s2, o);
    }
    __shared__ float sm[3][8];
    __shared__ float sw[3];
    int wid = t >> 5, ln = t & 31;
    if (ln == 0) { sm[0][wid] = s0; sm[1][wid] = s1; sm[2][wid] = s2; }
    __syncthreads();
    if (t == 0) {
        float t0 = 0.f, t1 = 0.f, t2 = 0.f;
#pragma unroll
        for (int kk = 0; kk < 8; kk++) { t0 += sm[0][kk]; t1 += sm[1][kk]; t2 += sm[2][kk]; }
        float mx = fmaxf(t0, fmaxf(t1, t2));
        float e0 = expf(t0 - mx), e1 = expf(t1 - mx), e2 = expf(t2 - mx);
        float inv = 1.f / (e0 + e1 + e2);
        sw[0] = e0 * inv; sw[1] = e1 * inv; sw[2] = e2 * inv;
    }
    __syncthreads();
    out[off] = sw[0] * x0v + sw[1] * x1v + sw[2] * x2v;
}

// ---------------- stream/event setup (static init: before harness checkpoints) -----
struct AsyncCtx {
    cudaStream_t s1;
    cudaEvent_t ev[16];
    int ok;
    AsyncCtx() : ok(0) {
        if (cudaStreamCreateWithFlags(&s1, cudaStreamNonBlocking) != cudaSuccess) return;
        for (int i = 0; i < 16; i++)
            if (cudaEventCreateWithFlags(&ev[i], cudaEventDisableTiming) != cudaSuccess) return;
        ok = 1;
    }
};
static AsyncCtx g_async;

// ---------------- launcher ----------------
extern "C" void kernel_launch(void* const* d_in, const int* in_sizes, int n_in,
                              void* d_out, int out_size) {
    const float* init = (const float*)d_in[0];
    const int*   ei[3] = {(const int*)d_in[1], (const int*)d_in[2], (const int*)d_in[3]};
    const float* ea[3] = {(const float*)d_in[4], (const float*)d_in[5], (const float*)d_in[6]};
    const float* pW1 = (const float*)d_in[7];
    const float* pb1 = (const float*)d_in[8];
    const float* pW2 = (const float*)d_in[9];
    const float* pb2 = (const float*)d_in[10];
    const float* Wb[3] = {(const float*)d_in[11], (const float*)d_in[13], (const float*)d_in[15]};
    const float* bb[3] = {(const float*)d_in[12], (const float*)d_in[14], (const float*)d_in[16]};
    const float* watt = (const float*)d_in[17];
    float* out = (float*)d_out;

    float *colemb, *h0, *hh, *deg, *dinv, *nrm, *rcnt;
    float *br[3];
    int *hist, *cur, *start, *src, *bsum, *bbase;
    __nv_bfloat16 *x0h, *x0l, *xhb, *xlb, *Wh, *Wl, *mask, *colTh, *colTl;
    cudaGetSymbolAddress((void**)&colemb, g_colemb);
    cudaGetSymbolAddress((void**)&h0,     g_h0);
    cudaGetSymbolAddress((void**)&hh,     g_hh);
    cudaGetSymbolAddress((void**)&br[0],  g_br0);
    cudaGetSymbolAddress((void**)&br[1],  g_br1);
    cudaGetSymbolAddress((void**)&br[2],  g_br2);
    cudaGetSymbolAddress((void**)&deg,    g_deg);
    cudaGetSymbolAddress((void**)&dinv,   g_dinv);
    cudaGetSymbolAddress((void**)&hist,   g_hist);
    cudaGetSymbolAddress((void**)&cur,    g_cur);
    cudaGetSymbolAddress((void**)&start,  g_start);
    cudaGetSymbolAddress((void**)&bsum,   g_bsum);
    cudaGetSymbolAddress((void**)&bbase,  g_bbase);
    cudaGetSymbolAddress((void**)&src,    g_src);
    cudaGetSymbolAddress((void**)&nrm,    g_nrm);
    cudaGetSymbolAddress((void**)&rcnt,   g_rcnt);
    cudaGetSymbolAddress((void**)&mask,   g_mask);
    cudaGetSymbolAddress((void**)&colTh,  g_colTh);
    cudaGetSymbolAddress((void**)&colTl,  g_colTl);
    cudaGetSymbolAddress((void**)&x0h,    g_x0h);
    cudaGetSymbolAddress((void**)&x0l,    g_x0l);
    cudaGetSymbolAddress((void**)&xhb,    g_xhb);
    cudaGetSymbolAddress((void**)&xlb,    g_xlb);
    cudaGetSymbolAddress((void**)&Wh,     g_Wh);
    cudaGetSymbolAddress((void**)&Wl,     g_Wl);

    static int attr_set = 0;
    if (!attr_set) {
        cudaFuncSetAttribute(gemm_mma2, cudaFuncAttributeMaxDynamicSharedMemorySize, 73728);
        cudaFuncSetAttribute(x0gemm, cudaFuncAttributeMaxDynamicSharedMemorySize, 55296);
        attr_set = 1;
    }

    const int use2 = g_async.ok;
    cudaStream_t sP = use2 ? g_async.s1 : (cudaStream_t)0;  // prep/gemm side stream
    cudaEvent_t* ev = g_async.ev;
    // ev[0]=fork, ev[1]=prep-done, ev[2..7]=agg-done forks, ev[8..13]=gemm-done joins

    if (use2) {
        cudaEventRecord(ev[0], 0);
        cudaStreamWaitEvent(sP, ev[0], 0);
    }

    // ---- prep chain (side stream)
    branch_init<<<dim3(NB, 1, 3), 256, 0, sP>>>(deg, hist);
    edge_count<<<dim3(EB, 1, 3), 256, 0, sP>>>(ei[0], ei[1], ei[2], ea[0], ea[1], ea[2],
                                               deg, hist);
    dinv_kernel<<<dim3(NB, 1, 3), 256, 0, sP>>>(deg, dinv);
    scanP1<<<3 * NB, 256, 0, sP>>>(hist, bsum);
    scanP2<<<1, 256, 0, sP>>>(bsum, bbase, start);
    scanP3<<<3 * NB, 256, 0, sP>>>(hist, bbase, start, cur);
    scatter_kernel<<<dim3(EB, 1, 3), 256, 0, sP>>>(ei[0], ei[1], ei[2], ea[0], ea[1], ea[2],
                                                   dinv, cur, src, nrm);
    if (use2) cudaEventRecord(ev[1], sP);

    // ---- x0 chain (main stream)
    colemb_kernel<<<MCOLS, DD>>>(pW1, pb1, pW2, pb2, colemb);
    maskbuild_kernel<<<NNODES, 256>>>(init, mask, rcnt);
    colembT_kernel<<<dim3(32, 8), dim3(32, 8)>>>(colemb, colTh, colTl);
    wconv_kernel<<<dim3(8, 8, 9), dim3(32, 8)>>>(Wb[0], Wb[1], Wb[2], Wh, Wl);
    x0gemm<<<dim3(157, 2), 256, 55296>>>(mask, colTh, colTl, rcnt, x0h, x0l);
    // layer-0 GEMM batched across all branches (Wh l-major: w'=0,1,2 -> [768][256])
    gemm_mma2<<<dim3(157, 6), 256, 73728>>>(x0h, x0l, Wh, Wl, h0, 768);

    if (use2) cudaStreamWaitEvent(0, ev[1], 0);

    // ---- pipelined layers: aggs on main stream, gemms on side stream
    // main order: A(b,l) for l=0..2, b=0..2 round-robin; G(b,l+1) forked after A(b,l)
    for (int s = 0; s < 9; s++) {
        int b = s % 3;
        int l = s / 3;
        // wait for gemm that produced this layer's h (l>=1)
        if (l >= 1 && use2) cudaStreamWaitEvent(0, ev[8 + (l - 1) * 3 + b], 0);
        const float* ah = (l == 0) ? (h0 + b * DD) : (hh + (size_t)b * NPAD * DD);
        int hstride = (l == 0) ? 768 : DD;
        int pack = (l < 2), wf32 = (l == 2);
        agg_kernel<<<NNODES, 64>>>(ah, hstride, src + b * NEDGE, nrm + b * NEDGE,
                                   start + b * (NNODES + 1), dinv + b * NNODES,
                                   bb[b] + l * DD, br[b],
                                   xhb + (size_t)b * NPAD * DD, xlb + (size_t)b * NPAD * DD,
                                   pack, wf32);
        if (l < 2) {
            // fork gemm for next layer of this branch
            if (use2) {
                cudaEventRecord(ev[2 + s], 0);
                cudaStreamWaitEvent(sP, ev[2 + s], 0);
            }
            int w = (l + 1) * 3 + b;
            gemm_mma2<<<dim3(157, 2), 256, 73728, sP>>>(
                xhb + (size_t)b * NPAD * DD, xlb + (size_t)b * NPAD * DD,
                Wh + (size_t)w * DD * DD, Wl + (size_t)w * DD * DD,
                hh + (size_t)b * NPAD * DD, DD);
            if (use2) cudaEventRecord(ev[8 + l * 3 + b], sP);
        }
    }

    attn_kernel<<<NNODES, 256>>>(br[0], br[1], br[2], watt, out);
}

// round 11
// speedup vs baseline: 1.7858x; 1.2595x over previous
#include <cuda_runtime.h>
#include <cuda_bf16.h>
#include <cstdint>

#define NNODES 20000
#define NPAD   20096            // 157 * 128
#define MCOLS  1024
#define NEDGE  640000
#define DD     256
#define NB     79               // ceil(20000/256)
#define EB     2500             // ceil(640000/256)

// ---------------- scratch (__device__ globals; zero-initialized bss) ----------------
__device__ float g_colemb[MCOLS * DD];
__device__ float g_h[NPAD * DD];
__device__ float g_h0[NPAD * 768];              // batched layer-0 output (3 branches)
__device__ float g_br0[NPAD * DD];
__device__ float g_br1[NPAD * DD];
__device__ float g_br2[NPAD * DD];
__device__ float g_deg[3 * NNODES];
__device__ float g_dinv[3 * NNODES];
__device__ int   g_hist[3 * NNODES];
__device__ int   g_cur[3 * NNODES];
__device__ int   g_start[3 * (NNODES + 1)];
__device__ int   g_bsum[3 * NB];
__device__ int   g_bbase[3 * NB];
__device__ int   g_src[3 * NEDGE];
__device__ float g_nrm[3 * NEDGE];
// x0-as-GEMM operands
__device__ __nv_bfloat16 g_mask[NPAD * MCOLS];  // bf16 0/1 mask (padded rows stay 0)
__device__ float g_rcnt[NPAD];                  // 1/max(cnt,1) (padded rows 0)
__device__ __nv_bfloat16 g_colTh[DD * MCOLS];
__device__ __nv_bfloat16 g_colTl[DD * MCOLS];
// packed bf16 hi/lo planes
__device__ __nv_bfloat16 g_x0h[NPAD * DD];
__device__ __nv_bfloat16 g_x0l[NPAD * DD];
__device__ __nv_bfloat16 g_xh[NPAD * DD];
__device__ __nv_bfloat16 g_xl[NPAD * DD];
// transposed bf16 hi/lo weights, l-major: index w' = l*3+b, each [n=256][k=256]
__device__ __nv_bfloat16 g_Wh[9 * DD * DD];
__device__ __nv_bfloat16 g_Wl[9 * DD * DD];

// ================= shared MMA helpers =================
#define KC 64
#define PITCH 36      // uint32 words per smem row (32 kpairs + 4 pad)

__device__ __forceinline__ void mma_bf16(float* c, const uint32_t* a, const uint32_t* b) {
    asm volatile(
        "mma.sync.aligned.m16n8k16.row.col.f32.bf16.bf16.f32 "
        "{%0,%1,%2,%3}, {%4,%5,%6,%7}, {%8,%9}, {%0,%1,%2,%3};"
        : "+f"(c[0]), "+f"(c[1]), "+f"(c[2]), "+f"(c[3])
        : "r"(a[0]), "r"(a[1]), "r"(a[2]), "r"(a[3]), "r"(b[0]), "r"(b[1]));
}
__device__ __forceinline__ void ldsm4(uint32_t* r, uint32_t addr) {
    asm volatile("ldmatrix.sync.aligned.m8n8.x4.shared.b16 {%0,%1,%2,%3}, [%4];"
        : "=r"(r[0]), "=r"(r[1]), "=r"(r[2]), "=r"(r[3]) : "r"(addr));
}
__device__ __forceinline__ void cp16(uint32_t smem_dst, const void* gsrc) {
    asm volatile("cp.async.cg.shared.global [%0], [%1], 16;" :: "r"(smem_dst), "l"(gsrc));
}
__device__ __forceinline__ uint32_t packsplit(float v0, float v1, uint32_t& lo) {
    __nv_bfloat162 h, l;
    h.x = __float2bfloat16(v0); h.y = __float2bfloat16(v1);
    l.x = __float2bfloat16(v0 - __bfloat162float(h.x));
    l.y = __float2bfloat16(v1 - __bfloat162float(h.y));
    lo = *reinterpret_cast<uint32_t*>(&l);
    return *reinterpret_cast<uint32_t*>(&h);
}

// ---------------- front-end kernels ----------------
__global__ void colemb_kernel(const float* __restrict__ pW1, const float* __restrict__ pb1,
                              const float* __restrict__ pW2, const float* __restrict__ pb2,
                              float* __restrict__ colemb) {
    int j = blockIdx.x;
    int d = threadIdx.x;
    float jf = (float)j;
    float acc = pb2[d];
#pragma unroll
    for (int k = 0; k < 16; k++) {
        float hk = fmaxf(jf * pW1[k] + pb1[k], 0.f);
        acc += hk * pW2[k * DD + d];
    }
    colemb[j * DD + d] = acc;
}

__global__ void maskbuild_kernel(const float* __restrict__ init,
                                 __nv_bfloat16* __restrict__ mask, float* __restrict__ rcnt) {
    int i = blockIdx.x;
    int t = threadIdx.x;  // 256, 4 cols each
    __shared__ int scnt;
    if (t == 0) scnt = 0;
    __syncthreads();
    float4 v = *(const float4*)&init[(size_t)i * MCOLS + t * 4];
    float m0 = (v.x != 0.f) ? 1.f : 0.f;
    float m1 = (v.y != 0.f) ? 1.f : 0.f;
    float m2 = (v.z != 0.f) ? 1.f : 0.f;
    float m3 = (v.w != 0.f) ? 1.f : 0.f;
    int c = (int)(m0 + m1 + m2 + m3);
#pragma unroll
    for (int o = 16; o; o >>= 1) c += __shfl_xor_sync(0xffffffffu, c, o);
    if ((t & 31) == 0) atomicAdd(&scnt, c);
    __nv_bfloat162 p01, p23;
    p01.x = __float2bfloat16(m0); p01.y = __float2bfloat16(m1);
    p23.x = __float2bfloat16(m2); p23.y = __float2bfloat16(m3);
    uint2 pk;
    pk.x = *reinterpret_cast<uint32_t*>(&p01);
    pk.y = *reinterpret_cast<uint32_t*>(&p23);
    *reinterpret_cast<uint2*>(&mask[(size_t)i * MCOLS + t * 4]) = pk;
    __syncthreads();
    if (t == 0) rcnt[i] = 1.f / (float)max(scnt, 1);
}

__global__ void colembT_kernel(const float* __restrict__ colemb,
                               __nv_bfloat16* __restrict__ Th, __nv_bfloat16* __restrict__ Tl) {
    __shared__ float tile[32][33];
    int j0 = blockIdx.x * 32, d0 = blockIdx.y * 32;
    int tx = threadIdx.x, ty = threadIdx.y;  // 32 x 8
#pragma unroll
    for (int i = 0; i < 32; i += 8)
        tile[ty + i][tx] = colemb[(size_t)(j0 + ty + i) * DD + d0 + tx];
    __syncthreads();
#pragma unroll
    for (int i = 0; i < 32; i += 8) {
        float v = tile[tx][ty + i];
        __nv_bfloat16 h = __float2bfloat16(v);
        size_t o = (size_t)(d0 + ty + i) * MCOLS + j0 + tx;
        Th[o] = h;
        Tl[o] = __float2bfloat16(v - __bfloat162float(h));
    }
}

__global__ void wconv_kernel(const float* __restrict__ W0, const float* __restrict__ W1,
                             const float* __restrict__ W2,
                             __nv_bfloat16* __restrict__ Ht, __nv_bfloat16* __restrict__ Lt) {
    __shared__ float tile[32][33];
    int z = blockIdx.z;           // b*3 + l
    int b = z / 3, l = z % 3;
    const float* W = (b == 0) ? W0 : (b == 1) ? W1 : W2;
    W += (size_t)l * DD * DD;
    size_t dbase = (size_t)(l * 3 + b) * DD * DD;
    int n0 = blockIdx.x * 32, k0 = blockIdx.y * 32;
    int tx = threadIdx.x, ty = threadIdx.y;  // 32 x 8
#pragma unroll
    for (int i = 0; i < 32; i += 8)
        tile[ty + i][tx] = W[(size_t)(k0 + ty + i) * DD + n0 + tx];
    __syncthreads();
#pragma unroll
    for (int i = 0; i < 32; i += 8) {
        float v = tile[tx][ty + i];
        __nv_bfloat16 h = __float2bfloat16(v);
        size_t o = dbase + (size_t)(n0 + ty + i) * DD + k0 + tx;
        Ht[o] = h;
        Lt[o] = __float2bfloat16(v - __bfloat162float(h));
    }
}

// ---------------- graph prep (grid.z = branch) ----------------
__global__ void branch_init(float* __restrict__ deg, int* __restrict__ hist) {
    int i = blockIdx.x * blockDim.x + threadIdx.x;
    int b = blockIdx.z;
    if (i < NNODES) { deg[b * NNODES + i] = 1.0f; hist[b * NNODES + i] = 0; }
}

__global__ void edge_count(const int* __restrict__ ei0, const int* __restrict__ ei1,
                           const int* __restrict__ ei2,
                           const float* __restrict__ ea0, const float* __restrict__ ea1,
                           const float* __restrict__ ea2,
                           float* __restrict__ deg, int* __restrict__ hist) {
    int e = blockIdx.x * blockDim.x + threadIdx.x;
    int b = blockIdx.z;
    const int* ei = (b == 0) ? ei0 : (b == 1) ? ei1 : ei2;
    const float* ea = (b == 0) ? ea0 : (b == 1) ? ea1 : ea2;
    if (e < NEDGE) {
        int c = ei[NEDGE + e];
        atomicAdd(&deg[b * NNODES + c], ea[e]);
        atomicAdd(&hist[b * NNODES + c], 1);
    }
}

__global__ void dinv_kernel(const float* __restrict__ deg, float* __restrict__ dinv) {
    int i = blockIdx.x * blockDim.x + threadIdx.x;
    int b = blockIdx.z;
    if (i < NNODES) dinv[b * NNODES + i] = rsqrtf(deg[b * NNODES + i]);
}

// ---- 3-phase exclusive scan over hist (per branch) ----
__global__ void scanP1(const int* __restrict__ hist, int* __restrict__ bsum) {
    int bid = blockIdx.x;        // 3*NB
    int b = bid / NB, blk = bid % NB;
    int t = threadIdx.x;         // 256
    int gi = blk * 256 + t;
    int v = (gi < NNODES) ? hist[b * NNODES + gi] : 0;
#pragma unroll
    for (int o = 16; o; o >>= 1) v += __shfl_xor_sync(0xffffffffu, v, o);
    __shared__ int ws[8];
    if ((t & 31) == 0) ws[t >> 5] = v;
    __syncthreads();
    if (t == 0) {
        int s = 0;
#pragma unroll
        for (int w = 0; w < 8; w++) s += ws[w];
        bsum[b * NB + blk] = s;
    }
}
__global__ void scanP2(const int* __restrict__ bsum, int* __restrict__ bbase,
                       int* __restrict__ start) {
    int t = threadIdx.x;
    if (t < 3) {
        int s = 0;
        for (int i = 0; i < NB; i++) {
            bbase[t * NB + i] = s;
            s += bsum[t * NB + i];
        }
        start[t * (NNODES + 1) + NNODES] = s;
    }
}
__global__ void scanP3(const int* __restrict__ hist, const int* __restrict__ bbase,
                       int* __restrict__ start, int* __restrict__ cur) {
    int bid = blockIdx.x;
    int b = bid / NB, blk = bid % NB;
    int t = threadIdx.x;
    int lane = t & 31, w = t >> 5;
    int gi = blk * 256 + t;
    int v = (gi < NNODES) ? hist[b * NNODES + gi] : 0;
    int s = v;
#pragma unroll
    for (int o = 1; o < 32; o <<= 1) {
        int x = __shfl_up_sync(0xffffffffu, s, o);
        if (lane >= o) s += x;
    }
    __shared__ int ws[8];
    if (lane == 31) ws[w] = s;
    __syncthreads();
    if (t == 0) {
        int acc = 0;
#pragma unroll
        for (int i = 0; i < 8; i++) { int x = ws[i]; ws[i] = acc; acc += x; }
    }
    __syncthreads();
    int excl = s - v + ws[w] + bbase[b * NB + blk];
    if (gi < NNODES) {
        start[b * (NNODES + 1) + gi] = excl;
        cur[b * NNODES + gi] = excl;
    }
}

__global__ void scatter_kernel(const int* __restrict__ ei0, const int* __restrict__ ei1,
                               const int* __restrict__ ei2,
                               const float* __restrict__ ea0, const float* __restrict__ ea1,
                               const float* __restrict__ ea2,
                               const float* __restrict__ dinv, int* __restrict__ cur,
                               int* __restrict__ src, float* __restrict__ nrm) {
    int e = blockIdx.x * blockDim.x + threadIdx.x;
    int b = blockIdx.z;
    const int* ei = (b == 0) ? ei0 : (b == 1) ? ei1 : ei2;
    const float* ea = (b == 0) ? ea0 : (b == 1) ? ea1 : ea2;
    if (e < NEDGE) {
        int r = ei[e];
        int c = ei[NEDGE + e];
        float n = dinv[b * NNODES + r] * ea[e] * dinv[b * NNODES + c];
        int p = atomicAdd(&cur[b * NNODES + c], 1);
        src[b * NEDGE + p] = r;
        nrm[b * NEDGE + p] = n;
    }
}

// ================= x0 GEMM: x0 = (mask @ colembT) * rcnt -> bf16 hi/lo ==========
__global__ void __launch_bounds__(256, 2) x0gemm(
    const __nv_bfloat16* __restrict__ Am, const __nv_bfloat16* __restrict__ Bh_g,
    const __nv_bfloat16* __restrict__ Bl_g, const float* __restrict__ rcnt,
    __nv_bfloat16* __restrict__ xh, __nv_bfloat16* __restrict__ xl) {
    extern __shared__ uint32_t smem[];
    uint32_t* sA  = smem;
    uint32_t* sBh = smem + 128 * PITCH;
    uint32_t* sBl = smem + 2 * 128 * PITCH;

    int tid = threadIdx.x;
    int lane = tid & 31, wid = tid >> 5;
    int g = lane >> 2, tig = lane & 3;
    int wm = wid & 1, wn = wid >> 1;
    int bm = blockIdx.x * 128;
    int bn = blockIdx.y * 128;

    uint32_t sA_a  = (uint32_t)__cvta_generic_to_shared(sA);
    uint32_t sBh_a = (uint32_t)__cvta_generic_to_shared(sBh);
    uint32_t sBl_a = (uint32_t)__cvta_generic_to_shared(sBl);

    int lane15 = lane & 15;
    int khalf = lane >> 4;
    uint32_t A_loff = (uint32_t)((wm * 64 + lane15) * PITCH) * 4u + (uint32_t)khalf * 16u;
    int bnrow = wn * 32 + (lane >> 4) * 8 + (lane & 7);
    uint32_t B_loff = (uint32_t)(bnrow * PITCH) * 4u + (uint32_t)((lane >> 3) & 1) * 16u;

    float acc[4][4][4];
#pragma unroll
    for (int mt = 0; mt < 4; mt++)
#pragma unroll
        for (int nt = 0; nt < 4; nt++)
#pragma unroll
            for (int q = 0; q < 4; q++) acc[mt][nt][q] = 0.f;

    for (int k0 = 0; k0 < MCOLS; k0 += KC) {
#pragma unroll
        for (int i = 0; i < 4; i++) {
            int sl = tid + i * 256;
            int row = sl >> 3;
            int s = sl & 7;
            uint32_t so = (uint32_t)(row * PITCH + s * 4) * 4u;
            size_t ga = (size_t)(bm + row) * MCOLS + k0 + s * 8;
            size_t gb = (size_t)(bn + row) * MCOLS + k0 + s * 8;
            cp16(sA_a + so, Am + ga);
            cp16(sBh_a + so, Bh_g + gb);
            cp16(sBl_a + so, Bl_g + gb);
        }
        asm volatile("cp.async.commit_group;");
        asm volatile("cp.async.wait_group 0;");
        __syncthreads();

#pragma unroll
        for (int ks = 0; ks < 4; ks++) {
            uint32_t koff = (uint32_t)ks * 32u;
            uint32_t Bh[4][2], Bl[4][2];
#pragma unroll
            for (int ntp = 0; ntp < 2; ntp++) {
                uint32_t r[4];
                uint32_t off = B_loff + (uint32_t)(ntp * 16 * PITCH) * 4u + koff;
                ldsm4(r, sBh_a + off);
                Bh[2 * ntp][0] = r[0]; Bh[2 * ntp][1] = r[1];
                Bh[2 * ntp + 1][0] = r[2]; Bh[2 * ntp + 1][1] = r[3];
                ldsm4(r, sBl_a + off);
                Bl[2 * ntp][0] = r[0]; Bl[2 * ntp][1] = r[1];
                Bl[2 * ntp + 1][0] = r[2]; Bl[2 * ntp + 1][1] = r[3];
            }
#pragma unroll
            for (int mt = 0; mt < 4; mt++) {
                uint32_t off = A_loff + (uint32_t)(mt * 16 * PITCH) * 4u + koff;
                uint32_t Af[4];
                ldsm4(Af, sA_a + off);
#pragma unroll
                for (int nt = 0; nt < 4; nt++) {
                    mma_bf16(acc[mt][nt], Af, Bh[nt]);
                    mma_bf16(acc[mt][nt], Af, Bl[nt]);
                }
            }
        }
        __syncthreads();
    }

#pragma unroll
    for (int mt = 0; mt < 4; mt++) {
        int row = bm + wm * 64 + mt * 16 + g;
        float rc0 = rcnt[row];
        float rc1 = rcnt[row + 8];
#pragma unroll
        for (int nt = 0; nt < 4; nt++) {
            int col = bn + wn * 32 + nt * 8 + tig * 2;
            uint32_t lo;
            uint32_t hi = packsplit(acc[mt][nt][0] * rc0, acc[mt][nt][1] * rc0, lo);
            *reinterpret_cast<uint32_t*>(&xh[(size_t)row * DD + col]) = hi;
            *reinterpret_cast<uint32_t*>(&xl[(size_t)row * DD + col]) = lo;
            hi = packsplit(acc[mt][nt][2] * rc1, acc[mt][nt][3] * rc1, lo);
            *reinterpret_cast<uint32_t*>(&xh[(size_t)(row + 8) * DD + col]) = hi;
            *reinterpret_cast<uint32_t*>(&xl[(size_t)(row + 8) * DD + col]) = lo;
        }
    }
}

// ================= split-bf16 HMMA GEMM =================
__global__ void __launch_bounds__(256, 2) gemm_mma2(
    const __nv_bfloat16* __restrict__ Ah_g, const __nv_bfloat16* __restrict__ Al_g,
    const __nv_bfloat16* __restrict__ Bh_g, const __nv_bfloat16* __restrict__ Bl_g,
    float* __restrict__ C, int cstride) {
    extern __shared__ uint32_t smem[];
    uint32_t* sAh = smem;
    uint32_t* sAl = smem + 128 * PITCH;
    uint32_t* sBh = smem + 2 * 128 * PITCH;
    uint32_t* sBl = smem + 3 * 128 * PITCH;

    int tid = threadIdx.x;
    int lane = tid & 31, wid = tid >> 5;
    int g = lane >> 2, tig = lane & 3;
    int wm = wid & 1, wn = wid >> 1;
    int bm = blockIdx.x * 128;
    int bn = blockIdx.y * 128;

    uint32_t sAh_a = (uint32_t)__cvta_generic_to_shared(sAh);
    uint32_t sAl_a = (uint32_t)__cvta_generic_to_shared(sAl);
    uint32_t sBh_a = (uint32_t)__cvta_generic_to_shared(sBh);
    uint32_t sBl_a = (uint32_t)__cvta_generic_to_shared(sBl);

    int lane15 = lane & 15;
    int khalf = lane >> 4;
    uint32_t A_loff = (uint32_t)((wm * 64 + lane15) * PITCH) * 4u + (uint32_t)khalf * 16u;
    int bnrow = wn * 32 + (lane >> 4) * 8 + (lane & 7);
    uint32_t B_loff = (uint32_t)(bnrow * PITCH) * 4u + (uint32_t)((lane >> 3) & 1) * 16u;

    float acc[4][4][4];
#pragma unroll
    for (int mt = 0; mt < 4; mt++)
#pragma unroll
        for (int nt = 0; nt < 4; nt++)
#pragma unroll
            for (int q = 0; q < 4; q++) acc[mt][nt][q] = 0.f;

    for (int k0 = 0; k0 < DD; k0 += KC) {
#pragma unroll
        for (int i = 0; i < 4; i++) {
            int sl = tid + i * 256;
            int row = sl >> 3;
            int s = sl & 7;
            uint32_t so = (uint32_t)(row * PITCH + s * 4) * 4u;
            size_t ga = (size_t)(bm + row) * DD + k0 + s * 8;
            size_t gb = (size_t)(bn + row) * DD + k0 + s * 8;
            cp16(sAh_a + so, Ah_g + ga);
            cp16(sAl_a + so, Al_g + ga);
            cp16(sBh_a + so, Bh_g + gb);
            cp16(sBl_a + so, Bl_g + gb);
        }
        asm volatile("cp.async.commit_group;");
        asm volatile("cp.async.wait_group 0;");
        __syncthreads();

#pragma unroll
        for (int ks = 0; ks < 4; ks++) {
            uint32_t koff = (uint32_t)ks * 32u;
            uint32_t Bh[4][2], Bl[4][2];
#pragma unroll
            for (int ntp = 0; ntp < 2; ntp++) {
                uint32_t r[4];
                uint32_t off = B_loff + (uint32_t)(ntp * 16 * PITCH) * 4u + koff;
                ldsm4(r, sBh_a + off);
                Bh[2 * ntp][0] = r[0]; Bh[2 * ntp][1] = r[1];
                Bh[2 * ntp + 1][0] = r[2]; Bh[2 * ntp + 1][1] = r[3];
                ldsm4(r, sBl_a + off);
                Bl[2 * ntp][0] = r[0]; Bl[2 * ntp][1] = r[1];
                Bl[2 * ntp + 1][0] = r[2]; Bl[2 * ntp + 1][1] = r[3];
            }
#pragma unroll
            for (int mt = 0; mt < 4; mt++) {
                uint32_t off = A_loff + (uint32_t)(mt * 16 * PITCH) * 4u + koff;
                uint32_t Ah[4], Al[4];
                ldsm4(Ah, sAh_a + off);
                ldsm4(Al, sAl_a + off);
#pragma unroll
                for (int nt = 0; nt < 4; nt++) {
                    mma_bf16(acc[mt][nt], Ah, Bh[nt]);
                    mma_bf16(acc[mt][nt], Al, Bh[nt]);
                    mma_bf16(acc[mt][nt], Ah, Bl[nt]);
                }
            }
        }
        __syncthreads();
    }

#pragma unroll
    for (int mt = 0; mt < 4; mt++) {
        int row = bm + wm * 64 + mt * 16 + g;
#pragma unroll
        for (int nt = 0; nt < 4; nt++) {
            int col = bn + wn * 32 + nt * 8 + tig * 2;
            *(float2*)&C[(size_t)row * cstride + col] = make_float2(acc[mt][nt][0], acc[mt][nt][1]);
            *(float2*)&C[(size_t)(row + 8) * cstride + col] = make_float2(acc[mt][nt][2], acc[mt][nt][3]);
        }
    }
}

// ---------------- aggregation (1 node/block, 64 threads, no smem) --------
__global__ void __launch_bounds__(64) agg_kernel(const float* __restrict__ h, int hstride,
                           const int* __restrict__ src,
                           const float* __restrict__ nrm, const int* __restrict__ start,
                           const float* __restrict__ dinv, const float* __restrict__ bias,
                           float* __restrict__ out,
                           __nv_bfloat16* __restrict__ xh, __nv_bfloat16* __restrict__ xl,
                           int pack, int wf32) {
    int i = blockIdx.x;
    int t = threadIdx.x;
    int s = start[i];
    int e = start[i + 1];
    float4 a0 = make_float4(0.f, 0.f, 0.f, 0.f);
    float4 a1 = make_float4(0.f, 0.f, 0.f, 0.f);
    float4 a2 = make_float4(0.f, 0.f, 0.f, 0.f);
    float4 a3 = make_float4(0.f, 0.f, 0.f, 0.f);
    int k = s;
    for (; k + 7 < e; k += 8) {
        int r0 = src[k], r1 = src[k + 1], r2 = src[k + 2], r3 = src[k + 3];
        int r4 = src[k + 4], r5 = src[k + 5], r6 = src[k + 6], r7 = src[k + 7];
        float w0 = nrm[k], w1 = nrm[k + 1], w2 = nrm[k + 2], w3 = nrm[k + 3];
        float w4 = nrm[k + 4], w5 = nrm[k + 5], w6 = nrm[k + 6], w7 = nrm[k + 7];
        float4 v0 = *(const float4*)&h[(size_t)r0 * hstride + t * 4];
        float4 v1 = *(const float4*)&h[(size_t)r1 * hstride + t * 4];
        float4 v2 = *(const float4*)&h[(size_t)r2 * hstride + t * 4];
        float4 v3 = *(const float4*)&h[(size_t)r3 * hstride + t * 4];
        float4 v4 = *(const float4*)&h[(size_t)r4 * hstride + t * 4];
        float4 v5 = *(const float4*)&h[(size_t)r5 * hstride + t * 4];
        float4 v6 = *(const float4*)&h[(size_t)r6 * hstride + t * 4];
        float4 v7 = *(const float4*)&h[(size_t)r7 * hstride + t * 4];
        a0.x += w0 * v0.x; a0.y += w0 * v0.y; a0.z += w0 * v0.z; a0.w += w0 * v0.w;
        a1.x += w1 * v1.x; a1.y += w1 * v1.y; a1.z += w1 * v1.z; a1.w += w1 * v1.w;
        a2.x += w2 * v2.x; a2.y += w2 * v2.y; a2.z += w2 * v2.z; a2.w += w2 * v2.w;
        a3.x += w3 * v3.x; a3.y += w3 * v3.y; a3.z += w3 * v3.z; a3.w += w3 * v3.w;
        a0.x += w4 * v4.x; a0.y += w4 * v4.y; a0.z += w4 * v4.z; a0.w += w4 * v4.w;
        a1.x += w5 * v5.x; a1.y += w5 * v5.y; a1.z += w5 * v5.z; a1.w += w5 * v5.w;
        a2.x += w6 * v6.x; a2.y += w6 * v6.y; a2.z += w6 * v6.z; a2.w += w6 * v6.w;
        a3.x += w7 * v7.x; a3.y += w7 * v7.y; a3.z += w7 * v7.z; a3.w += w7 * v7.w;
    }
    for (; k < e; k++) {
        int r = src[k];
        float w = nrm[k];
        float4 v = *(const float4*)&h[(size_t)r * hstride + t * 4];
        a0.x += w * v.x; a0.y += w * v.y; a0.z += w * v.z; a0.w += w * v.w;
    }
    float di = dinv[i];
    float sn = di * di;
    float4 hv = *(const float4*)&h[(size_t)i * hstride + t * 4];
    float4 bv = *(const float4*)&bias[t * 4];
    float4 acc;
    acc.x = a0.x + a1.x + a2.x + a3.x + sn * hv.x + bv.x;
    acc.y = a0.y + a1.y + a2.y + a3.y + sn * hv.y + bv.y;
    acc.z = a0.z + a1.z + a2.z + a3.z + sn * hv.z + bv.z;
    acc.w = a0.w + a1.w + a2.w + a3.w + sn * hv.w + bv.w;
    if (wf32) *(float4*)&out[(size_t)i * DD + t * 4] = acc;
    if (pack) {
        float r0 = fmaxf(acc.x, 0.f), r1 = fmaxf(acc.y, 0.f);
        float r2 = fmaxf(acc.z, 0.f), r3 = fmaxf(acc.w, 0.f);
        uint32_t lo0, lo1;
        uint32_t hi0 = packsplit(r0, r1, lo0);
        uint32_t hi1 = packsplit(r2, r3, lo1);
        uint2 hp, lp;
        hp.x = hi0; hp.y = hi1;
        lp.x = lo0; lp.y = lo1;
        reinterpret_cast<uint2*>(xh)[(size_t)i * 64 + t] = hp;
        reinterpret_cast<uint2*>(xl)[(size_t)i * 64 + t] = lp;
    }
}

// ---------------- meta-path attention ----------------
__global__ void attn_kernel(const float* __restrict__ b0, const float* __restrict__ b1,
                            const float* __restrict__ b2, const float* __restrict__ watt,
                            float* __restrict__ out) {
    int i = blockIdx.x;
    int t = threadIdx.x;
    size_t off = (size_t)i * DD + t;
    float x0v = fmaxf(b0[off], 0.f);
    float x1v = fmaxf(b1[off], 0.f);
    float x2v = fmaxf(b2[off], 0.f);
    float w = watt[t];
    float s0 = x0v * w, s1 = x1v * w, s2 = x2v * w;
#pragma unroll
    for (int o = 16; o; o >>= 1) {
        s0 += __shfl_xor_sync(0xffffffffu, s0, o);
        s1 += __shfl_xor_sync(0xffffffffu, s1, o);
        s2 += __shfl_xor_sync(0xffffffffu, s2, o);
    }
    __shared__ float sm[3][8];
    __shared__ float sw[3];
    int wid = t >> 5, ln = t & 31;
    if (ln == 0) { sm[0][wid] = s0; sm[1][wid] = s1; sm[2][wid] = s2; }
    __syncthreads();
    if (t == 0) {
        float t0 = 0.f, t1 = 0.f, t2 = 0.f;
#pragma unroll
        for (int kk = 0; kk < 8; kk++) { t0 += sm[0][kk]; t1 += sm[1][kk]; t2 += sm[2][kk]; }
        float mx = fmaxf(t0, fmaxf(t1, t2));
        float e0 = expf(t0 - mx), e1 = expf(t1 - mx), e2 = expf(t2 - mx);
        float inv = 1.f / (e0 + e1 + e2);
        sw[0] = e0 * inv; sw[1] = e1 * inv; sw[2] = e2 * inv;
    }
    __syncthreads();
    out[off] = sw[0] * x0v + sw[1] * x1v + sw[2] * x2v;
}

// ---------------- launcher (serial schedule — proven fastest) ----------------
extern "C" void kernel_launch(void* const* d_in, const int* in_sizes, int n_in,
                              void* d_out, int out_size) {
    const float* init = (const float*)d_in[0];
    const int*   ei[3] = {(const int*)d_in[1], (const int*)d_in[2], (const int*)d_in[3]};
    const float* ea[3] = {(const float*)d_in[4], (const float*)d_in[5], (const float*)d_in[6]};
    const float* pW1 = (const float*)d_in[7];
    const float* pb1 = (const float*)d_in[8];
    const float* pW2 = (const float*)d_in[9];
    const float* pb2 = (const float*)d_in[10];
    const float* Wb[3] = {(const float*)d_in[11], (const float*)d_in[13], (const float*)d_in[15]};
    const float* bb[3] = {(const float*)d_in[12], (const float*)d_in[14], (const float*)d_in[16]};
    const float* watt = (const float*)d_in[17];
    float* out = (float*)d_out;

    float *colemb, *h, *h0, *deg, *dinv, *nrm, *rcnt;
    float *br[3];
    int *hist, *cur, *start, *src, *bsum, *bbase;
    __nv_bfloat16 *x0h, *x0l, *xh, *xl, *Wh, *Wl, *mask, *colTh, *colTl;
    cudaGetSymbolAddress((void**)&colemb, g_colemb);
    cudaGetSymbolAddress((void**)&h,      g_h);
    cudaGetSymbolAddress((void**)&h0,     g_h0);
    cudaGetSymbolAddress((void**)&br[0],  g_br0);
    cudaGetSymbolAddress((void**)&br[1],  g_br1);
    cudaGetSymbolAddress((void**)&br[2],  g_br2);
    cudaGetSymbolAddress((void**)&deg,    g_deg);
    cudaGetSymbolAddress((void**)&dinv,   g_dinv);
    cudaGetSymbolAddress((void**)&hist,   g_hist);
    cudaGetSymbolAddress((void**)&cur,    g_cur);
    cudaGetSymbolAddress((void**)&start,  g_start);
    cudaGetSymbolAddress((void**)&bsum,   g_bsum);
    cudaGetSymbolAddress((void**)&bbase,  g_bbase);
    cudaGetSymbolAddress((void**)&src,    g_src);
    cudaGetSymbolAddress((void**)&nrm,    g_nrm);
    cudaGetSymbolAddress((void**)&rcnt,   g_rcnt);
    cudaGetSymbolAddress((void**)&mask,   g_mask);
    cudaGetSymbolAddress((void**)&colTh,  g_colTh);
    cudaGetSymbolAddress((void**)&colTl,  g_colTl);
    cudaGetSymbolAddress((void**)&x0h,    g_x0h);
    cudaGetSymbolAddress((void**)&x0l,    g_x0l);
    cudaGetSymbolAddress((void**)&xh,     g_xh);
    cudaGetSymbolAddress((void**)&xl,     g_xl);
    cudaGetSymbolAddress((void**)&Wh,     g_Wh);
    cudaGetSymbolAddress((void**)&Wl,     g_Wl);

    static int attr_set = 0;
    if (!attr_set) {
        cudaFuncSetAttribute(gemm_mma2, cudaFuncAttributeMaxDynamicSharedMemorySize, 73728);
        cudaFuncSetAttribute(x0gemm, cudaFuncAttributeMaxDynamicSharedMemorySize, 55296);
        attr_set = 1;
    }

    // ---- front end (x0 path)
    colemb_kernel<<<MCOLS, DD>>>(pW1, pb1, pW2, pb2, colemb);
    maskbuild_kernel<<<NNODES, 256>>>(init, mask, rcnt);
    colembT_kernel<<<dim3(32, 8), dim3(32, 8)>>>(colemb, colTh, colTl);
    x0gemm<<<dim3(157, 2), 256, 55296>>>(mask, colTh, colTl, rcnt, x0h, x0l);
    wconv_kernel<<<dim3(8, 8, 9), dim3(32, 8)>>>(Wb[0], Wb[1], Wb[2], Wh, Wl);

    // ---- graph prep (all branches; fast 3-phase scan)
    branch_init<<<dim3(NB, 1, 3), 256>>>(deg, hist);
    edge_count<<<dim3(EB, 1, 3), 256>>>(ei[0], ei[1], ei[2], ea[0], ea[1], ea[2], deg, hist);
    dinv_kernel<<<dim3(NB, 1, 3), 256>>>(deg, dinv);
    scanP1<<<3 * NB, 256>>>(hist, bsum);
    scanP2<<<1, 256>>>(bsum, bbase, start);
    scanP3<<<3 * NB, 256>>>(hist, bbase, start, cur);
    scatter_kernel<<<dim3(EB, 1, 3), 256>>>(ei[0], ei[1], ei[2], ea[0], ea[1], ea[2],
                                            dinv, cur, src, nrm);

    // ---- layer-0 GEMM batched across branches (Wh l-major: w'=0,1,2 -> [768][256])
    gemm_mma2<<<dim3(157, 6), 256, 73728>>>(x0h, x0l, Wh, Wl, h0, 768);

    // ---- per-branch layers (serial; L2-bound agg must own the machine)
    for (int b = 0; b < 3; b++) {
        const int* sb = src + b * NEDGE;
        const float* nb = nrm + b * NEDGE;
        const int* stb = start + b * (NNODES + 1);
        const float* db = dinv + b * NNODES;

        agg_kernel<<<NNODES, 64>>>(h0 + b * DD, 768, sb, nb, stb, db, bb[b],
                                   br[b], xh, xl, 1, 0);
        for (int l = 1; l < 3; l++) {
            int w = l * 3 + b;
            gemm_mma2<<<dim3(157, 2), 256, 73728>>>(xh, xl,
                                                    Wh + (size_t)w * DD * DD,
                                                    Wl + (size_t)w * DD * DD, h, DD);
            int last = (l == 2);
            agg_kernel<<<NNODES, 64>>>(h, DD, sb, nb, stb, db, bb[b] + l * DD,
                                       br[b], xh, xl, !last, last);
        }
    }

    attn_kernel<<<NNODES, 256>>>(br[0], br[1], br[2], watt, out);
}

// round 12
// speedup vs baseline: 1.7967x; 1.0061x over previous
#include <cuda_runtime.h>
#include <cuda_bf16.h>
#include <cstdint>

#define NNODES 20000
#define NPAD   20096            // 157 * 128
#define MCOLS  1024
#define NEDGE  640000
#define DD     256
#define NB     79               // ceil(20000/256)
#define EB     2500             // ceil(640000/256)

// ---------------- scratch (__device__ globals; zero-initialized bss) ----------------
__device__ float g_colemb[MCOLS * DD];
__device__ float g_h[NPAD * DD];
__device__ float g_h0[NPAD * 768];              // batched layer-0 output (3 branches)
__device__ float g_br0[NPAD * DD];
__device__ float g_br1[NPAD * DD];
__device__ float g_br2[NPAD * DD];
__device__ float g_deg[3 * NNODES];
__device__ float g_dinv[3 * NNODES];
__device__ int   g_hist[3 * NNODES];
__device__ int   g_cur[3 * NNODES];
__device__ int   g_start[3 * (NNODES + 1)];
__device__ int   g_bsum[3 * NB];
__device__ int   g_bbase[3 * NB];
__device__ int   g_src[3 * NEDGE];
__device__ float g_nrm[3 * NEDGE];
// x0-as-GEMM operands
__device__ __nv_bfloat16 g_mask[NPAD * MCOLS];  // bf16 0/1 mask (padded rows stay 0)
__device__ float g_rcnt[NPAD];                  // 1/max(cnt,1) (padded rows 0)
__device__ __nv_bfloat16 g_colTh[DD * MCOLS];
__device__ __nv_bfloat16 g_colTl[DD * MCOLS];
// packed bf16 hi/lo planes
__device__ __nv_bfloat16 g_x0h[NPAD * DD];
__device__ __nv_bfloat16 g_x0l[NPAD * DD];
__device__ __nv_bfloat16 g_xh[NPAD * DD];
__device__ __nv_bfloat16 g_xl[NPAD * DD];
// transposed bf16 hi/lo weights, l-major: index w' = l*3+b, each [n=256][k=256]
__device__ __nv_bfloat16 g_Wh[9 * DD * DD];
__device__ __nv_bfloat16 g_Wl[9 * DD * DD];

// ================= shared MMA helpers =================
#define KC 64
#define PITCH 36      // uint32 words per smem row (32 kpairs + 4 pad)
#define XSTAGE (3 * 128 * PITCH * 4)   // bytes per x0gemm pipeline stage

__device__ __forceinline__ void mma_bf16(float* c, const uint32_t* a, const uint32_t* b) {
    asm volatile(
        "mma.sync.aligned.m16n8k16.row.col.f32.bf16.bf16.f32 "
        "{%0,%1,%2,%3}, {%4,%5,%6,%7}, {%8,%9}, {%0,%1,%2,%3};"
        : "+f"(c[0]), "+f"(c[1]), "+f"(c[2]), "+f"(c[3])
        : "r"(a[0]), "r"(a[1]), "r"(a[2]), "r"(a[3]), "r"(b[0]), "r"(b[1]));
}
__device__ __forceinline__ void ldsm4(uint32_t* r, uint32_t addr) {
    asm volatile("ldmatrix.sync.aligned.m8n8.x4.shared.b16 {%0,%1,%2,%3}, [%4];"
        : "=r"(r[0]), "=r"(r[1]), "=r"(r[2]), "=r"(r[3]) : "r"(addr));
}
__device__ __forceinline__ void cp16(uint32_t smem_dst, const void* gsrc) {
    asm volatile("cp.async.cg.shared.global [%0], [%1], 16;" :: "r"(smem_dst), "l"(gsrc));
}
__device__ __forceinline__ uint32_t packsplit(float v0, float v1, uint32_t& lo) {
    __nv_bfloat162 h, l;
    h.x = __float2bfloat16(v0); h.y = __float2bfloat16(v1);
    l.x = __float2bfloat16(v0 - __bfloat162float(h.x));
    l.y = __float2bfloat16(v1 - __bfloat162float(h.y));
    lo = *reinterpret_cast<uint32_t*>(&l);
    return *reinterpret_cast<uint32_t*>(&h);
}

// ---------------- front-end kernels ----------------
__global__ void colemb_kernel(const float* __restrict__ pW1, const float* __restrict__ pb1,
                              const float* __restrict__ pW2, const float* __restrict__ pb2,
                              float* __restrict__ colemb) {
    int j = blockIdx.x;
    int d = threadIdx.x;
    float jf = (float)j;
    float acc = pb2[d];
#pragma unroll
    for (int k = 0; k < 16; k++) {
        float hk = fmaxf(jf * pW1[k] + pb1[k], 0.f);
        acc += hk * pW2[k * DD + d];
    }
    colemb[j * DD + d] = acc;
}

__global__ void maskbuild_kernel(const float* __restrict__ init,
                                 __nv_bfloat16* __restrict__ mask, float* __restrict__ rcnt) {
    int i = blockIdx.x;
    int t = threadIdx.x;  // 256, 4 cols each
    __shared__ int scnt;
    if (t == 0) scnt = 0;
    __syncthreads();
    float4 v = *(const float4*)&init[(size_t)i * MCOLS + t * 4];
    float m0 = (v.x != 0.f) ? 1.f : 0.f;
    float m1 = (v.y != 0.f) ? 1.f : 0.f;
    float m2 = (v.z != 0.f) ? 1.f : 0.f;
    float m3 = (v.w != 0.f) ? 1.f : 0.f;
    int c = (int)(m0 + m1 + m2 + m3);
#pragma unroll
    for (int o = 16; o; o >>= 1) c += __shfl_xor_sync(0xffffffffu, c, o);
    if ((t & 31) == 0) atomicAdd(&scnt, c);
    __nv_bfloat162 p01, p23;
    p01.x = __float2bfloat16(m0); p01.y = __float2bfloat16(m1);
    p23.x = __float2bfloat16(m2); p23.y = __float2bfloat16(m3);
    uint2 pk;
    pk.x = *reinterpret_cast<uint32_t*>(&p01);
    pk.y = *reinterpret_cast<uint32_t*>(&p23);
    *reinterpret_cast<uint2*>(&mask[(size_t)i * MCOLS + t * 4]) = pk;
    __syncthreads();
    if (t == 0) rcnt[i] = 1.f / (float)max(scnt, 1);
}

__global__ void colembT_kernel(const float* __restrict__ colemb,
                               __nv_bfloat16* __restrict__ Th, __nv_bfloat16* __restrict__ Tl) {
    __shared__ float tile[32][33];
    int j0 = blockIdx.x * 32, d0 = blockIdx.y * 32;
    int tx = threadIdx.x, ty = threadIdx.y;  // 32 x 8
#pragma unroll
    for (int i = 0; i < 32; i += 8)
        tile[ty + i][tx] = colemb[(size_t)(j0 + ty + i) * DD + d0 + tx];
    __syncthreads();
#pragma unroll
    for (int i = 0; i < 32; i += 8) {
        float v = tile[tx][ty + i];
        __nv_bfloat16 h = __float2bfloat16(v);
        size_t o = (size_t)(d0 + ty + i) * MCOLS + j0 + tx;
        Th[o] = h;
        Tl[o] = __float2bfloat16(v - __bfloat162float(h));
    }
}

__global__ void wconv_kernel(const float* __restrict__ W0, const float* __restrict__ W1,
                             const float* __restrict__ W2,
                             __nv_bfloat16* __restrict__ Ht, __nv_bfloat16* __restrict__ Lt) {
    __shared__ float tile[32][33];
    int z = blockIdx.z;           // b*3 + l
    int b = z / 3, l = z % 3;
    const float* W = (b == 0) ? W0 : (b == 1) ? W1 : W2;
    W += (size_t)l * DD * DD;
    size_t dbase = (size_t)(l * 3 + b) * DD * DD;
    int n0 = blockIdx.x * 32, k0 = blockIdx.y * 32;
    int tx = threadIdx.x, ty = threadIdx.y;  // 32 x 8
#pragma unroll
    for (int i = 0; i < 32; i += 8)
        tile[ty + i][tx] = W[(size_t)(k0 + ty + i) * DD + n0 + tx];
    __syncthreads();
#pragma unroll
    for (int i = 0; i < 32; i += 8) {
        float v = tile[tx][ty + i];
        __nv_bfloat16 h = __float2bfloat16(v);
        size_t o = dbase + (size_t)(n0 + ty + i) * DD + k0 + tx;
        Ht[o] = h;
        Lt[o] = __float2bfloat16(v - __bfloat162float(h));
    }
}

// ---------------- graph prep (grid.z = branch) ----------------
__global__ void branch_init(float* __restrict__ deg, int* __restrict__ hist) {
    int i = blockIdx.x * blockDim.x + threadIdx.x;
    int b = blockIdx.z;
    if (i < NNODES) { deg[b * NNODES + i] = 1.0f; hist[b * NNODES + i] = 0; }
}

__global__ void edge_count(const int* __restrict__ ei0, const int* __restrict__ ei1,
                           const int* __restrict__ ei2,
                           const float* __restrict__ ea0, const float* __restrict__ ea1,
                           const float* __restrict__ ea2,
                           float* __restrict__ deg, int* __restrict__ hist) {
    int e = blockIdx.x * blockDim.x + threadIdx.x;
    int b = blockIdx.z;
    const int* ei = (b == 0) ? ei0 : (b == 1) ? ei1 : ei2;
    const float* ea = (b == 0) ? ea0 : (b == 1) ? ea1 : ea2;
    if (e < NEDGE) {
        int c = ei[NEDGE + e];
        atomicAdd(&deg[b * NNODES + c], ea[e]);
        atomicAdd(&hist[b * NNODES + c], 1);
    }
}

__global__ void dinv_kernel(const float* __restrict__ deg, float* __restrict__ dinv) {
    int i = blockIdx.x * blockDim.x + threadIdx.x;
    int b = blockIdx.z;
    if (i < NNODES) dinv[b * NNODES + i] = rsqrtf(deg[b * NNODES + i]);
}

// ---- 3-phase exclusive scan over hist (per branch) ----
__global__ void scanP1(const int* __restrict__ hist, int* __restrict__ bsum) {
    int bid = blockIdx.x;        // 3*NB
    int b = bid / NB, blk = bid % NB;
    int t = threadIdx.x;         // 256
    int gi = blk * 256 + t;
    int v = (gi < NNODES) ? hist[b * NNODES + gi] : 0;
#pragma unroll
    for (int o = 16; o; o >>= 1) v += __shfl_xor_sync(0xffffffffu, v, o);
    __shared__ int ws[8];
    if ((t & 31) == 0) ws[t >> 5] = v;
    __syncthreads();
    if (t == 0) {
        int s = 0;
#pragma unroll
        for (int w = 0; w < 8; w++) s += ws[w];
        bsum[b * NB + blk] = s;
    }
}
__global__ void scanP2(const int* __restrict__ bsum, int* __restrict__ bbase,
                       int* __restrict__ start) {
    int t = threadIdx.x;
    if (t < 3) {
        int s = 0;
        for (int i = 0; i < NB; i++) {
            bbase[t * NB + i] = s;
            s += bsum[t * NB + i];
        }
        start[t * (NNODES + 1) + NNODES] = s;
    }
}
__global__ void scanP3(const int* __restrict__ hist, const int* __restrict__ bbase,
                       int* __restrict__ start, int* __restrict__ cur) {
    int bid = blockIdx.x;
    int b = bid / NB, blk = bid % NB;
    int t = threadIdx.x;
    int lane = t & 31, w = t >> 5;
    int gi = blk * 256 + t;
    int v = (gi < NNODES) ? hist[b * NNODES + gi] : 0;
    int s = v;
#pragma unroll
    for (int o = 1; o < 32; o <<= 1) {
        int x = __shfl_up_sync(0xffffffffu, s, o);
        if (lane >= o) s += x;
    }
    __shared__ int ws[8];
    if (lane == 31) ws[w] = s;
    __syncthreads();
    if (t == 0) {
        int acc = 0;
#pragma unroll
        for (int i = 0; i < 8; i++) { int x = ws[i]; ws[i] = acc; acc += x; }
    }
    __syncthreads();
    int excl = s - v + ws[w] + bbase[b * NB + blk];
    if (gi < NNODES) {
        start[b * (NNODES + 1) + gi] = excl;
        cur[b * NNODES + gi] = excl;
    }
}

__global__ void scatter_kernel(const int* __restrict__ ei0, const int* __restrict__ ei1,
                               const int* __restrict__ ei2,
                               const float* __restrict__ ea0, const float* __restrict__ ea1,
                               const float* __restrict__ ea2,
                               const float* __restrict__ dinv, int* __restrict__ cur,
                               int* __restrict__ src, float* __restrict__ nrm) {
    int e = blockIdx.x * blockDim.x + threadIdx.x;
    int b = blockIdx.z;
    const int* ei = (b == 0) ? ei0 : (b == 1) ? ei1 : ei2;
    const float* ea = (b == 0) ? ea0 : (b == 1) ? ea1 : ea2;
    if (e < NEDGE) {
        int r = ei[e];
        int c = ei[NEDGE + e];
        float n = dinv[b * NNODES + r] * ea[e] * dinv[b * NNODES + c];
        int p = atomicAdd(&cur[b * NNODES + c], 1);
        src[b * NEDGE + p] = r;
        nrm[b * NEDGE + p] = n;
    }
}

// ================= x0 GEMM (double-buffered cp.async pipeline) ==========
// x0 = (mask @ colembT) * rcnt -> bf16 hi/lo.  Two smem stages hide load latency.
__global__ void __launch_bounds__(256, 2) x0gemm(
    const __nv_bfloat16* __restrict__ Am, const __nv_bfloat16* __restrict__ Bh_g,
    const __nv_bfloat16* __restrict__ Bl_g, const float* __restrict__ rcnt,
    __nv_bfloat16* __restrict__ xh, __nv_bfloat16* __restrict__ xl) {
    extern __shared__ uint32_t smem[];

    int tid = threadIdx.x;
    int lane = tid & 31, wid = tid >> 5;
    int g = lane >> 2, tig = lane & 3;
    int wm = wid & 1, wn = wid >> 1;
    int bm = blockIdx.x * 128;
    int bn = blockIdx.y * 128;

    uint32_t s_base = (uint32_t)__cvta_generic_to_shared(smem);
    // per-stage layout: A @0, Bh @128*PITCH*4, Bl @2*128*PITCH*4; stage stride XSTAGE
    const uint32_t OFF_BH = 128 * PITCH * 4;
    const uint32_t OFF_BL = 2 * 128 * PITCH * 4;

    int lane15 = lane & 15;
    int khalf = lane >> 4;
    uint32_t A_loff = (uint32_t)((wm * 64 + lane15) * PITCH) * 4u + (uint32_t)khalf * 16u;
    int bnrow = wn * 32 + (lane >> 4) * 8 + (lane & 7);
    uint32_t B_loff = (uint32_t)(bnrow * PITCH) * 4u + (uint32_t)((lane >> 3) & 1) * 16u;

    float acc[4][4][4];
#pragma unroll
    for (int mt = 0; mt < 4; mt++)
#pragma unroll
        for (int nt = 0; nt < 4; nt++)
#pragma unroll
            for (int q = 0; q < 4; q++) acc[mt][nt][q] = 0.f;

    const int NK = MCOLS / KC;   // 16

    // --- chunk loader: stage stg <- k-chunk kc
    auto load_chunk = [&](int kc, int stg) {
        uint32_t sb = s_base + (uint32_t)stg * XSTAGE;
        int k0 = kc * KC;
#pragma unroll
        for (int i = 0; i < 4; i++) {
            int sl = tid + i * 256;
            int row = sl >> 3;
            int s = sl & 7;
            uint32_t so = (uint32_t)(row * PITCH + s * 4) * 4u;
            size_t ga = (size_t)(bm + row) * MCOLS + k0 + s * 8;
            size_t gb = (size_t)(bn + row) * MCOLS + k0 + s * 8;
            cp16(sb + so, Am + ga);
            cp16(sb + OFF_BH + so, Bh_g + gb);
            cp16(sb + OFF_BL + so, Bl_g + gb);
        }
        asm volatile("cp.async.commit_group;");
    };

    load_chunk(0, 0);

    for (int kc = 0; kc < NK; kc++) {
        if (kc + 1 < NK) {
            load_chunk(kc + 1, (kc + 1) & 1);
            asm volatile("cp.async.wait_group 1;");
        } else {
            asm volatile("cp.async.wait_group 0;");
        }
        __syncthreads();

        uint32_t sb = s_base + (uint32_t)(kc & 1) * XSTAGE;
        uint32_t sA_a = sb;
        uint32_t sBh_a = sb + OFF_BH;
        uint32_t sBl_a = sb + OFF_BL;

#pragma unroll
        for (int ks = 0; ks < 4; ks++) {
            uint32_t koff = (uint32_t)ks * 32u;
            uint32_t Bh[4][2], Bl[4][2];
#pragma unroll
            for (int ntp = 0; ntp < 2; ntp++) {
                uint32_t r[4];
                uint32_t off = B_loff + (uint32_t)(ntp * 16 * PITCH) * 4u + koff;
                ldsm4(r, sBh_a + off);
                Bh[2 * ntp][0] = r[0]; Bh[2 * ntp][1] = r[1];
                Bh[2 * ntp + 1][0] = r[2]; Bh[2 * ntp + 1][1] = r[3];
                ldsm4(r, sBl_a + off);
                Bl[2 * ntp][0] = r[0]; Bl[2 * ntp][1] = r[1];
                Bl[2 * ntp + 1][0] = r[2]; Bl[2 * ntp + 1][1] = r[3];
            }
#pragma unroll
            for (int mt = 0; mt < 4; mt++) {
                uint32_t off = A_loff + (uint32_t)(mt * 16 * PITCH) * 4u + koff;
                uint32_t Af[4];
                ldsm4(Af, sA_a + off);
#pragma unroll
                for (int nt = 0; nt < 4; nt++) {
                    mma_bf16(acc[mt][nt], Af, Bh[nt]);
                    mma_bf16(acc[mt][nt], Af, Bl[nt]);
                }
            }
        }
        __syncthreads();
    }

#pragma unroll
    for (int mt = 0; mt < 4; mt++) {
        int row = bm + wm * 64 + mt * 16 + g;
        float rc0 = rcnt[row];
        float rc1 = rcnt[row + 8];
#pragma unroll
        for (int nt = 0; nt < 4; nt++) {
            int col = bn + wn * 32 + nt * 8 + tig * 2;
            uint32_t lo;
            uint32_t hi = packsplit(acc[mt][nt][0] * rc0, acc[mt][nt][1] * rc0, lo);
            *reinterpret_cast<uint32_t*>(&xh[(size_t)row * DD + col]) = hi;
            *reinterpret_cast<uint32_t*>(&xl[(size_t)row * DD + col]) = lo;
            hi = packsplit(acc[mt][nt][2] * rc1, acc[mt][nt][3] * rc1, lo);
            *reinterpret_cast<uint32_t*>(&xh[(size_t)(row + 8) * DD + col]) = hi;
            *reinterpret_cast<uint32_t*>(&xl[(size_t)(row + 8) * DD + col]) = lo;
        }
    }
}

// ================= split-bf16 HMMA GEMM =================
__global__ void __launch_bounds__(256, 2) gemm_mma2(
    const __nv_bfloat16* __restrict__ Ah_g, const __nv_bfloat16* __restrict__ Al_g,
    const __nv_bfloat16* __restrict__ Bh_g, const __nv_bfloat16* __restrict__ Bl_g,
    float* __restrict__ C, int cstride) {
    extern __shared__ uint32_t smem[];
    uint32_t* sAh = smem;
    uint32_t* sAl = smem + 128 * PITCH;
    uint32_t* sBh = smem + 2 * 128 * PITCH;
    uint32_t* sBl = smem + 3 * 128 * PITCH;

    int tid = threadIdx.x;
    int lane = tid & 31, wid = tid >> 5;
    int g = lane >> 2, tig = lane & 3;
    int wm = wid & 1, wn = wid >> 1;
    int bm = blockIdx.x * 128;
    int bn = blockIdx.y * 128;

    uint32_t sAh_a = (uint32_t)__cvta_generic_to_shared(sAh);
    uint32_t sAl_a = (uint32_t)__cvta_generic_to_shared(sAl);
    uint32_t sBh_a = (uint32_t)__cvta_generic_to_shared(sBh);
    uint32_t sBl_a = (uint32_t)__cvta_generic_to_shared(sBl);

    int lane15 = lane & 15;
    int khalf = lane >> 4;
    uint32_t A_loff = (uint32_t)((wm * 64 + lane15) * PITCH) * 4u + (uint32_t)khalf * 16u;
    int bnrow = wn * 32 + (lane >> 4) * 8 + (lane & 7);
    uint32_t B_loff = (uint32_t)(bnrow * PITCH) * 4u + (uint32_t)((lane >> 3) & 1) * 16u;

    float acc[4][4][4];
#pragma unroll
    for (int mt = 0; mt < 4; mt++)
#pragma unroll
        for (int nt = 0; nt < 4; nt++)
#pragma unroll
            for (int q = 0; q < 4; q++) acc[mt][nt][q] = 0.f;

    for (int k0 = 0; k0 < DD; k0 += KC) {
#pragma unroll
        for (int i = 0; i < 4; i++) {
            int sl = tid + i * 256;
            int row = sl >> 3;
            int s = sl & 7;
            uint32_t so = (uint32_t)(row * PITCH + s * 4) * 4u;
            size_t ga = (size_t)(bm + row) * DD + k0 + s * 8;
            size_t gb = (size_t)(bn + row) * DD + k0 + s * 8;
            cp16(sAh_a + so, Ah_g + ga);
            cp16(sAl_a + so, Al_g + ga);
            cp16(sBh_a + so, Bh_g + gb);
            cp16(sBl_a + so, Bl_g + gb);
        }
        asm volatile("cp.async.commit_group;");
        asm volatile("cp.async.wait_group 0;");
        __syncthreads();

#pragma unroll
        for (int ks = 0; ks < 4; ks++) {
            uint32_t koff = (uint32_t)ks * 32u;
            uint32_t Bh[4][2], Bl[4][2];
#pragma unroll
            for (int ntp = 0; ntp < 2; ntp++) {
                uint32_t r[4];
                uint32_t off = B_loff + (uint32_t)(ntp * 16 * PITCH) * 4u + koff;
                ldsm4(r, sBh_a + off);
                Bh[2 * ntp][0] = r[0]; Bh[2 * ntp][1] = r[1];
                Bh[2 * ntp + 1][0] = r[2]; Bh[2 * ntp + 1][1] = r[3];
                ldsm4(r, sBl_a + off);
                Bl[2 * ntp][0] = r[0]; Bl[2 * ntp][1] = r[1];
                Bl[2 * ntp + 1][0] = r[2]; Bl[2 * ntp + 1][1] = r[3];
            }
#pragma unroll
            for (int mt = 0; mt < 4; mt++) {
                uint32_t off = A_loff + (uint32_t)(mt * 16 * PITCH) * 4u + koff;
                uint32_t Ah[4], Al[4];
                ldsm4(Ah, sAh_a + off);
                ldsm4(Al, sAl_a + off);
#pragma unroll
                for (int nt = 0; nt < 4; nt++) {
                    mma_bf16(acc[mt][nt], Ah, Bh[nt]);
                    mma_bf16(acc[mt][nt], Al, Bh[nt]);
                    mma_bf16(acc[mt][nt], Ah, Bl[nt]);
                }
            }
        }
        __syncthreads();
    }

#pragma unroll
    for (int mt = 0; mt < 4; mt++) {
        int row = bm + wm * 64 + mt * 16 + g;
#pragma unroll
        for (int nt = 0; nt < 4; nt++) {
            int col = bn + wn * 32 + nt * 8 + tig * 2;
            *(float2*)&C[(size_t)row * cstride + col] = make_float2(acc[mt][nt][0], acc[mt][nt][1]);
            *(float2*)&C[(size_t)(row + 8) * cstride + col] = make_float2(acc[mt][nt][2], acc[mt][nt][3]);
        }
    }
}

// ---------------- aggregation (1 node/block, 64 threads, no smem) --------
__global__ void __launch_bounds__(64) agg_kernel(const float* __restrict__ h, int hstride,
                           const int* __restrict__ src,
                           const float* __restrict__ nrm, const int* __restrict__ start,
                           const float* __restrict__ dinv, const float* __restrict__ bias,
                           float* __restrict__ out,
                           __nv_bfloat16* __restrict__ xh, __nv_bfloat16* __restrict__ xl,
                           int pack, int wf32) {
    int i = blockIdx.x;
    int t = threadIdx.x;
    int s = start[i];
    int e = start[i + 1];
    float4 a0 = make_float4(0.f, 0.f, 0.f, 0.f);
    float4 a1 = make_float4(0.f, 0.f, 0.f, 0.f);
    float4 a2 = make_float4(0.f, 0.f, 0.f, 0.f);
    float4 a3 = make_float4(0.f, 0.f, 0.f, 0.f);
    int k = s;
    for (; k + 7 < e; k += 8) {
        int r0 = src[k], r1 = src[k + 1], r2 = src[k + 2], r3 = src[k + 3];
        int r4 = src[k + 4], r5 = src[k + 5], r6 = src[k + 6], r7 = src[k + 7];
        float w0 = nrm[k], w1 = nrm[k + 1], w2 = nrm[k + 2], w3 = nrm[k + 3];
        float w4 = nrm[k + 4], w5 = nrm[k + 5], w6 = nrm[k + 6], w7 = nrm[k + 7];
        float4 v0 = *(const float4*)&h[(size_t)r0 * hstride + t * 4];
        float4 v1 = *(const float4*)&h[(size_t)r1 * hstride + t * 4];
        float4 v2 = *(const float4*)&h[(size_t)r2 * hstride + t * 4];
        float4 v3 = *(const float4*)&h[(size_t)r3 * hstride + t * 4];
        float4 v4 = *(const float4*)&h[(size_t)r4 * hstride + t * 4];
        float4 v5 = *(const float4*)&h[(size_t)r5 * hstride + t * 4];
        float4 v6 = *(const float4*)&h[(size_t)r6 * hstride + t * 4];
        float4 v7 = *(const float4*)&h[(size_t)r7 * hstride + t * 4];
        a0.x += w0 * v0.x; a0.y += w0 * v0.y; a0.z += w0 * v0.z; a0.w += w0 * v0.w;
        a1.x += w1 * v1.x; a1.y += w1 * v1.y; a1.z += w1 * v1.z; a1.w += w1 * v1.w;
        a2.x += w2 * v2.x; a2.y += w2 * v2.y; a2.z += w2 * v2.z; a2.w += w2 * v2.w;
        a3.x += w3 * v3.x; a3.y += w3 * v3.y; a3.z += w3 * v3.z; a3.w += w3 * v3.w;
        a0.x += w4 * v4.x; a0.y += w4 * v4.y; a0.z += w4 * v4.z; a0.w += w4 * v4.w;
        a1.x += w5 * v5.x; a1.y += w5 * v5.y; a1.z += w5 * v5.z; a1.w += w5 * v5.w;
        a2.x += w6 * v6.x; a2.y += w6 * v6.y; a2.z += w6 * v6.z; a2.w += w6 * v6.w;
        a3.x += w7 * v7.x; a3.y += w7 * v7.y; a3.z += w7 * v7.z; a3.w += w7 * v7.w;
    }
    for (; k < e; k++) {
        int r = src[k];
        float w = nrm[k];
        float4 v = *(const float4*)&h[(size_t)r * hstride + t * 4];
        a0.x += w * v.x; a0.y += w * v.y; a0.z += w * v.z; a0.w += w * v.w;
    }
    float di = dinv[i];
    float sn = di * di;
    float4 hv = *(const float4*)&h[(size_t)i * hstride + t * 4];
    float4 bv = *(const float4*)&bias[t * 4];
    float4 acc;
    acc.x = a0.x + a1.x + a2.x + a3.x + sn * hv.x + bv.x;
    acc.y = a0.y + a1.y + a2.y + a3.y + sn * hv.y + bv.y;
    acc.z = a0.z + a1.z + a2.z + a3.z + sn * hv.z + bv.z;
    acc.w = a0.w + a1.w + a2.w + a3.w + sn * hv.w + bv.w;
    if (wf32) *(float4*)&out[(size_t)i * DD + t * 4] = acc;
    if (pack) {
        float r0 = fmaxf(acc.x, 0.f), r1 = fmaxf(acc.y, 0.f);
        float r2 = fmaxf(acc.z, 0.f), r3 = fmaxf(acc.w, 0.f);
        uint32_t lo0, lo1;
        uint32_t hi0 = packsplit(r0, r1, lo0);
        uint32_t hi1 = packsplit(r2, r3, lo1);
        uint2 hp, lp;
        hp.x = hi0; hp.y = hi1;
        lp.x = lo0; lp.y = lo1;
        reinterpret_cast<uint2*>(xh)[(size_t)i * 64 + t] = hp;
        reinterpret_cast<uint2*>(xl)[(size_t)i * 64 + t] = lp;
    }
}

// ---------------- meta-path attention ----------------
__global__ void attn_kernel(const float* __restrict__ b0, const float* __restrict__ b1,
                            const float* __restrict__ b2, const float* __restrict__ watt,
                            float* __restrict__ out) {
    int i = blockIdx.x;
    int t = threadIdx.x;
    size_t off = (size_t)i * DD + t;
    float x0v = fmaxf(b0[off], 0.f);
    float x1v = fmaxf(b1[off], 0.f);
    float x2v = fmaxf(b2[off], 0.f);
    float w = watt[t];
    float s0 = x0v * w, s1 = x1v * w, s2 = x2v * w;
#pragma unroll
    for (int o = 16; o; o >>= 1) {
        s0 += __shfl_xor_sync(0xffffffffu, s0, o);
        s1 += __shfl_xor_sync(0xffffffffu, s1, o);
        s2 += __shfl_xor_sync(0xffffffffu, s2, o);
    }
    __shared__ float sm[3][8];
    __shared__ float sw[3];
    int wid = t >> 5, ln = t & 31;
    if (ln == 0) { sm[0][wid] = s0; sm[1][wid] = s1; sm[2][wid] = s2; }
    __syncthreads();
    if (t == 0) {
        float t0 = 0.f, t1 = 0.f, t2 = 0.f;
#pragma unroll
        for (int kk = 0; kk < 8; kk++) { t0 += sm[0][kk]; t1 += sm[1][kk]; t2 += sm[2][kk]; }
        float mx = fmaxf(t0, fmaxf(t1, t2));
        float e0 = expf(t0 - mx), e1 = expf(t1 - mx), e2 = expf(t2 - mx);
        float inv = 1.f / (e0 + e1 + e2);
        sw[0] = e0 * inv; sw[1] = e1 * inv; sw[2] = e2 * inv;
    }
    __syncthreads();
    out[off] = sw[0] * x0v + sw[1] * x1v + sw[2] * x2v;
}

// ---------------- launcher (serial schedule — proven fastest) ----------------
extern "C" void kernel_launch(void* const* d_in, const int* in_sizes, int n_in,
                              void* d_out, int out_size) {
    const float* init = (const float*)d_in[0];
    const int*   ei[3] = {(const int*)d_in[1], (const int*)d_in[2], (const int*)d_in[3]};
    const float* ea[3] = {(const float*)d_in[4], (const float*)d_in[5], (const float*)d_in[6]};
    const float* pW1 = (const float*)d_in[7];
    const float* pb1 = (const float*)d_in[8];
    const float* pW2 = (const float*)d_in[9];
    const float* pb2 = (const float*)d_in[10];
    const float* Wb[3] = {(const float*)d_in[11], (const float*)d_in[13], (const float*)d_in[15]};
    const float* bb[3] = {(const float*)d_in[12], (const float*)d_in[14], (const float*)d_in[16]};
    const float* watt = (const float*)d_in[17];
    float* out = (float*)d_out;

    float *colemb, *h, *h0, *deg, *dinv, *nrm, *rcnt;
    float *br[3];
    int *hist, *cur, *start, *src, *bsum, *bbase;
    __nv_bfloat16 *x0h, *x0l, *xh, *xl, *Wh, *Wl, *mask, *colTh, *colTl;
    cudaGetSymbolAddress((void**)&colemb, g_colemb);
    cudaGetSymbolAddress((void**)&h,      g_h);
    cudaGetSymbolAddress((void**)&h0,     g_h0);
    cudaGetSymbolAddress((void**)&br[0],  g_br0);
    cudaGetSymbolAddress((void**)&br[1],  g_br1);
    cudaGetSymbolAddress((void**)&br[2],  g_br2);
    cudaGetSymbolAddress((void**)&deg,    g_deg);
    cudaGetSymbolAddress((void**)&dinv,   g_dinv);
    cudaGetSymbolAddress((void**)&hist,   g_hist);
    cudaGetSymbolAddress((void**)&cur,    g_cur);
    cudaGetSymbolAddress((void**)&start,  g_start);
    cudaGetSymbolAddress((void**)&bsum,   g_bsum);
    cudaGetSymbolAddress((void**)&bbase,  g_bbase);
    cudaGetSymbolAddress((void**)&src,    g_src);
    cudaGetSymbolAddress((void**)&nrm,    g_nrm);
    cudaGetSymbolAddress((void**)&rcnt,   g_rcnt);
    cudaGetSymbolAddress((void**)&mask,   g_mask);
    cudaGetSymbolAddress((void**)&colTh,  g_colTh);
    cudaGetSymbolAddress((void**)&colTl,  g_colTl);
    cudaGetSymbolAddress((void**)&x0h,    g_x0h);
    cudaGetSymbolAddress((void**)&x0l,    g_x0l);
    cudaGetSymbolAddress((void**)&xh,     g_xh);
    cudaGetSymbolAddress((void**)&xl,     g_xl);
    cudaGetSymbolAddress((void**)&Wh,     g_Wh);
    cudaGetSymbolAddress((void**)&Wl,     g_Wl);

    static int attr_set = 0;
    if (!attr_set) {
        cudaFuncSetAttribute(gemm_mma2, cudaFuncAttributeMaxDynamicSharedMemorySize, 73728);
        cudaFuncSetAttribute(x0gemm, cudaFuncAttributeMaxDynamicSharedMemorySize, 2 * XSTAGE);
        attr_set = 1;
    }

    // ---- front end (x0 path)
    colemb_kernel<<<MCOLS, DD>>>(pW1, pb1, pW2, pb2, colemb);
    maskbuild_kernel<<<NNODES, 256>>>(init, mask, rcnt);
    colembT_kernel<<<dim3(32, 8), dim3(32, 8)>>>(colemb, colTh, colTl);
    x0gemm<<<dim3(157, 2), 256, 2 * XSTAGE>>>(mask, colTh, colTl, rcnt, x0h, x0l);
    wconv_kernel<<<dim3(8, 8, 9), dim3(32, 8)>>>(Wb[0], Wb[1], Wb[2], Wh, Wl);

    // ---- graph prep (all branches; fast 3-phase scan)
    branch_init<<<dim3(NB, 1, 3), 256>>>(deg, hist);
    edge_count<<<dim3(EB, 1, 3), 256>>>(ei[0], ei[1], ei[2], ea[0], ea[1], ea[2], deg, hist);
    dinv_kernel<<<dim3(NB, 1, 3), 256>>>(deg, dinv);
    scanP1<<<3 * NB, 256>>>(hist, bsum);
    scanP2<<<1, 256>>>(bsum, bbase, start);
    scanP3<<<3 * NB, 256>>>(hist, bbase, start, cur);
    scatter_kernel<<<dim3(EB, 1, 3), 256>>>(ei[0], ei[1], ei[2], ea[0], ea[1], ea[2],
                                            dinv, cur, src, nrm);

    // ---- layer-0 GEMM batched across branches (Wh l-major: w'=0,1,2 -> [768][256])
    gemm_mma2<<<dim3(157, 6), 256, 73728>>>(x0h, x0l, Wh, Wl, h0, 768);

    // ---- per-branch layers (serial; L2-bound agg must own the machine)
    for (int b = 0; b < 3; b++) {
        const int* sb = src + b * NEDGE;
        const float* nb = nrm + b * NEDGE;
        const int* stb = start + b * (NNODES + 1);
        const float* db = dinv + b * NNODES;

        agg_kernel<<<NNODES, 64>>>(h0 + b * DD, 768, sb, nb, stb, db, bb[b],
                                   br[b], xh, xl, 1, 0);
        for (int l = 1; l < 3; l++) {
            int w = l * 3 + b;
            gemm_mma2<<<dim3(157, 2), 256, 73728>>>(xh, xl,
                                                    Wh + (size_t)w * DD * DD,
                                                    Wl + (size_t)w * DD * DD, h, DD);
            int last = (l == 2);
            agg_kernel<<<NNODES, 64>>>(h, DD, sb, nb, stb, db, bb[b] + l * DD,
                                       br[b], xh, xl, !last, last);
        }
    }

    attn_kernel<<<NNODES, 256>>>(br[0], br[1], br[2], watt, out);
}

// round 13
// speedup vs baseline: 1.8656x; 1.0383x over previous
#include <cuda_runtime.h>
#include <cuda_bf16.h>
#include <cstdint>

#define NNODES 20000
#define NPAD   20096            // 157 * 128
#define MCOLS  1024
#define NEDGE  640000
#define DD     256
#define NB     79               // ceil(20000/256)
#define EB     2500             // ceil(640000/256)

// ---------------- scratch (__device__ globals; zero-initialized bss) ----------------
__device__ float g_colemb[MCOLS * DD];
__device__ float g_h0[NPAD * 768];              // batched layer-0 output (3 branches)
__device__ float g_hb[3 * NPAD * DD];           // per-branch GEMM outputs
__device__ float g_br0[NPAD * DD];
__device__ float g_br1[NPAD * DD];
__device__ float g_br2[NPAD * DD];
__device__ float g_deg[3 * NNODES];
__device__ float g_dinv[3 * NNODES];
__device__ int   g_hist[3 * NNODES];
__device__ int   g_cur[3 * NNODES];
__device__ int   g_start[3 * (NNODES + 1)];
__device__ int   g_bsum[3 * NB];
__device__ int   g_bbase[3 * NB];
__device__ int   g_src[3 * NEDGE];
__device__ float g_nrm[3 * NEDGE];
// x0-as-GEMM operands
__device__ __nv_bfloat16 g_mask[NPAD * MCOLS];  // bf16 0/1 mask (padded rows stay 0)
__device__ float g_rcnt[NPAD];                  // 1/max(cnt,1) (padded rows 0)
__device__ __nv_bfloat16 g_colTh[DD * MCOLS];
__device__ __nv_bfloat16 g_colTl[DD * MCOLS];
// packed bf16 hi/lo planes
__device__ __nv_bfloat16 g_x0h[NPAD * DD];
__device__ __nv_bfloat16 g_x0l[NPAD * DD];
__device__ __nv_bfloat16 g_xhb[3 * NPAD * DD];  // per-branch
__device__ __nv_bfloat16 g_xlb[3 * NPAD * DD];
// transposed bf16 hi/lo weights, l-major: index w' = l*3+b, each [n=256][k=256]
__device__ __nv_bfloat16 g_Wh[9 * DD * DD];
__device__ __nv_bfloat16 g_Wl[9 * DD * DD];

// ================= shared MMA helpers =================
#define KC 64
#define PITCH 36      // uint32 words per smem row (32 kpairs + 4 pad)
// x0gemm stage: A(64 rows) + Bh(128) + Bl(128) = 320 rows
#define XSTG (320 * PITCH * 4)

__device__ __forceinline__ void mma_bf16(float* c, const uint32_t* a, const uint32_t* b) {
    asm volatile(
        "mma.sync.aligned.m16n8k16.row.col.f32.bf16.bf16.f32 "
        "{%0,%1,%2,%3}, {%4,%5,%6,%7}, {%8,%9}, {%0,%1,%2,%3};"
        : "+f"(c[0]), "+f"(c[1]), "+f"(c[2]), "+f"(c[3])
        : "r"(a[0]), "r"(a[1]), "r"(a[2]), "r"(a[3]), "r"(b[0]), "r"(b[1]));
}
__device__ __forceinline__ void ldsm4(uint32_t* r, uint32_t addr) {
    asm volatile("ldmatrix.sync.aligned.m8n8.x4.shared.b16 {%0,%1,%2,%3}, [%4];"
        : "=r"(r[0]), "=r"(r[1]), "=r"(r[2]), "=r"(r[3]) : "r"(addr));
}
__device__ __forceinline__ void cp16(uint32_t smem_dst, const void* gsrc) {
    asm volatile("cp.async.cg.shared.global [%0], [%1], 16;" :: "r"(smem_dst), "l"(gsrc));
}
__device__ __forceinline__ uint32_t packsplit(float v0, float v1, uint32_t& lo) {
    __nv_bfloat162 h, l;
    h.x = __float2bfloat16(v0); h.y = __float2bfloat16(v1);
    l.x = __float2bfloat16(v0 - __bfloat162float(h.x));
    l.y = __float2bfloat16(v1 - __bfloat162float(h.y));
    lo = *reinterpret_cast<uint32_t*>(&l);
    return *reinterpret_cast<uint32_t*>(&h);
}

// ---------------- front-end kernels ----------------
__global__ void colemb_kernel(const float* __restrict__ pW1, const float* __restrict__ pb1,
                              const float* __restrict__ pW2, const float* __restrict__ pb2,
                              float* __restrict__ colemb) {
    int j = blockIdx.x;
    int d = threadIdx.x;
    float jf = (float)j;
    float acc = pb2[d];
#pragma unroll
    for (int k = 0; k < 16; k++) {
        float hk = fmaxf(jf * pW1[k] + pb1[k], 0.f);
        acc += hk * pW2[k * DD + d];
    }
    colemb[j * DD + d] = acc;
}

__global__ void maskbuild_kernel(const float* __restrict__ init,
                                 __nv_bfloat16* __restrict__ mask, float* __restrict__ rcnt) {
    int i = blockIdx.x;
    int t = threadIdx.x;  // 256, 4 cols each
    __shared__ int scnt;
    if (t == 0) scnt = 0;
    __syncthreads();
    float4 v = *(const float4*)&init[(size_t)i * MCOLS + t * 4];
    float m0 = (v.x != 0.f) ? 1.f : 0.f;
    float m1 = (v.y != 0.f) ? 1.f : 0.f;
    float m2 = (v.z != 0.f) ? 1.f : 0.f;
    float m3 = (v.w != 0.f) ? 1.f : 0.f;
    int c = (int)(m0 + m1 + m2 + m3);
#pragma unroll
    for (int o = 16; o; o >>= 1) c += __shfl_xor_sync(0xffffffffu, c, o);
    if ((t & 31) == 0) atomicAdd(&scnt, c);
    __nv_bfloat162 p01, p23;
    p01.x = __float2bfloat16(m0); p01.y = __float2bfloat16(m1);
    p23.x = __float2bfloat16(m2); p23.y = __float2bfloat16(m3);
    uint2 pk;
    pk.x = *reinterpret_cast<uint32_t*>(&p01);
    pk.y = *reinterpret_cast<uint32_t*>(&p23);
    *reinterpret_cast<uint2*>(&mask[(size_t)i * MCOLS + t * 4]) = pk;
    __syncthreads();
    if (t == 0) rcnt[i] = 1.f / (float)max(scnt, 1);
}

__global__ void colembT_kernel(const float* __restrict__ colemb,
                               __nv_bfloat16* __restrict__ Th, __nv_bfloat16* __restrict__ Tl) {
    __shared__ float tile[32][33];
    int j0 = blockIdx.x * 32, d0 = blockIdx.y * 32;
    int tx = threadIdx.x, ty = threadIdx.y;  // 32 x 8
#pragma unroll
    for (int i = 0; i < 32; i += 8)
        tile[ty + i][tx] = colemb[(size_t)(j0 + ty + i) * DD + d0 + tx];
    __syncthreads();
#pragma unroll
    for (int i = 0; i < 32; i += 8) {
        float v = tile[tx][ty + i];
        __nv_bfloat16 h = __float2bfloat16(v);
        size_t o = (size_t)(d0 + ty + i) * MCOLS + j0 + tx;
        Th[o] = h;
        Tl[o] = __float2bfloat16(v - __bfloat162float(h));
    }
}

__global__ void wconv_kernel(const float* __restrict__ W0, const float* __restrict__ W1,
                             const float* __restrict__ W2,
                             __nv_bfloat16* __restrict__ Ht, __nv_bfloat16* __restrict__ Lt) {
    __shared__ float tile[32][33];
    int z = blockIdx.z;           // b*3 + l
    int b = z / 3, l = z % 3;
    const float* W = (b == 0) ? W0 : (b == 1) ? W1 : W2;
    W += (size_t)l * DD * DD;
    size_t dbase = (size_t)(l * 3 + b) * DD * DD;
    int n0 = blockIdx.x * 32, k0 = blockIdx.y * 32;
    int tx = threadIdx.x, ty = threadIdx.y;  // 32 x 8
#pragma unroll
    for (int i = 0; i < 32; i += 8)
        tile[ty + i][tx] = W[(size_t)(k0 + ty + i) * DD + n0 + tx];
    __syncthreads();
#pragma unroll
    for (int i = 0; i < 32; i += 8) {
        float v = tile[tx][ty + i];
        __nv_bfloat16 h = __float2bfloat16(v);
        size_t o = dbase + (size_t)(n0 + ty + i) * DD + k0 + tx;
        Ht[o] = h;
        Lt[o] = __float2bfloat16(v - __bfloat162float(h));
    }
}

// ---------------- graph prep (grid.z = branch) ----------------
__global__ void branch_init(float* __restrict__ deg, int* __restrict__ hist) {
    int i = blockIdx.x * blockDim.x + threadIdx.x;
    int b = blockIdx.z;
    if (i < NNODES) { deg[b * NNODES + i] = 1.0f; hist[b * NNODES + i] = 0; }
}

__global__ void edge_count(const int* __restrict__ ei0, const int* __restrict__ ei1,
                           const int* __restrict__ ei2,
                           const float* __restrict__ ea0, const float* __restrict__ ea1,
                           const float* __restrict__ ea2,
                           float* __restrict__ deg, int* __restrict__ hist) {
    int e = blockIdx.x * blockDim.x + threadIdx.x;
    int b = blockIdx.z;
    const int* ei = (b == 0) ? ei0 : (b == 1) ? ei1 : ei2;
    const float* ea = (b == 0) ? ea0 : (b == 1) ? ea1 : ea2;
    if (e < NEDGE) {
        int c = ei[NEDGE + e];
        atomicAdd(&deg[b * NNODES + c], ea[e]);
        atomicAdd(&hist[b * NNODES + c], 1);
    }
}

__global__ void dinv_kernel(const float* __restrict__ deg, float* __restrict__ dinv) {
    int i = blockIdx.x * blockDim.x + threadIdx.x;
    int b = blockIdx.z;
    if (i < NNODES) dinv[b * NNODES + i] = rsqrtf(deg[b * NNODES + i]);
}

// ---- 3-phase exclusive scan over hist (per branch) ----
__global__ void scanP1(const int* __restrict__ hist, int* __restrict__ bsum) {
    int bid = blockIdx.x;        // 3*NB
    int b = bid / NB, blk = bid % NB;
    int t = threadIdx.x;         // 256
    int gi = blk * 256 + t;
    int v = (gi < NNODES) ? hist[b * NNODES + gi] : 0;
#pragma unroll
    for (int o = 16; o; o >>= 1) v += __shfl_xor_sync(0xffffffffu, v, o);
    __shared__ int ws[8];
    if ((t & 31) == 0) ws[t >> 5] = v;
    __syncthreads();
    if (t == 0) {
        int s = 0;
#pragma unroll
        for (int w = 0; w < 8; w++) s += ws[w];
        bsum[b * NB + blk] = s;
    }
}
__global__ void scanP2(const int* __restrict__ bsum, int* __restrict__ bbase,
                       int* __restrict__ start) {
    int t = threadIdx.x;
    if (t < 3) {
        int s = 0;
        for (int i = 0; i < NB; i++) {
            bbase[t * NB + i] = s;
            s += bsum[t * NB + i];
        }
        start[t * (NNODES + 1) + NNODES] = s;
    }
}
__global__ void scanP3(const int* __restrict__ hist, const int* __restrict__ bbase,
                       int* __restrict__ start, int* __restrict__ cur) {
    int bid = blockIdx.x;
    int b = bid / NB, blk = bid % NB;
    int t = threadIdx.x;
    int lane = t & 31, w = t >> 5;
    int gi = blk * 256 + t;
    int v = (gi < NNODES) ? hist[b * NNODES + gi] : 0;
    int s = v;
#pragma unroll
    for (int o = 1; o < 32; o <<= 1) {
        int x = __shfl_up_sync(0xffffffffu, s, o);
        if (lane >= o) s += x;
    }
    __shared__ int ws[8];
    if (lane == 31) ws[w] = s;
    __syncthreads();
    if (t == 0) {
        int acc = 0;
#pragma unroll
        for (int i = 0; i < 8; i++) { int x = ws[i]; ws[i] = acc; acc += x; }
    }
    __syncthreads();
    int excl = s - v + ws[w] + bbase[b * NB + blk];
    if (gi < NNODES) {
        start[b * (NNODES + 1) + gi] = excl;
        cur[b * NNODES + gi] = excl;
    }
}

__global__ void scatter_kernel(const int* __restrict__ ei0, const int* __restrict__ ei1,
                               const int* __restrict__ ei2,
                               const float* __restrict__ ea0, const float* __restrict__ ea1,
                               const float* __restrict__ ea2,
                               const float* __restrict__ dinv, int* __restrict__ cur,
                               int* __restrict__ src, float* __restrict__ nrm) {
    int e = blockIdx.x * blockDim.x + threadIdx.x;
    int b = blockIdx.z;
    const int* ei = (b == 0) ? ei0 : (b == 1) ? ei1 : ei2;
    const float* ea = (b == 0) ? ea0 : (b == 1) ? ea1 : ea2;
    if (e < NEDGE) {
        int r = ei[e];
        int c = ei[NEDGE + e];
        float n = dinv[b * NNODES + r] * ea[e] * dinv[b * NNODES + c];
        int p = atomicAdd(&cur[b * NNODES + c], 1);
        src[b * NEDGE + p] = r;
        nrm[b * NEDGE + p] = n;
    }
}

// ================= x0 GEMM (M-tile 64, double-buffered) ==========
// x0 = (mask @ colembT) * rcnt -> bf16 hi/lo. grid (314, 2). 8 warps = 2(M:32) x 4(N:32).
__global__ void __launch_bounds__(256, 2) x0gemm(
    const __nv_bfloat16* __restrict__ Am, const __nv_bfloat16* __restrict__ Bh_g,
    const __nv_bfloat16* __restrict__ Bl_g, const float* __restrict__ rcnt,
    __nv_bfloat16* __restrict__ xh, __nv_bfloat16* __restrict__ xl) {
    extern __shared__ uint32_t smem[];

    int tid = threadIdx.x;
    int lane = tid & 31, wid = tid >> 5;
    int g = lane >> 2, tig = lane & 3;
    int wm = wid & 1, wn = wid >> 1;
    int bm = blockIdx.x * 64;
    int bn = blockIdx.y * 128;

    uint32_t s_base = (uint32_t)__cvta_generic_to_shared(smem);
    const uint32_t OFF_BH = 64 * PITCH * 4;
    const uint32_t OFF_BL = (64 + 128) * PITCH * 4;

    int lane15 = lane & 15;
    int khalf = lane >> 4;
    uint32_t A_loff = (uint32_t)((wm * 32 + lane15) * PITCH) * 4u + (uint32_t)khalf * 16u;
    int bnrow = wn * 32 + (lane >> 4) * 8 + (lane & 7);
    uint32_t B_loff = (uint32_t)(bnrow * PITCH) * 4u + (uint32_t)((lane >> 3) & 1) * 16u;

    float acc[2][4][4];
#pragma unroll
    for (int mt = 0; mt < 2; mt++)
#pragma unroll
        for (int nt = 0; nt < 4; nt++)
#pragma unroll
            for (int q = 0; q < 4; q++) acc[mt][nt][q] = 0.f;

    const int NK = MCOLS / KC;   // 16

    auto load_chunk = [&](int kc, int stg) {
        uint32_t sb = s_base + (uint32_t)stg * XSTG;
        int k0 = kc * KC;
        // A: 64 rows x 8 segs = 512
#pragma unroll
        for (int i = 0; i < 2; i++) {
            int sl = tid + i * 256;
            int row = sl >> 3;
            int s = sl & 7;
            uint32_t so = (uint32_t)(row * PITCH + s * 4) * 4u;
            cp16(sb + so, Am + (size_t)(bm + row) * MCOLS + k0 + s * 8);
        }
        // B: 128 rows x 8 segs per plane
#pragma unroll
        for (int i = 0; i < 4; i++) {
            int sl = tid + i * 256;
            int row = sl >> 3;
            int s = sl & 7;
            uint32_t so = (uint32_t)(row * PITCH + s * 4) * 4u;
            size_t gb = (size_t)(bn + row) * MCOLS + k0 + s * 8;
            cp16(sb + OFF_BH + so, Bh_g + gb);
            cp16(sb + OFF_BL + so, Bl_g + gb);
        }
        asm volatile("cp.async.commit_group;");
    };

    load_chunk(0, 0);

    for (int kc = 0; kc < NK; kc++) {
        if (kc + 1 < NK) {
            load_chunk(kc + 1, (kc + 1) & 1);
            asm volatile("cp.async.wait_group 1;");
        } else {
            asm volatile("cp.async.wait_group 0;");
        }
        __syncthreads();

        uint32_t sb = s_base + (uint32_t)(kc & 1) * XSTG;
        uint32_t sA_a = sb;
        uint32_t sBh_a = sb + OFF_BH;
        uint32_t sBl_a = sb + OFF_BL;

#pragma unroll
        for (int ks = 0; ks < 4; ks++) {
            uint32_t koff = (uint32_t)ks * 32u;
            uint32_t Bh[4][2], Bl[4][2];
#pragma unroll
            for (int ntp = 0; ntp < 2; ntp++) {
                uint32_t r[4];
                uint32_t off = B_loff + (uint32_t)(ntp * 16 * PITCH) * 4u + koff;
                ldsm4(r, sBh_a + off);
                Bh[2 * ntp][0] = r[0]; Bh[2 * ntp][1] = r[1];
                Bh[2 * ntp + 1][0] = r[2]; Bh[2 * ntp + 1][1] = r[3];
                ldsm4(r, sBl_a + off);
                Bl[2 * ntp][0] = r[0]; Bl[2 * ntp][1] = r[1];
                Bl[2 * ntp + 1][0] = r[2]; Bl[2 * ntp + 1][1] = r[3];
            }
#pragma unroll
            for (int mt = 0; mt < 2; mt++) {
                uint32_t off = A_loff + (uint32_t)(mt * 16 * PITCH) * 4u + koff;
                uint32_t Af[4];
                ldsm4(Af, sA_a + off);
#pragma unroll
                for (int nt = 0; nt < 4; nt++) {
                    mma_bf16(acc[mt][nt], Af, Bh[nt]);
                    mma_bf16(acc[mt][nt], Af, Bl[nt]);
                }
            }
        }
        __syncthreads();
    }

#pragma unroll
    for (int mt = 0; mt < 2; mt++) {
        int row = bm + wm * 32 + mt * 16 + g;
        float rc0 = rcnt[row];
        float rc1 = rcnt[row + 8];
#pragma unroll
        for (int nt = 0; nt < 4; nt++) {
            int col = bn + wn * 32 + nt * 8 + tig * 2;
            uint32_t lo;
            uint32_t hi = packsplit(acc[mt][nt][0] * rc0, acc[mt][nt][1] * rc0, lo);
            *reinterpret_cast<uint32_t*>(&xh[(size_t)row * DD + col]) = hi;
            *reinterpret_cast<uint32_t*>(&xl[(size_t)row * DD + col]) = lo;
            hi = packsplit(acc[mt][nt][2] * rc1, acc[mt][nt][3] * rc1, lo);
            *reinterpret_cast<uint32_t*>(&xh[(size_t)(row + 8) * DD + col]) = hi;
            *reinterpret_cast<uint32_t*>(&xl[(size_t)(row + 8) * DD + col]) = lo;
        }
    }
}

// ================= split-bf16 HMMA GEMM core (device fn) =================
__device__ __forceinline__ void gemm_core(
    const __nv_bfloat16* __restrict__ Ah_g, const __nv_bfloat16* __restrict__ Al_g,
    const __nv_bfloat16* __restrict__ Bh_g, const __nv_bfloat16* __restrict__ Bl_g,
    float* __restrict__ C, int cstride, int bm, int bn, uint32_t* smem) {
    uint32_t* sAh = smem;
    uint32_t* sAl = smem + 128 * PITCH;
    uint32_t* sBh = smem + 2 * 128 * PITCH;
    uint32_t* sBl = smem + 3 * 128 * PITCH;

    int tid = threadIdx.x;
    int lane = tid & 31, wid = tid >> 5;
    int g = lane >> 2, tig = lane & 3;
    int wm = wid & 1, wn = wid >> 1;

    uint32_t sAh_a = (uint32_t)__cvta_generic_to_shared(sAh);
    uint32_t sAl_a = (uint32_t)__cvta_generic_to_shared(sAl);
    uint32_t sBh_a = (uint32_t)__cvta_generic_to_shared(sBh);
    uint32_t sBl_a = (uint32_t)__cvta_generic_to_shared(sBl);

    int lane15 = lane & 15;
    int khalf = lane >> 4;
    uint32_t A_loff = (uint32_t)((wm * 64 + lane15) * PITCH) * 4u + (uint32_t)khalf * 16u;
    int bnrow = wn * 32 + (lane >> 4) * 8 + (lane & 7);
    uint32_t B_loff = (uint32_t)(bnrow * PITCH) * 4u + (uint32_t)((lane >> 3) & 1) * 16u;

    float acc[4][4][4];
#pragma unroll
    for (int mt = 0; mt < 4; mt++)
#pragma unroll
        for (int nt = 0; nt < 4; nt++)
#pragma unroll
            for (int q = 0; q < 4; q++) acc[mt][nt][q] = 0.f;

    for (int k0 = 0; k0 < DD; k0 += KC) {
#pragma unroll
        for (int i = 0; i < 4; i++) {
            int sl = tid + i * 256;
            int row = sl >> 3;
            int s = sl & 7;
            uint32_t so = (uint32_t)(row * PITCH + s * 4) * 4u;
            size_t ga = (size_t)(bm + row) * DD + k0 + s * 8;
            size_t gb = (size_t)(bn + row) * DD + k0 + s * 8;
            cp16(sAh_a + so, Ah_g + ga);
            cp16(sAl_a + so, Al_g + ga);
            cp16(sBh_a + so, Bh_g + gb);
            cp16(sBl_a + so, Bl_g + gb);
        }
        asm volatile("cp.async.commit_group;");
        asm volatile("cp.async.wait_group 0;");
        __syncthreads();

#pragma unroll
        for (int ks = 0; ks < 4; ks++) {
            uint32_t koff = (uint32_t)ks * 32u;
            uint32_t Bh[4][2], Bl[4][2];
#pragma unroll
            for (int ntp = 0; ntp < 2; ntp++) {
                uint32_t r[4];
                uint32_t off = B_loff + (uint32_t)(ntp * 16 * PITCH) * 4u + koff;
                ldsm4(r, sBh_a + off);
                Bh[2 * ntp][0] = r[0]; Bh[2 * ntp][1] = r[1];
                Bh[2 * ntp + 1][0] = r[2]; Bh[2 * ntp + 1][1] = r[3];
                ldsm4(r, sBl_a + off);
                Bl[2 * ntp][0] = r[0]; Bl[2 * ntp][1] = r[1];
                Bl[2 * ntp + 1][0] = r[2]; Bl[2 * ntp + 1][1] = r[3];
            }
#pragma unroll
            for (int mt = 0; mt < 4; mt++) {
                uint32_t off = A_loff + (uint32_t)(mt * 16 * PITCH) * 4u + koff;
                uint32_t Ah[4], Al[4];
                ldsm4(Ah, sAh_a + off);
                ldsm4(Al, sAl_a + off);
#pragma unroll
                for (int nt = 0; nt < 4; nt++) {
                    mma_bf16(acc[mt][nt], Ah, Bh[nt]);
                    mma_bf16(acc[mt][nt], Al, Bh[nt]);
                    mma_bf16(acc[mt][nt], Ah, Bl[nt]);
                }
            }
        }
        __syncthreads();
    }

#pragma unroll
    for (int mt = 0; mt < 4; mt++) {
        int row = bm + wm * 64 + mt * 16 + g;
#pragma unroll
        for (int nt = 0; nt < 4; nt++) {
            int col = bn + wn * 32 + nt * 8 + tig * 2;
            *(float2*)&C[(size_t)row * cstride + col] = make_float2(acc[mt][nt][0], acc[mt][nt][1]);
            *(float2*)&C[(size_t)(row + 8) * cstride + col] = make_float2(acc[mt][nt][2], acc[mt][nt][3]);
        }
    }
}

// layer-0: C [NPAD][768]
__global__ void __launch_bounds__(256, 2) gemm_mma2(
    const __nv_bfloat16* __restrict__ Ah_g, const __nv_bfloat16* __restrict__ Al_g,
    const __nv_bfloat16* __restrict__ Bh_g, const __nv_bfloat16* __restrict__ Bl_g,
    float* __restrict__ C, int cstride) {
    extern __shared__ uint32_t smem[];
    gemm_core(Ah_g, Al_g, Bh_g, Bl_g, C, cstride, blockIdx.x * 128, blockIdx.y * 128, smem);
}

// batched over branches: z = branch; weight index = wbase + z (l-major layout)
__global__ void __launch_bounds__(256, 2) gemm_mma3(
    const __nv_bfloat16* __restrict__ Ah_base, const __nv_bfloat16* __restrict__ Al_base,
    const __nv_bfloat16* __restrict__ Wh_base, const __nv_bfloat16* __restrict__ Wl_base,
    float* __restrict__ C_base, int wbase) {
    extern __shared__ uint32_t smem[];
    int z = blockIdx.z;
    gemm_core(Ah_base + (size_t)z * NPAD * DD, Al_base + (size_t)z * NPAD * DD,
              Wh_base + (size_t)(wbase + z) * DD * DD, Wl_base + (size_t)(wbase + z) * DD * DD,
              C_base + (size_t)z * NPAD * DD, DD, blockIdx.x * 128, blockIdx.y * 128, smem);
}

// ---------------- aggregation (1 node/block, 64 threads, no smem) --------
__global__ void __launch_bounds__(64) agg_kernel(const float* __restrict__ h, int hstride,
                           const int* __restrict__ src,
                           const float* __restrict__ nrm, const int* __restrict__ start,
                           const float* __restrict__ dinv, const float* __restrict__ bias,
                           float* __restrict__ out,
                           __nv_bfloat16* __restrict__ xh, __nv_bfloat16* __restrict__ xl,
                           int pack, int wf32) {
    int i = blockIdx.x;
    int t = threadIdx.x;
    int s = start[i];
    int e = start[i + 1];
    float4 a0 = make_float4(0.f, 0.f, 0.f, 0.f);
    float4 a1 = make_float4(0.f, 0.f, 0.f, 0.f);
    float4 a2 = make_float4(0.f, 0.f, 0.f, 0.f);
    float4 a3 = make_float4(0.f, 0.f, 0.f, 0.f);
    int k = s;
    for (; k + 7 < e; k += 8) {
        int r0 = src[k], r1 = src[k + 1], r2 = src[k + 2], r3 = src[k + 3];
        int r4 = src[k + 4], r5 = src[k + 5], r6 = src[k + 6], r7 = src[k + 7];
        float w0 = nrm[k], w1 = nrm[k + 1], w2 = nrm[k + 2], w3 = nrm[k + 3];
        float w4 = nrm[k + 4], w5 = nrm[k + 5], w6 = nrm[k + 6], w7 = nrm[k + 7];
        float4 v0 = *(const float4*)&h[(size_t)r0 * hstride + t * 4];
        float4 v1 = *(const float4*)&h[(size_t)r1 * hstride + t * 4];
        float4 v2 = *(const float4*)&h[(size_t)r2 * hstride + t * 4];
        float4 v3 = *(const float4*)&h[(size_t)r3 * hstride + t * 4];
        float4 v4 = *(const float4*)&h[(size_t)r4 * hstride + t * 4];
        float4 v5 = *(const float4*)&h[(size_t)r5 * hstride + t * 4];
        float4 v6 = *(const float4*)&h[(size_t)r6 * hstride + t * 4];
        float4 v7 = *(const float4*)&h[(size_t)r7 * hstride + t * 4];
        a0.x += w0 * v0.x; a0.y += w0 * v0.y; a0.z += w0 * v0.z; a0.w += w0 * v0.w;
        a1.x += w1 * v1.x; a1.y += w1 * v1.y; a1.z += w1 * v1.z; a1.w += w1 * v1.w;
        a2.x += w2 * v2.x; a2.y += w2 * v2.y; a2.z += w2 * v2.z; a2.w += w2 * v2.w;
        a3.x += w3 * v3.x; a3.y += w3 * v3.y; a3.z += w3 * v3.z; a3.w += w3 * v3.w;
        a0.x += w4 * v4.x; a0.y += w4 * v4.y; a0.z += w4 * v4.z; a0.w += w4 * v4.w;
        a1.x += w5 * v5.x; a1.y += w5 * v5.y; a1.z += w5 * v5.z; a1.w += w5 * v5.w;
        a2.x += w6 * v6.x; a2.y += w6 * v6.y; a2.z += w6 * v6.z; a2.w += w6 * v6.w;
        a3.x += w7 * v7.x; a3.y += w7 * v7.y; a3.z += w7 * v7.z; a3.w += w7 * v7.w;
    }
    for (; k < e; k++) {
        int r = src[k];
        float w = nrm[k];
        float4 v = *(const float4*)&h[(size_t)r * hstride + t * 4];
        a0.x += w * v.x; a0.y += w * v.y; a0.z += w * v.z; a0.w += w * v.w;
    }
    float di = dinv[i];
    float sn = di * di;
    float4 hv = *(const float4*)&h[(size_t)i * hstride + t * 4];
    float4 bv = *(const float4*)&bias[t * 4];
    float4 acc;
    acc.x = a0.x + a1.x + a2.x + a3.x + sn * hv.x + bv.x;
    acc.y = a0.y + a1.y + a2.y + a3.y + sn * hv.y + bv.y;
    acc.z = a0.z + a1.z + a2.z + a3.z + sn * hv.z + bv.z;
    acc.w = a0.w + a1.w + a2.w + a3.w + sn * hv.w + bv.w;
    if (wf32) *(float4*)&out[(size_t)i * DD + t * 4] = acc;
    if (pack) {
        float r0 = fmaxf(acc.x, 0.f), r1 = fmaxf(acc.y, 0.f);
        float r2 = fmaxf(acc.z, 0.f), r3 = fmaxf(acc.w, 0.f);
        uint32_t lo0, lo1;
        uint32_t hi0 = packsplit(r0, r1, lo0);
        uint32_t hi1 = packsplit(r2, r3, lo1);
        uint2 hp, lp;
        hp.x = hi0; hp.y = hi1;
        lp.x = lo0; lp.y = lo1;
        reinterpret_cast<uint2*>(xh)[(size_t)i * 64 + t] = hp;
        reinterpret_cast<uint2*>(xl)[(size_t)i * 64 + t] = lp;
    }
}

// ---------------- meta-path attention ----------------
__global__ void attn_kernel(const float* __restrict__ b0, const float* __restrict__ b1,
                            const float* __restrict__ b2, const float* __restrict__ watt,
                            float* __restrict__ out) {
    int i = blockIdx.x;
    int t = threadIdx.x;
    size_t off = (size_t)i * DD + t;
    float x0v = fmaxf(b0[off], 0.f);
    float x1v = fmaxf(b1[off], 0.f);
    float x2v = fmaxf(b2[off], 0.f);
    float w = watt[t];
    float s0 = x0v * w, s1 = x1v * w, s2 = x2v * w;
#pragma unroll
    for (int o = 16; o; o >>= 1) {
        s0 += __shfl_xor_sync(0xffffffffu, s0, o);
        s1 += __shfl_xor_sync(0xffffffffu, s1, o);
        s2 += __shfl_xor_sync(0xffffffffu, s2, o);
    }
    __shared__ float sm[3][8];
    __shared__ float sw[3];
    int wid = t >> 5, ln = t & 31;
    if (ln == 0) { sm[0][wid] = s0; sm[1][wid] = s1; sm[2][wid] = s2; }
    __syncthreads();
    if (t == 0) {
        float t0 = 0.f, t1 = 0.f, t2 = 0.f;
#pragma unroll
        for (int kk = 0; kk < 8; kk++) { t0 += sm[0][kk]; t1 += sm[1][kk]; t2 += sm[2][kk]; }
        float mx = fmaxf(t0, fmaxf(t1, t2));
        float e0 = expf(t0 - mx), e1 = expf(t1 - mx), e2 = expf(t2 - mx);
        float inv = 1.f / (e0 + e1 + e2);
        sw[0] = e0 * inv; sw[1] = e1 * inv; sw[2] = e2 * inv;
    }
    __syncthreads();
    out[off] = sw[0] * x0v + sw[1] * x1v + sw[2] * x2v;
}

// ---------------- launcher (serial schedule, layer-major batched GEMMs) ----------------
extern "C" void kernel_launch(void* const* d_in, const int* in_sizes, int n_in,
                              void* d_out, int out_size) {
    const float* init = (const float*)d_in[0];
    const int*   ei[3] = {(const int*)d_in[1], (const int*)d_in[2], (const int*)d_in[3]};
    const float* ea[3] = {(const float*)d_in[4], (const float*)d_in[5], (const float*)d_in[6]};
    const float* pW1 = (const float*)d_in[7];
    const float* pb1 = (const float*)d_in[8];
    const float* pW2 = (const float*)d_in[9];
    const float* pb2 = (const float*)d_in[10];
    const float* Wb[3] = {(const float*)d_in[11], (const float*)d_in[13], (const float*)d_in[15]};
    const float* bb[3] = {(const float*)d_in[12], (const float*)d_in[14], (const float*)d_in[16]};
    const float* watt = (const float*)d_in[17];
    float* out = (float*)d_out;

    float *colemb, *h0, *hb, *deg, *dinv, *nrm, *rcnt;
    float *br[3];
    int *hist, *cur, *start, *src, *bsum, *bbase;
    __nv_bfloat16 *x0h, *x0l, *xhb, *xlb, *Wh, *Wl, *mask, *colTh, *colTl;
    cudaGetSymbolAddress((void**)&colemb, g_colemb);
    cudaGetSymbolAddress((void**)&h0,     g_h0);
    cudaGetSymbolAddress((void**)&hb,     g_hb);
    cudaGetSymbolAddress((void**)&br[0],  g_br0);
    cudaGetSymbolAddress((void**)&br[1],  g_br1);
    cudaGetSymbolAddress((void**)&br[2],  g_br2);
    cudaGetSymbolAddress((void**)&deg,    g_deg);
    cudaGetSymbolAddress((void**)&dinv,   g_dinv);
    cudaGetSymbolAddress((void**)&hist,   g_hist);
    cudaGetSymbolAddress((void**)&cur,    g_cur);
    cudaGetSymbolAddress((void**)&start,  g_start);
    cudaGetSymbolAddress((void**)&bsum,   g_bsum);
    cudaGetSymbolAddress((void**)&bbase,  g_bbase);
    cudaGetSymbolAddress((void**)&src,    g_src);
    cudaGetSymbolAddress((void**)&nrm,    g_nrm);
    cudaGetSymbolAddress((void**)&rcnt,   g_rcnt);
    cudaGetSymbolAddress((void**)&mask,   g_mask);
    cudaGetSymbolAddress((void**)&colTh,  g_colTh);
    cudaGetSymbolAddress((void**)&colTl,  g_colTl);
    cudaGetSymbolAddress((void**)&x0h,    g_x0h);
    cudaGetSymbolAddress((void**)&x0l,    g_x0l);
    cudaGetSymbolAddress((void**)&xhb,    g_xhb);
    cudaGetSymbolAddress((void**)&xlb,    g_xlb);
    cudaGetSymbolAddress((void**)&Wh,     g_Wh);
    cudaGetSymbolAddress((void**)&Wl,     g_Wl);

    static int attr_set = 0;
    if (!attr_set) {
        cudaFuncSetAttribute(gemm_mma2, cudaFuncAttributeMaxDynamicSharedMemorySize, 73728);
        cudaFuncSetAttribute(gemm_mma3, cudaFuncAttributeMaxDynamicSharedMemorySize, 73728);
        cudaFuncSetAttribute(x0gemm, cudaFuncAttributeMaxDynamicSharedMemorySize, 2 * XSTG);
        attr_set = 1;
    }

    // ---- front end (x0 path)
    colemb_kernel<<<MCOLS, DD>>>(pW1, pb1, pW2, pb2, colemb);
    maskbuild_kernel<<<NNODES, 256>>>(init, mask, rcnt);
    colembT_kernel<<<dim3(32, 8), dim3(32, 8)>>>(colemb, colTh, colTl);
    x0gemm<<<dim3(314, 2), 256, 2 * XSTG>>>(mask, colTh, colTl, rcnt, x0h, x0l);
    wconv_kernel<<<dim3(8, 8, 9), dim3(32, 8)>>>(Wb[0], Wb[1], Wb[2], Wh, Wl);

    // ---- graph prep (all branches; fast 3-phase scan)
    branch_init<<<dim3(NB, 1, 3), 256>>>(deg, hist);
    edge_count<<<dim3(EB, 1, 3), 256>>>(ei[0], ei[1], ei[2], ea[0], ea[1], ea[2], deg, hist);
    dinv_kernel<<<dim3(NB, 1, 3), 256>>>(deg, dinv);
    scanP1<<<3 * NB, 256>>>(hist, bsum);
    scanP2<<<1, 256>>>(bsum, bbase, start);
    scanP3<<<3 * NB, 256>>>(hist, bbase, start, cur);
    scatter_kernel<<<dim3(EB, 1, 3), 256>>>(ei[0], ei[1], ei[2], ea[0], ea[1], ea[2],
                                            dinv, cur, src, nrm);

    // ---- layer-0 GEMM batched across branches (Wh l-major: w'=0,1,2 -> [768][256])
    gemm_mma2<<<dim3(157, 6), 256, 73728>>>(x0h, x0l, Wh, Wl, h0, 768);

    // ---- layer-major schedule: per-layer aggs, then one batched GEMM for all branches
    // layer 0 aggs (input h0, stride 768) -> pack xhb/xlb per branch
    for (int b = 0; b < 3; b++)
        agg_kernel<<<NNODES, 64>>>(h0 + b * DD, 768, src + b * NEDGE, nrm + b * NEDGE,
                                   start + b * (NNODES + 1), dinv + b * NNODES, bb[b],
                                   br[b], xhb + (size_t)b * NPAD * DD,
                                   xlb + (size_t)b * NPAD * DD, 1, 0);
    // layer 1 GEMMs (w = 3+b), batched
    gemm_mma3<<<dim3(157, 2, 3), 256, 73728>>>(xhb, xlb, Wh, Wl, hb, 3);
    for (int b = 0; b < 3; b++)
        agg_kernel<<<NNODES, 64>>>(hb + (size_t)b * NPAD * DD, DD, src + b * NEDGE,
                                   nrm + b * NEDGE, start + b * (NNODES + 1),
                                   dinv + b * NNODES, bb[b] + DD,
                                   br[b], xhb + (size_t)b * NPAD * DD,
                                   xlb + (size_t)b * NPAD * DD, 1, 0);
    // layer 2 GEMMs (w = 6+b), batched
    gemm_mma3<<<dim3(157, 2, 3), 256, 73728>>>(xhb, xlb, Wh, Wl, hb, 6);
    for (int b = 0; b < 3; b++)
        agg_kernel<<<NNODES, 64>>>(hb + (size_t)b * NPAD * DD, DD, src + b * NEDGE,
                                   nrm + b * NEDGE, start + b * (NNODES + 1),
                                   dinv + b * NNODES, bb[b] + 2 * DD,
                                   br[b], xhb, xlb, 0, 1);

    attn_kernel<<<NNODES, 256>>>(br[0], br[1], br[2], watt, out);
}

// round 14
// speedup vs baseline: 2.0348x; 1.0907x over previous
#include <cuda_runtime.h>
#include <cuda_bf16.h>
#include <cstdint>

#define NNODES 20000
#define NPAD   20096            // 157 * 128
#define MCOLS  1024
#define NEDGE  640000
#define DD     256
#define NB     79               // ceil(20000/256)
#define EB     2500             // ceil(640000/256)

// ---------------- scratch (__device__ globals; zero-initialized bss) ----------------
__device__ float g_colemb[MCOLS * DD];
__device__ __nv_bfloat16 g_h0[NPAD * 768];      // batched layer-0 output (bf16)
__device__ __nv_bfloat16 g_hb[3 * NPAD * DD];   // per-branch GEMM outputs (bf16)
__device__ float g_br0[NPAD * DD];
__device__ float g_br1[NPAD * DD];
__device__ float g_br2[NPAD * DD];
__device__ float g_deg[3 * NNODES];
__device__ float g_dinv[3 * NNODES];
__device__ int   g_hist[3 * NNODES];
__device__ int   g_cur[3 * NNODES];
__device__ int   g_start[3 * (NNODES + 1)];
__device__ int   g_bsum[3 * NB];
__device__ int   g_bbase[3 * NB];
__device__ int   g_src[3 * NEDGE];
__device__ float g_nrm[3 * NEDGE];
// x0-as-GEMM operands
__device__ __nv_bfloat16 g_mask[NPAD * MCOLS];  // bf16 0/1 mask (padded rows stay 0)
__device__ float g_rcnt[NPAD];                  // 1/max(cnt,1) (padded rows 0)
__device__ __nv_bfloat16 g_colTh[DD * MCOLS];
__device__ __nv_bfloat16 g_colTl[DD * MCOLS];
// packed bf16 hi/lo planes
__device__ __nv_bfloat16 g_x0h[NPAD * DD];
__device__ __nv_bfloat16 g_x0l[NPAD * DD];
__device__ __nv_bfloat16 g_xhb[3 * NPAD * DD];  // per-branch
__device__ __nv_bfloat16 g_xlb[3 * NPAD * DD];
// transposed bf16 hi/lo weights, l-major: index w' = l*3+b, each [n=256][k=256]
__device__ __nv_bfloat16 g_Wh[9 * DD * DD];
__device__ __nv_bfloat16 g_Wl[9 * DD * DD];

// ================= shared MMA helpers =================
#define KC 64
#define PITCH 36      // uint32 words per smem row (32 kpairs + 4 pad)
// x0gemm stage: A(64 rows) + Bh(128) + Bl(128) = 320 rows
#define XSTG (320 * PITCH * 4)

__device__ __forceinline__ void mma_bf16(float* c, const uint32_t* a, const uint32_t* b) {
    asm volatile(
        "mma.sync.aligned.m16n8k16.row.col.f32.bf16.bf16.f32 "
        "{%0,%1,%2,%3}, {%4,%5,%6,%7}, {%8,%9}, {%0,%1,%2,%3};"
        : "+f"(c[0]), "+f"(c[1]), "+f"(c[2]), "+f"(c[3])
        : "r"(a[0]), "r"(a[1]), "r"(a[2]), "r"(a[3]), "r"(b[0]), "r"(b[1]));
}
__device__ __forceinline__ void ldsm4(uint32_t* r, uint32_t addr) {
    asm volatile("ldmatrix.sync.aligned.m8n8.x4.shared.b16 {%0,%1,%2,%3}, [%4];"
        : "=r"(r[0]), "=r"(r[1]), "=r"(r[2]), "=r"(r[3]) : "r"(addr));
}
__device__ __forceinline__ void cp16(uint32_t smem_dst, const void* gsrc) {
    asm volatile("cp.async.cg.shared.global [%0], [%1], 16;" :: "r"(smem_dst), "l"(gsrc));
}
__device__ __forceinline__ uint32_t packsplit(float v0, float v1, uint32_t& lo) {
    __nv_bfloat162 h, l;
    h.x = __float2bfloat16(v0); h.y = __float2bfloat16(v1);
    l.x = __float2bfloat16(v0 - __bfloat162float(h.x));
    l.y = __float2bfloat16(v1 - __bfloat162float(h.y));
    lo = *reinterpret_cast<uint32_t*>(&l);
    return *reinterpret_cast<uint32_t*>(&h);
}
__device__ __forceinline__ uint32_t packbf2(float v0, float v1) {
    __nv_bfloat162 h;
    h.x = __float2bfloat16(v0); h.y = __float2bfloat16(v1);
    return *reinterpret_cast<uint32_t*>(&h);
}

// ---------------- front-end kernels ----------------
__global__ void colemb_kernel(const float* __restrict__ pW1, const float* __restrict__ pb1,
                              const float* __restrict__ pW2, const float* __restrict__ pb2,
                              float* __restrict__ colemb) {
    int j = blockIdx.x;
    int d = threadIdx.x;
    float jf = (float)j;
    float acc = pb2[d];
#pragma unroll
    for (int k = 0; k < 16; k++) {
        float hk = fmaxf(jf * pW1[k] + pb1[k], 0.f);
        acc += hk * pW2[k * DD + d];
    }
    colemb[j * DD + d] = acc;
}

__global__ void maskbuild_kernel(const float* __restrict__ init,
                                 __nv_bfloat16* __restrict__ mask, float* __restrict__ rcnt) {
    int i = blockIdx.x;
    int t = threadIdx.x;  // 256, 4 cols each
    __shared__ int scnt;
    if (t == 0) scnt = 0;
    __syncthreads();
    float4 v = *(const float4*)&init[(size_t)i * MCOLS + t * 4];
    float m0 = (v.x != 0.f) ? 1.f : 0.f;
    float m1 = (v.y != 0.f) ? 1.f : 0.f;
    float m2 = (v.z != 0.f) ? 1.f : 0.f;
    float m3 = (v.w != 0.f) ? 1.f : 0.f;
    int c = (int)(m0 + m1 + m2 + m3);
#pragma unroll
    for (int o = 16; o; o >>= 1) c += __shfl_xor_sync(0xffffffffu, c, o);
    if ((t & 31) == 0) atomicAdd(&scnt, c);
    uint2 pk;
    pk.x = packbf2(m0, m1);
    pk.y = packbf2(m2, m3);
    *reinterpret_cast<uint2*>(&mask[(size_t)i * MCOLS + t * 4]) = pk;
    __syncthreads();
    if (t == 0) rcnt[i] = 1.f / (float)max(scnt, 1);
}

__global__ void colembT_kernel(const float* __restrict__ colemb,
                               __nv_bfloat16* __restrict__ Th, __nv_bfloat16* __restrict__ Tl) {
    __shared__ float tile[32][33];
    int j0 = blockIdx.x * 32, d0 = blockIdx.y * 32;
    int tx = threadIdx.x, ty = threadIdx.y;  // 32 x 8
#pragma unroll
    for (int i = 0; i < 32; i += 8)
        tile[ty + i][tx] = colemb[(size_t)(j0 + ty + i) * DD + d0 + tx];
    __syncthreads();
#pragma unroll
    for (int i = 0; i < 32; i += 8) {
        float v = tile[tx][ty + i];
        __nv_bfloat16 h = __float2bfloat16(v);
        size_t o = (size_t)(d0 + ty + i) * MCOLS + j0 + tx;
        Th[o] = h;
        Tl[o] = __float2bfloat16(v - __bfloat162float(h));
    }
}

__global__ void wconv_kernel(const float* __restrict__ W0, const float* __restrict__ W1,
                             const float* __restrict__ W2,
                             __nv_bfloat16* __restrict__ Ht, __nv_bfloat16* __restrict__ Lt) {
    __shared__ float tile[32][33];
    int z = blockIdx.z;           // b*3 + l
    int b = z / 3, l = z % 3;
    const float* W = (b == 0) ? W0 : (b == 1) ? W1 : W2;
    W += (size_t)l * DD * DD;
    size_t dbase = (size_t)(l * 3 + b) * DD * DD;
    int n0 = blockIdx.x * 32, k0 = blockIdx.y * 32;
    int tx = threadIdx.x, ty = threadIdx.y;  // 32 x 8
#pragma unroll
    for (int i = 0; i < 32; i += 8)
        tile[ty + i][tx] = W[(size_t)(k0 + ty + i) * DD + n0 + tx];
    __syncthreads();
#pragma unroll
    for (int i = 0; i < 32; i += 8) {
        float v = tile[tx][ty + i];
        __nv_bfloat16 h = __float2bfloat16(v);
        size_t o = dbase + (size_t)(n0 + ty + i) * DD + k0 + tx;
        Ht[o] = h;
        Lt[o] = __float2bfloat16(v - __bfloat162float(h));
    }
}

// ---------------- graph prep (grid.z = branch) ----------------
__global__ void branch_init(float* __restrict__ deg, int* __restrict__ hist) {
    int i = blockIdx.x * blockDim.x + threadIdx.x;
    int b = blockIdx.z;
    if (i < NNODES) { deg[b * NNODES + i] = 1.0f; hist[b * NNODES + i] = 0; }
}

__global__ void edge_count(const int* __restrict__ ei0, const int* __restrict__ ei1,
                           const int* __restrict__ ei2,
                           const float* __restrict__ ea0, const float* __restrict__ ea1,
                           const float* __restrict__ ea2,
                           float* __restrict__ deg, int* __restrict__ hist) {
    int e = blockIdx.x * blockDim.x + threadIdx.x;
    int b = blockIdx.z;
    const int* ei = (b == 0) ? ei0 : (b == 1) ? ei1 : ei2;
    const float* ea = (b == 0) ? ea0 : (b == 1) ? ea1 : ea2;
    if (e < NEDGE) {
        int c = ei[NEDGE + e];
        atomicAdd(&deg[b * NNODES + c], ea[e]);
        atomicAdd(&hist[b * NNODES + c], 1);
    }
}

__global__ void dinv_kernel(const float* __restrict__ deg, float* __restrict__ dinv) {
    int i = blockIdx.x * blockDim.x + threadIdx.x;
    int b = blockIdx.z;
    if (i < NNODES) dinv[b * NNODES + i] = rsqrtf(deg[b * NNODES + i]);
}

// ---- 3-phase exclusive scan over hist (per branch) ----
__global__ void scanP1(const int* __restrict__ hist, int* __restrict__ bsum) {
    int bid = blockIdx.x;        // 3*NB
    int b = bid / NB, blk = bid % NB;
    int t = threadIdx.x;         // 256
    int gi = blk * 256 + t;
    int v = (gi < NNODES) ? hist[b * NNODES + gi] : 0;
#pragma unroll
    for (int o = 16; o; o >>= 1) v += __shfl_xor_sync(0xffffffffu, v, o);
    __shared__ int ws[8];
    if ((t & 31) == 0) ws[t >> 5] = v;
    __syncthreads();
    if (t == 0) {
        int s = 0;
#pragma unroll
        for (int w = 0; w < 8; w++) s += ws[w];
        bsum[b * NB + blk] = s;
    }
}
__global__ void scanP2(const int* __restrict__ bsum, int* __restrict__ bbase,
                       int* __restrict__ start) {
    int t = threadIdx.x;
    if (t < 3) {
        int s = 0;
        for (int i = 0; i < NB; i++) {
            bbase[t * NB + i] = s;
            s += bsum[t * NB + i];
        }
        start[t * (NNODES + 1) + NNODES] = s;
    }
}
__global__ void scanP3(const int* __restrict__ hist, const int* __restrict__ bbase,
                       int* __restrict__ start, int* __restrict__ cur) {
    int bid = blockIdx.x;
    int b = bid / NB, blk = bid % NB;
    int t = threadIdx.x;
    int lane = t & 31, w = t >> 5;
    int gi = blk * 256 + t;
    int v = (gi < NNODES) ? hist[b * NNODES + gi] : 0;
    int s = v;
#pragma unroll
    for (int o = 1; o < 32; o <<= 1) {
        int x = __shfl_up_sync(0xffffffffu, s, o);
        if (lane >= o) s += x;
    }
    __shared__ int ws[8];
    if (lane == 31) ws[w] = s;
    __syncthreads();
    if (t == 0) {
        int acc = 0;
#pragma unroll
        for (int i = 0; i < 8; i++) { int x = ws[i]; ws[i] = acc; acc += x; }
    }
    __syncthreads();
    int excl = s - v + ws[w] + bbase[b * NB + blk];
    if (gi < NNODES) {
        start[b * (NNODES + 1) + gi] = excl;
        cur[b * NNODES + gi] = excl;
    }
}

__global__ void scatter_kernel(const int* __restrict__ ei0, const int* __restrict__ ei1,
                               const int* __restrict__ ei2,
                               const float* __restrict__ ea0, const float* __restrict__ ea1,
                               const float* __restrict__ ea2,
                               const float* __restrict__ dinv, int* __restrict__ cur,
                               int* __restrict__ src, float* __restrict__ nrm) {
    int e = blockIdx.x * blockDim.x + threadIdx.x;
    int b = blockIdx.z;
    const int* ei = (b == 0) ? ei0 : (b == 1) ? ei1 : ei2;
    const float* ea = (b == 0) ? ea0 : (b == 1) ? ea1 : ea2;
    if (e < NEDGE) {
        int r = ei[e];
        int c = ei[NEDGE + e];
        float n = dinv[b * NNODES + r] * ea[e] * dinv[b * NNODES + c];
        int p = atomicAdd(&cur[b * NNODES + c], 1);
        src[b * NEDGE + p] = r;
        nrm[b * NEDGE + p] = n;
    }
}

// ================= x0 GEMM (M-tile 64, double-buffered) ==========
__global__ void __launch_bounds__(256, 2) x0gemm(
    const __nv_bfloat16* __restrict__ Am, const __nv_bfloat16* __restrict__ Bh_g,
    const __nv_bfloat16* __restrict__ Bl_g, const float* __restrict__ rcnt,
    __nv_bfloat16* __restrict__ xh, __nv_bfloat16* __restrict__ xl) {
    extern __shared__ uint32_t smem[];

    int tid = threadIdx.x;
    int lane = tid & 31, wid = tid >> 5;
    int g = lane >> 2, tig = lane & 3;
    int wm = wid & 1, wn = wid >> 1;
    int bm = blockIdx.x * 64;
    int bn = blockIdx.y * 128;

    uint32_t s_base = (uint32_t)__cvta_generic_to_shared(smem);
    const uint32_t OFF_BH = 64 * PITCH * 4;
    const uint32_t OFF_BL = (64 + 128) * PITCH * 4;

    int lane15 = lane & 15;
    int khalf = lane >> 4;
    uint32_t A_loff = (uint32_t)((wm * 32 + lane15) * PITCH) * 4u + (uint32_t)khalf * 16u;
    int bnrow = wn * 32 + (lane >> 4) * 8 + (lane & 7);
    uint32_t B_loff = (uint32_t)(bnrow * PITCH) * 4u + (uint32_t)((lane >> 3) & 1) * 16u;

    float acc[2][4][4];
#pragma unroll
    for (int mt = 0; mt < 2; mt++)
#pragma unroll
        for (int nt = 0; nt < 4; nt++)
#pragma unroll
            for (int q = 0; q < 4; q++) acc[mt][nt][q] = 0.f;

    const int NK = MCOLS / KC;   // 16

    auto load_chunk = [&](int kc, int stg) {
        uint32_t sb = s_base + (uint32_t)stg * XSTG;
        int k0 = kc * KC;
#pragma unroll
        for (int i = 0; i < 2; i++) {
            int sl = tid + i * 256;
            int row = sl >> 3;
            int s = sl & 7;
            uint32_t so = (uint32_t)(row * PITCH + s * 4) * 4u;
            cp16(sb + so, Am + (size_t)(bm + row) * MCOLS + k0 + s * 8);
        }
#pragma unroll
        for (int i = 0; i < 4; i++) {
            int sl = tid + i * 256;
            int row = sl >> 3;
            int s = sl & 7;
            uint32_t so = (uint32_t)(row * PITCH + s * 4) * 4u;
            size_t gb = (size_t)(bn + row) * MCOLS + k0 + s * 8;
            cp16(sb + OFF_BH + so, Bh_g + gb);
            cp16(sb + OFF_BL + so, Bl_g + gb);
        }
        asm volatile("cp.async.commit_group;");
    };

    load_chunk(0, 0);

    for (int kc = 0; kc < NK; kc++) {
        if (kc + 1 < NK) {
            load_chunk(kc + 1, (kc + 1) & 1);
            asm volatile("cp.async.wait_group 1;");
        } else {
            asm volatile("cp.async.wait_group 0;");
        }
        __syncthreads();

        uint32_t sb = s_base + (uint32_t)(kc & 1) * XSTG;
        uint32_t sA_a = sb;
        uint32_t sBh_a = sb + OFF_BH;
        uint32_t sBl_a = sb + OFF_BL;

#pragma unroll
        for (int ks = 0; ks < 4; ks++) {
            uint32_t koff = (uint32_t)ks * 32u;
            uint32_t Bh[4][2], Bl[4][2];
#pragma unroll
            for (int ntp = 0; ntp < 2; ntp++) {
                uint32_t r[4];
                uint32_t off = B_loff + (uint32_t)(ntp * 16 * PITCH) * 4u + koff;
                ldsm4(r, sBh_a + off);
                Bh[2 * ntp][0] = r[0]; Bh[2 * ntp][1] = r[1];
                Bh[2 * ntp + 1][0] = r[2]; Bh[2 * ntp + 1][1] = r[3];
                ldsm4(r, sBl_a + off);
                Bl[2 * ntp][0] = r[0]; Bl[2 * ntp][1] = r[1];
                Bl[2 * ntp + 1][0] = r[2]; Bl[2 * ntp + 1][1] = r[3];
            }
#pragma unroll
            for (int mt = 0; mt < 2; mt++) {
                uint32_t off = A_loff + (uint32_t)(mt * 16 * PITCH) * 4u + koff;
                uint32_t Af[4];
                ldsm4(Af, sA_a + off);
#pragma unroll
                for (int nt = 0; nt < 4; nt++) {
                    mma_bf16(acc[mt][nt], Af, Bh[nt]);
                    mma_bf16(acc[mt][nt], Af, Bl[nt]);
                }
            }
        }
        __syncthreads();
    }

#pragma unroll
    for (int mt = 0; mt < 2; mt++) {
        int row = bm + wm * 32 + mt * 16 + g;
        float rc0 = rcnt[row];
        float rc1 = rcnt[row + 8];
#pragma unroll
        for (int nt = 0; nt < 4; nt++) {
            int col = bn + wn * 32 + nt * 8 + tig * 2;
            uint32_t lo;
            uint32_t hi = packsplit(acc[mt][nt][0] * rc0, acc[mt][nt][1] * rc0, lo);
            *reinterpret_cast<uint32_t*>(&xh[(size_t)row * DD + col]) = hi;
            *reinterpret_cast<uint32_t*>(&xl[(size_t)row * DD + col]) = lo;
            hi = packsplit(acc[mt][nt][2] * rc1, acc[mt][nt][3] * rc1, lo);
            *reinterpret_cast<uint32_t*>(&xh[(size_t)(row + 8) * DD + col]) = hi;
            *reinterpret_cast<uint32_t*>(&xl[(size_t)(row + 8) * DD + col]) = lo;
        }
    }
}

// ================= split-bf16 HMMA GEMM core (bf16 output) =================
__device__ __forceinline__ void gemm_core(
    const __nv_bfloat16* __restrict__ Ah_g, const __nv_bfloat16* __restrict__ Al_g,
    const __nv_bfloat16* __restrict__ Bh_g, const __nv_bfloat16* __restrict__ Bl_g,
    __nv_bfloat16* __restrict__ C, int cstride, int bm, int bn, uint32_t* smem) {
    uint32_t* sAh = smem;
    uint32_t* sAl = smem + 128 * PITCH;
    uint32_t* sBh = smem + 2 * 128 * PITCH;
    uint32_t* sBl = smem + 3 * 128 * PITCH;

    int tid = threadIdx.x;
    int lane = tid & 31, wid = tid >> 5;
    int g = lane >> 2, tig = lane & 3;
    int wm = wid & 1, wn = wid >> 1;

    uint32_t sAh_a = (uint32_t)__cvta_generic_to_shared(sAh);
    uint32_t sAl_a = (uint32_t)__cvta_generic_to_shared(sAl);
    uint32_t sBh_a = (uint32_t)__cvta_generic_to_shared(sBh);
    uint32_t sBl_a = (uint32_t)__cvta_generic_to_shared(sBl);

    int lane15 = lane & 15;
    int khalf = lane >> 4;
    uint32_t A_loff = (uint32_t)((wm * 64 + lane15) * PITCH) * 4u + (uint32_t)khalf * 16u;
    int bnrow = wn * 32 + (lane >> 4) * 8 + (lane & 7);
    uint32_t B_loff = (uint32_t)(bnrow * PITCH) * 4u + (uint32_t)((lane >> 3) & 1) * 16u;

    float acc[4][4][4];
#pragma unroll
    for (int mt = 0; mt < 4; mt++)
#pragma unroll
        for (int nt = 0; nt < 4; nt++)
#pragma unroll
            for (int q = 0; q < 4; q++) acc[mt][nt][q] = 0.f;

    for (int k0 = 0; k0 < DD; k0 += KC) {
#pragma unroll
        for (int i = 0; i < 4; i++) {
            int sl = tid + i * 256;
            int row = sl >> 3;
            int s = sl & 7;
            uint32_t so = (uint32_t)(row * PITCH + s * 4) * 4u;
            size_t ga = (size_t)(bm + row) * DD + k0 + s * 8;
            size_t gb = (size_t)(bn + row) * DD + k0 + s * 8;
            cp16(sAh_a + so, Ah_g + ga);
            cp16(sAl_a + so, Al_g + ga);
            cp16(sBh_a + so, Bh_g + gb);
            cp16(sBl_a + so, Bl_g + gb);
        }
        asm volatile("cp.async.commit_group;");
        asm volatile("cp.async.wait_group 0;");
        __syncthreads();

#pragma unroll
        for (int ks = 0; ks < 4; ks++) {
            uint32_t koff = (uint32_t)ks * 32u;
            uint32_t Bh[4][2], Bl[4][2];
#pragma unroll
            for (int ntp = 0; ntp < 2; ntp++) {
                uint32_t r[4];
                uint32_t off = B_loff + (uint32_t)(ntp * 16 * PITCH) * 4u + koff;
                ldsm4(r, sBh_a + off);
                Bh[2 * ntp][0] = r[0]; Bh[2 * ntp][1] = r[1];
                Bh[2 * ntp + 1][0] = r[2]; Bh[2 * ntp + 1][1] = r[3];
                ldsm4(r, sBl_a + off);
                Bl[2 * ntp][0] = r[0]; Bl[2 * ntp][1] = r[1];
                Bl[2 * ntp + 1][0] = r[2]; Bl[2 * ntp + 1][1] = r[3];
            }
#pragma unroll
            for (int mt = 0; mt < 4; mt++) {
                uint32_t off = A_loff + (uint32_t)(mt * 16 * PITCH) * 4u + koff;
                uint32_t Ah[4], Al[4];
                ldsm4(Ah, sAh_a + off);
                ldsm4(Al, sAl_a + off);
#pragma unroll
                for (int nt = 0; nt < 4; nt++) {
                    mma_bf16(acc[mt][nt], Ah, Bh[nt]);
                    mma_bf16(acc[mt][nt], Al, Bh[nt]);
                    mma_bf16(acc[mt][nt], Ah, Bl[nt]);
                }
            }
        }
        __syncthreads();
    }

    // bf16 output (halves h traffic for the agg gathers)
#pragma unroll
    for (int mt = 0; mt < 4; mt++) {
        int row = bm + wm * 64 + mt * 16 + g;
#pragma unroll
        for (int nt = 0; nt < 4; nt++) {
            int col = bn + wn * 32 + nt * 8 + tig * 2;
            *reinterpret_cast<uint32_t*>(&C[(size_t)row * cstride + col]) =
                packbf2(acc[mt][nt][0], acc[mt][nt][1]);
            *reinterpret_cast<uint32_t*>(&C[(size_t)(row + 8) * cstride + col]) =
                packbf2(acc[mt][nt][2], acc[mt][nt][3]);
        }
    }
}

// layer-0: C [NPAD][768] bf16
__global__ void __launch_bounds__(256, 2) gemm_mma2(
    const __nv_bfloat16* __restrict__ Ah_g, const __nv_bfloat16* __restrict__ Al_g,
    const __nv_bfloat16* __restrict__ Bh_g, const __nv_bfloat16* __restrict__ Bl_g,
    __nv_bfloat16* __restrict__ C, int cstride) {
    extern __shared__ uint32_t smem[];
    gemm_core(Ah_g, Al_g, Bh_g, Bl_g, C, cstride, blockIdx.x * 128, blockIdx.y * 128, smem);
}

// batched over branches: z = branch; weight index = wbase + z (l-major layout)
__global__ void __launch_bounds__(256, 2) gemm_mma3(
    const __nv_bfloat16* __restrict__ Ah_base, const __nv_bfloat16* __restrict__ Al_base,
    const __nv_bfloat16* __restrict__ Wh_base, const __nv_bfloat16* __restrict__ Wl_base,
    __nv_bfloat16* __restrict__ C_base, int wbase) {
    extern __shared__ uint32_t smem[];
    int z = blockIdx.z;
    gemm_core(Ah_base + (size_t)z * NPAD * DD, Al_base + (size_t)z * NPAD * DD,
              Wh_base + (size_t)(wbase + z) * DD * DD, Wl_base + (size_t)(wbase + z) * DD * DD,
              C_base + (size_t)z * NPAD * DD, DD, blockIdx.x * 128, blockIdx.y * 128, smem);
}

// ---------------- aggregation (bf16 h gathers; 1 node/block, 64 threads) --------
__device__ __forceinline__ float4 ld_bf4(const __nv_bfloat16* __restrict__ h, size_t off) {
    uint2 p = *reinterpret_cast<const uint2*>(h + off);
    __nv_bfloat162 b0 = *reinterpret_cast<__nv_bfloat162*>(&p.x);
    __nv_bfloat162 b1 = *reinterpret_cast<__nv_bfloat162*>(&p.y);
    float2 f0 = __bfloat1622float2(b0);
    float2 f1 = __bfloat1622float2(b1);
    return make_float4(f0.x, f0.y, f1.x, f1.y);
}

__global__ void __launch_bounds__(64) agg_kernel(const __nv_bfloat16* __restrict__ h, int hstride,
                           const int* __restrict__ src,
                           const float* __restrict__ nrm, const int* __restrict__ start,
                           const float* __restrict__ dinv, const float* __restrict__ bias,
                           float* __restrict__ out,
                           __nv_bfloat16* __restrict__ xh, __nv_bfloat16* __restrict__ xl,
                           int pack, int wf32) {
    int i = blockIdx.x;
    int t = threadIdx.x;
    int s = start[i];
    int e = start[i + 1];
    float4 a0 = make_float4(0.f, 0.f, 0.f, 0.f);
    float4 a1 = make_float4(0.f, 0.f, 0.f, 0.f);
    float4 a2 = make_float4(0.f, 0.f, 0.f, 0.f);
    float4 a3 = make_float4(0.f, 0.f, 0.f, 0.f);
    int k = s;
    for (; k + 7 < e; k += 8) {
        int r0 = src[k], r1 = src[k + 1], r2 = src[k + 2], r3 = src[k + 3];
        int r4 = src[k + 4], r5 = src[k + 5], r6 = src[k + 6], r7 = src[k + 7];
        float w0 = nrm[k], w1 = nrm[k + 1], w2 = nrm[k + 2], w3 = nrm[k + 3];
        float w4 = nrm[k + 4], w5 = nrm[k + 5], w6 = nrm[k + 6], w7 = nrm[k + 7];
        float4 v0 = ld_bf4(h, (size_t)r0 * hstride + t * 4);
        float4 v1 = ld_bf4(h, (size_t)r1 * hstride + t * 4);
        float4 v2 = ld_bf4(h, (size_t)r2 * hstride + t * 4);
        float4 v3 = ld_bf4(h, (size_t)r3 * hstride + t * 4);
        float4 v4 = ld_bf4(h, (size_t)r4 * hstride + t * 4);
        float4 v5 = ld_bf4(h, (size_t)r5 * hstride + t * 4);
        float4 v6 = ld_bf4(h, (size_t)r6 * hstride + t * 4);
        float4 v7 = ld_bf4(h, (size_t)r7 * hstride + t * 4);
        a0.x += w0 * v0.x; a0.y += w0 * v0.y; a0.z += w0 * v0.z; a0.w += w0 * v0.w;
        a1.x += w1 * v1.x; a1.y += w1 * v1.y; a1.z += w1 * v1.z; a1.w += w1 * v1.w;
        a2.x += w2 * v2.x; a2.y += w2 * v2.y; a2.z += w2 * v2.z; a2.w += w2 * v2.w;
        a3.x += w3 * v3.x; a3.y += w3 * v3.y; a3.z += w3 * v3.z; a3.w += w3 * v3.w;
        a0.x += w4 * v4.x; a0.y += w4 * v4.y; a0.z += w4 * v4.z; a0.w += w4 * v4.w;
        a1.x += w5 * v5.x; a1.y += w5 * v5.y; a1.z += w5 * v5.z; a1.w += w5 * v5.w;
        a2.x += w6 * v6.x; a2.y += w6 * v6.y; a2.z += w6 * v6.z; a2.w += w6 * v6.w;
        a3.x += w7 * v7.x; a3.y += w7 * v7.y; a3.z += w7 * v7.z; a3.w += w7 * v7.w;
    }
    for (; k < e; k++) {
        int r = src[k];
        float w = nrm[k];
        float4 v = ld_bf4(h, (size_t)r * hstride + t * 4);
        a0.x += w * v.x; a0.y += w * v.y; a0.z += w * v.z; a0.w += w * v.w;
    }
    float di = dinv[i];
    float sn = di * di;
    float4 hv = ld_bf4(h, (size_t)i * hstride + t * 4);
    float4 bv = *(const float4*)&bias[t * 4];
    float4 acc;
    acc.x = a0.x + a1.x + a2.x + a3.x + sn * hv.x + bv.x;
    acc.y = a0.y + a1.y + a2.y + a3.y + sn * hv.y + bv.y;
    acc.z = a0.z + a1.z + a2.z + a3.z + sn * hv.z + bv.z;
    acc.w = a0.w + a1.w + a2.w + a3.w + sn * hv.w + bv.w;
    if (wf32) *(float4*)&out[(size_t)i * DD + t * 4] = acc;
    if (pack) {
        float r0 = fmaxf(acc.x, 0.f), r1 = fmaxf(acc.y, 0.f);
        float r2 = fmaxf(acc.z, 0.f), r3 = fmaxf(acc.w, 0.f);
        uint32_t lo0, lo1;
        uint32_t hi0 = packsplit(r0, r1, lo0);
        uint32_t hi1 = packsplit(r2, r3, lo1);
        uint2 hp, lp;
        hp.x = hi0; hp.y = hi1;
        lp.x = lo0; lp.y = lo1;
        reinterpret_cast<uint2*>(xh)[(size_t)i * 64 + t] = hp;
        reinterpret_cast<uint2*>(xl)[(size_t)i * 64 + t] = lp;
    }
}

// ---------------- meta-path attention ----------------
__global__ void attn_kernel(const float* __restrict__ b0, const float* __restrict__ b1,
                            const float* __restrict__ b2, const float* __restrict__ watt,
                            float* __restrict__ out) {
    int i = blockIdx.x;
    int t = threadIdx.x;
    size_t off = (size_t)i * DD + t;
    float x0v = fmaxf(b0[off], 0.f);
    float x1v = fmaxf(b1[off], 0.f);
    float x2v = fmaxf(b2[off], 0.f);
    float w = watt[t];
    float s0 = x0v * w, s1 = x1v * w, s2 = x2v * w;
#pragma unroll
    for (int o = 16; o; o >>= 1) {
        s0 += __shfl_xor_sync(0xffffffffu, s0, o);
        s1 += __shfl_xor_sync(0xffffffffu, s1, o);
        s2 += __shfl_xor_sync(0xffffffffu, s2, o);
    }
    __shared__ float sm[3][8];
    __shared__ float sw[3];
    int wid = t >> 5, ln = t & 31;
    if (ln == 0) { sm[0][wid] = s0; sm[1][wid] = s1; sm[2][wid] = s2; }
    __syncthreads();
    if (t == 0) {
        float t0 = 0.f, t1 = 0.f, t2 = 0.f;
#pragma unroll
        for (int kk = 0; kk < 8; kk++) { t0 += sm[0][kk]; t1 += sm[1][kk]; t2 += sm[2][kk]; }
        float mx = fmaxf(t0, fmaxf(t1, t2));
        float e0 = expf(t0 - mx), e1 = expf(t1 - mx), e2 = expf(t2 - mx);
        float inv = 1.f / (e0 + e1 + e2);
        sw[0] = e0 * inv; sw[1] = e1 * inv; sw[2] = e2 * inv;
    }
    __syncthreads();
    out[off] = sw[0] * x0v + sw[1] * x1v + sw[2] * x2v;
}

// ---------------- launcher (serial schedule, layer-major batched GEMMs) ----------------
extern "C" void kernel_launch(void* const* d_in, const int* in_sizes, int n_in,
                              void* d_out, int out_size) {
    const float* init = (const float*)d_in[0];
    const int*   ei[3] = {(const int*)d_in[1], (const int*)d_in[2], (const int*)d_in[3]};
    const float* ea[3] = {(const float*)d_in[4], (const float*)d_in[5], (const float*)d_in[6]};
    const float* pW1 = (const float*)d_in[7];
    const float* pb1 = (const float*)d_in[8];
    const float* pW2 = (const float*)d_in[9];
    const float* pb2 = (const float*)d_in[10];
    const float* Wb[3] = {(const float*)d_in[11], (const float*)d_in[13], (const float*)d_in[15]};
    const float* bb[3] = {(const float*)d_in[12], (const float*)d_in[14], (const float*)d_in[16]};
    const float* watt = (const float*)d_in[17];
    float* out = (float*)d_out;

    float *colemb, *deg, *dinv, *nrm, *rcnt;
    float *br[3];
    int *hist, *cur, *start, *src, *bsum, *bbase;
    __nv_bfloat16 *h0, *hb, *x0h, *x0l, *xhb, *xlb, *Wh, *Wl, *mask, *colTh, *colTl;
    cudaGetSymbolAddress((void**)&colemb, g_colemb);
    cudaGetSymbolAddress((void**)&h0,     g_h0);
    cudaGetSymbolAddress((void**)&hb,     g_hb);
    cudaGetSymbolAddress((void**)&br[0],  g_br0);
    cudaGetSymbolAddress((void**)&br[1],  g_br1);
    cudaGetSymbolAddress((void**)&br[2],  g_br2);
    cudaGetSymbolAddress((void**)&deg,    g_deg);
    cudaGetSymbolAddress((void**)&dinv,   g_dinv);
    cudaGetSymbolAddress((void**)&hist,   g_hist);
    cudaGetSymbolAddress((void**)&cur,    g_cur);
    cudaGetSymbolAddress((void**)&start,  g_start);
    cudaGetSymbolAddress((void**)&bsum,   g_bsum);
    cudaGetSymbolAddress((void**)&bbase,  g_bbase);
    cudaGetSymbolAddress((void**)&src,    g_src);
    cudaGetSymbolAddress((void**)&nrm,    g_nrm);
    cudaGetSymbolAddress((void**)&rcnt,   g_rcnt);
    cudaGetSymbolAddress((void**)&mask,   g_mask);
    cudaGetSymbolAddress((void**)&colTh,  g_colTh);
    cudaGetSymbolAddress((void**)&colTl,  g_colTl);
    cudaGetSymbolAddress((void**)&x0h,    g_x0h);
    cudaGetSymbolAddress((void**)&x0l,    g_x0l);
    cudaGetSymbolAddress((void**)&xhb,    g_xhb);
    cudaGetSymbolAddress((void**)&xlb,    g_xlb);
    cudaGetSymbolAddress((void**)&Wh,     g_Wh);
    cudaGetSymbolAddress((void**)&Wl,     g_Wl);

    static int attr_set = 0;
    if (!attr_set) {
        cudaFuncSetAttribute(gemm_mma2, cudaFuncAttributeMaxDynamicSharedMemorySize, 73728);
        cudaFuncSetAttribute(gemm_mma3, cudaFuncAttributeMaxDynamicSharedMemorySize, 73728);
        cudaFuncSetAttribute(x0gemm, cudaFuncAttributeMaxDynamicSharedMemorySize, 2 * XSTG);
        attr_set = 1;
    }

    // ---- front end (x0 path)
    colemb_kernel<<<MCOLS, DD>>>(pW1, pb1, pW2, pb2, colemb);
    maskbuild_kernel<<<NNODES, 256>>>(init, mask, rcnt);
    colembT_kernel<<<dim3(32, 8), dim3(32, 8)>>>(colemb, colTh, colTl);
    x0gemm<<<dim3(314, 2), 256, 2 * XSTG>>>(mask, colTh, colTl, rcnt, x0h, x0l);
    wconv_kernel<<<dim3(8, 8, 9), dim3(32, 8)>>>(Wb[0], Wb[1], Wb[2], Wh, Wl);

    // ---- graph prep (all branches; fast 3-phase scan)
    branch_init<<<dim3(NB, 1, 3), 256>>>(deg, hist);
    edge_count<<<dim3(EB, 1, 3), 256>>>(ei[0], ei[1], ei[2], ea[0], ea[1], ea[2], deg, hist);
    dinv_kernel<<<dim3(NB, 1, 3), 256>>>(deg, dinv);
    scanP1<<<3 * NB, 256>>>(hist, bsum);
    scanP2<<<1, 256>>>(bsum, bbase, start);
    scanP3<<<3 * NB, 256>>>(hist, bbase, start, cur);
    scatter_kernel<<<dim3(EB, 1, 3), 256>>>(ei[0], ei[1], ei[2], ea[0], ea[1], ea[2],
                                            dinv, cur, src, nrm);

    // ---- layer-0 GEMM batched across branches (Wh l-major: w'=0,1,2 -> [768][256])
    gemm_mma2<<<dim3(157, 6), 256, 73728>>>(x0h, x0l, Wh, Wl, h0, 768);

    // ---- layer-major schedule: per-layer aggs, then one batched GEMM for all branches
    for (int b = 0; b < 3; b++)
        agg_kernel<<<NNODES, 64>>>(h0 + b * DD, 768, src + b * NEDGE, nrm + b * NEDGE,
                                   start + b * (NNODES + 1), dinv + b * NNODES, bb[b],
                                   br[b], xhb + (size_t)b * NPAD * DD,
                                   xlb + (size_t)b * NPAD * DD, 1, 0);
    gemm_mma3<<<dim3(157, 2, 3), 256, 73728>>>(xhb, xlb, Wh, Wl, hb, 3);
    for (int b = 0; b < 3; b++)
        agg_kernel<<<NNODES, 64>>>(hb + (size_t)b * NPAD * DD, DD, src + b * NEDGE,
                                   nrm + b * NEDGE, start + b * (NNODES + 1),
                                   dinv + b * NNODES, bb[b] + DD,
                                   br[b], xhb + (size_t)b * NPAD * DD,
                                   xlb + (size_t)b * NPAD * DD, 1, 0);
    gemm_mma3<<<dim3(157, 2, 3), 256, 73728>>>(xhb, xlb, Wh, Wl, hb, 6);
    for (int b = 0; b < 3; b++)
        agg_kernel<<<NNODES, 64>>>(hb + (size_t)b * NPAD * DD, DD, src + b * NEDGE,
                                   nrm + b * NEDGE, start + b * (NNODES + 1),
                                   dinv + b * NNODES, bb[b] + 2 * DD,
                                   br[b], xhb, xlb, 0, 1);

    attn_kernel<<<NNODES, 256>>>(br[0], br[1], br[2], watt, out);
}

// round 17
// speedup vs baseline: 2.0370x; 1.0011x over previous
#include <cuda_runtime.h>
#include <cuda_bf16.h>
#include <cuda_fp16.h>
#include <cstdint>

#define NNODES 20000
#define NPAD   20096            // 157 * 128
#define MCOLS  1024
#define NEDGE  640000
#define DD     256
#define NB     79               // ceil(20000/256)
#define EB     2500             // ceil(640000/256)

// ---------------- scratch (__device__ globals; zero-initialized bss) ----------------
__device__ float g_colemb[MCOLS * DD];
__device__ __half g_h0[NPAD * 768];             // batched layer-0 output (fp16)
__device__ __half g_hb[3 * NPAD * DD];          // per-branch GEMM outputs (fp16)
__device__ float g_br0[NPAD * DD];
__device__ float g_br1[NPAD * DD];
__device__ float g_br2[NPAD * DD];
__device__ float g_deg[3 * NNODES];
__device__ float g_dinv[3 * NNODES];
__device__ int   g_hist[3 * NNODES];
__device__ int   g_cur[3 * NNODES];
__device__ int   g_start[3 * (NNODES + 1)];
__device__ int   g_bsum[3 * NB];
__device__ int   g_bbase[3 * NB];
__device__ int   g_src[3 * NEDGE];
__device__ float g_nrm[3 * NEDGE];
// x0-as-GEMM operands
__device__ __nv_bfloat16 g_mask[NPAD * MCOLS];  // bf16 0/1 mask (padded rows stay 0)
__device__ float g_rcnt[NPAD];                  // 1/max(cnt,1) (padded rows 0)
__device__ __nv_bfloat16 g_colTh[DD * MCOLS];
__device__ __nv_bfloat16 g_colTl[DD * MCOLS];
// packed bf16 hi/lo planes
__device__ __nv_bfloat16 g_x0h[NPAD * DD];
__device__ __nv_bfloat16 g_x0l[NPAD * DD];
__device__ __nv_bfloat16 g_xhb[3 * NPAD * DD];  // per-branch
__device__ __nv_bfloat16 g_xlb[3 * NPAD * DD];
// transposed bf16 hi/lo weights, l-major: index w' = l*3+b, each [n=256][k=256]
__device__ __nv_bfloat16 g_Wh[9 * DD * DD];
__device__ __nv_bfloat16 g_Wl[9 * DD * DD];

// ================= shared MMA helpers =================
#define KC 64
#define PITCH 36      // uint32 words per smem row (32 kpairs + 4 pad)
// x0gemm stage: A(64 rows) + Bh(128) + Bl(128) = 320 rows
#define XSTG (320 * PITCH * 4)

__device__ __forceinline__ void mma_bf16(float* c, const uint32_t* a, const uint32_t* b) {
    asm volatile(
        "mma.sync.aligned.m16n8k16.row.col.f32.bf16.bf16.f32 "
        "{%0,%1,%2,%3}, {%4,%5,%6,%7}, {%8,%9}, {%0,%1,%2,%3};"
        : "+f"(c[0]), "+f"(c[1]), "+f"(c[2]), "+f"(c[3])
        : "r"(a[0]), "r"(a[1]), "r"(a[2]), "r"(a[3]), "r"(b[0]), "r"(b[1]));
}
__device__ __forceinline__ void ldsm4(uint32_t* r, uint32_t addr) {
    asm volatile("ldmatrix.sync.aligned.m8n8.x4.shared.b16 {%0,%1,%2,%3}, [%4];"
        : "=r"(r[0]), "=r"(r[1]), "=r"(r[2]), "=r"(r[3]) : "r"(addr));
}
__device__ __forceinline__ void cp16(uint32_t smem_dst, const void* gsrc) {
    asm volatile("cp.async.cg.shared.global [%0], [%1], 16;" :: "r"(smem_dst), "l"(gsrc));
}
__device__ __forceinline__ uint32_t packsplit(float v0, float v1, uint32_t& lo) {
    __nv_bfloat162 h, l;
    h.x = __float2bfloat16(v0); h.y = __float2bfloat16(v1);
    l.x = __float2bfloat16(v0 - __bfloat162float(h.x));
    l.y = __float2bfloat16(v1 - __bfloat162float(h.y));
    lo = *reinterpret_cast<uint32_t*>(&l);
    return *reinterpret_cast<uint32_t*>(&h);
}
__device__ __forceinline__ uint32_t packbf2(float v0, float v1) {
    __nv_bfloat162 h;
    h.x = __float2bfloat16(v0); h.y = __float2bfloat16(v1);
    return *reinterpret_cast<uint32_t*>(&h);
}
__device__ __forceinline__ uint32_t packh2(float v0, float v1) {
    __half2 h = __floats2half2_rn(v0, v1);
    return *reinterpret_cast<uint32_t*>(&h);
}

// ---------------- front-end kernels ----------------
__global__ void colemb_kernel(const float* __restrict__ pW1, const float* __restrict__ pb1,
                              const float* __restrict__ pW2, const float* __restrict__ pb2,
                              float* __restrict__ colemb) {
    int j = blockIdx.x;
    int d = threadIdx.x;
    float jf = (float)j;
    float acc = pb2[d];
#pragma unroll
    for (int k = 0; k < 16; k++) {
        float hk = fmaxf(jf * pW1[k] + pb1[k], 0.f);
        acc += hk * pW2[k * DD + d];
    }
    colemb[j * DD + d] = acc;
}

__global__ void maskbuild_kernel(const float* __restrict__ init,
                                 __nv_bfloat16* __restrict__ mask, float* __restrict__ rcnt) {
    int i = blockIdx.x;
    int t = threadIdx.x;  // 256, 4 cols each
    __shared__ int scnt;
    if (t == 0) scnt = 0;
    __syncthreads();
    float4 v = *(const float4*)&init[(size_t)i * MCOLS + t * 4];
    float m0 = (v.x != 0.f) ? 1.f : 0.f;
    float m1 = (v.y != 0.f) ? 1.f : 0.f;
    float m2 = (v.z != 0.f) ? 1.f : 0.f;
    float m3 = (v.w != 0.f) ? 1.f : 0.f;
    int c = (int)(m0 + m1 + m2 + m3);
#pragma unroll
    for (int o = 16; o; o >>= 1) c += __shfl_xor_sync(0xffffffffu, c, o);
    if ((t & 31) == 0) atomicAdd(&scnt, c);
    uint2 pk;
    pk.x = packbf2(m0, m1);
    pk.y = packbf2(m2, m3);
    *reinterpret_cast<uint2*>(&mask[(size_t)i * MCOLS + t * 4]) = pk;
    __syncthreads();
    if (t == 0) rcnt[i] = 1.f / (float)max(scnt, 1);
}

__global__ void colembT_kernel(const float* __restrict__ colemb,
                               __nv_bfloat16* __restrict__ Th, __nv_bfloat16* __restrict__ Tl) {
    __shared__ float tile[32][33];
    int j0 = blockIdx.x * 32, d0 = blockIdx.y * 32;
    int tx = threadIdx.x, ty = threadIdx.y;  // 32 x 8
#pragma unroll
    for (int i = 0; i < 32; i += 8)
        tile[ty + i][tx] = colemb[(size_t)(j0 + ty + i) * DD + d0 + tx];
    __syncthreads();
#pragma unroll
    for (int i = 0; i < 32; i += 8) {
        float v = tile[tx][ty + i];
        __nv_bfloat16 h = __float2bfloat16(v);
        size_t o = (size_t)(d0 + ty + i) * MCOLS + j0 + tx;
        Th[o] = h;
        Tl[o] = __float2bfloat16(v - __bfloat162float(h));
    }
}

__global__ void wconv_kernel(const float* __restrict__ W0, const float* __restrict__ W1,
                             const float* __restrict__ W2,
                             __nv_bfloat16* __restrict__ Ht, __nv_bfloat16* __restrict__ Lt) {
    __shared__ float tile[32][33];
    int z = blockIdx.z;           // b*3 + l
    int b = z / 3, l = z % 3;
    const float* W = (b == 0) ? W0 : (b == 1) ? W1 : W2;
    W += (size_t)l * DD * DD;
    size_t dbase = (size_t)(l * 3 + b) * DD * DD;
    int n0 = blockIdx.x * 32, k0 = blockIdx.y * 32;
    int tx = threadIdx.x, ty = threadIdx.y;  // 32 x 8
#pragma unroll
    for (int i = 0; i < 32; i += 8)
        tile[ty + i][tx] = W[(size_t)(k0 + ty + i) * DD + n0 + tx];
    __syncthreads();
#pragma unroll
    for (int i = 0; i < 32; i += 8) {
        float v = tile[tx][ty + i];
        __nv_bfloat16 h = __float2bfloat16(v);
        size_t o = dbase + (size_t)(n0 + ty + i) * DD + k0 + tx;
        Ht[o] = h;
        Lt[o] = __float2bfloat16(v - __bfloat162float(h));
    }
}

// ---------------- graph prep (grid.z = branch) ----------------
__global__ void branch_init(float* __restrict__ deg, int* __restrict__ hist) {
    int i = blockIdx.x * blockDim.x + threadIdx.x;
    int b = blockIdx.z;
    if (i < NNODES) { deg[b * NNODES + i] = 1.0f; hist[b * NNODES + i] = 0; }
}

__global__ void edge_count(const int* __restrict__ ei0, const int* __restrict__ ei1,
                           const int* __restrict__ ei2,
                           const float* __restrict__ ea0, const float* __restrict__ ea1,
                           const float* __restrict__ ea2,
                           float* __restrict__ deg, int* __restrict__ hist) {
    int e = blockIdx.x * blockDim.x + threadIdx.x;
    int b = blockIdx.z;
    const int* ei = (b == 0) ? ei0 : (b == 1) ? ei1 : ei2;
    const float* ea = (b == 0) ? ea0 : (b == 1) ? ea1 : ea2;
    if (e < NEDGE) {
        int c = ei[NEDGE + e];
        atomicAdd(&deg[b * NNODES + c], ea[e]);
        atomicAdd(&hist[b * NNODES + c], 1);
    }
}

__global__ void dinv_kernel(const float* __restrict__ deg, float* __restrict__ dinv) {
    int i = blockIdx.x * blockDim.x + threadIdx.x;
    int b = blockIdx.z;
    if (i < NNODES) dinv[b * NNODES + i] = rsqrtf(deg[b * NNODES + i]);
}

// ---- 3-phase exclusive scan over hist (per branch) ----
__global__ void scanP1(const int* __restrict__ hist, int* __restrict__ bsum) {
    int bid = blockIdx.x;        // 3*NB
    int b = bid / NB, blk = bid % NB;
    int t = threadIdx.x;         // 256
    int gi = blk * 256 + t;
    int v = (gi < NNODES) ? hist[b * NNODES + gi] : 0;
#pragma unroll
    for (int o = 16; o; o >>= 1) v += __shfl_xor_sync(0xffffffffu, v, o);
    __shared__ int ws[8];
    if ((t & 31) == 0) ws[t >> 5] = v;
    __syncthreads();
    if (t == 0) {
        int s = 0;
#pragma unroll
        for (int w = 0; w < 8; w++) s += ws[w];
        bsum[b * NB + blk] = s;
    }
}
__global__ void scanP2(const int* __restrict__ bsum, int* __restrict__ bbase,
                       int* __restrict__ start) {
    int t = threadIdx.x;
    if (t < 3) {
        int s = 0;
        for (int i = 0; i < NB; i++) {
            bbase[t * NB + i] = s;
            s += bsum[t * NB + i];
        }
        start[t * (NNODES + 1) + NNODES] = s;
    }
}
__global__ void scanP3(const int* __restrict__ hist, const int* __restrict__ bbase,
                       int* __restrict__ start, int* __restrict__ cur) {
    int bid = blockIdx.x;
    int b = bid / NB, blk = bid % NB;
    int t = threadIdx.x;
    int lane = t & 31, w = t >> 5;
    int gi = blk * 256 + t;
    int v = (gi < NNODES) ? hist[b * NNODES + gi] : 0;
    int s = v;
#pragma unroll
    for (int o = 1; o < 32; o <<= 1) {
        int x = __shfl_up_sync(0xffffffffu, s, o);
        if (lane >= o) s += x;
    }
    __shared__ int ws[8];
    if (lane == 31) ws[w] = s;
    __syncthreads();
    if (t == 0) {
        int acc = 0;
#pragma unroll
        for (int i = 0; i < 8; i++) { int x = ws[i]; ws[i] = acc; acc += x; }
    }
    __syncthreads();
    int excl = s - v + ws[w] + bbase[b * NB + blk];
    if (gi < NNODES) {
        start[b * (NNODES + 1) + gi] = excl;
        cur[b * NNODES + gi] = excl;
    }
}

__global__ void scatter_kernel(const int* __restrict__ ei0, const int* __restrict__ ei1,
                               const int* __restrict__ ei2,
                               const float* __restrict__ ea0, const float* __restrict__ ea1,
                               const float* __restrict__ ea2,
                               const float* __restrict__ dinv, int* __restrict__ cur,
                               int* __restrict__ src, float* __restrict__ nrm) {
    int e = blockIdx.x * blockDim.x + threadIdx.x;
    int b = blockIdx.z;
    const int* ei = (b == 0) ? ei0 : (b == 1) ? ei1 : ei2;
    const float* ea = (b == 0) ? ea0 : (b == 1) ? ea1 : ea2;
    if (e < NEDGE) {
        int r = ei[e];
        int c = ei[NEDGE + e];
        float n = dinv[b * NNODES + r] * ea[e] * dinv[b * NNODES + c];
        int p = atomicAdd(&cur[b * NNODES + c], 1);
        src[b * NEDGE + p] = r;
        nrm[b * NEDGE + p] = n;
    }
}

// ================= x0 GEMM (M-tile 64, double-buffered) ==========
__global__ void __launch_bounds__(256, 2) x0gemm(
    const __nv_bfloat16* __restrict__ Am, const __nv_bfloat16* __restrict__ Bh_g,
    const __nv_bfloat16* __restrict__ Bl_g, const float* __restrict__ rcnt,
    __nv_bfloat16* __restrict__ xh, __nv_bfloat16* __restrict__ xl) {
    extern __shared__ uint32_t smem[];

    int tid = threadIdx.x;
    int lane = tid & 31, wid = tid >> 5;
    int g = lane >> 2, tig = lane & 3;
    int wm = wid & 1, wn = wid >> 1;
    int bm = blockIdx.x * 64;
    int bn = blockIdx.y * 128;

    uint32_t s_base = (uint32_t)__cvta_generic_to_shared(smem);
    const uint32_t OFF_BH = 64 * PITCH * 4;
    const uint32_t OFF_BL = (64 + 128) * PITCH * 4;

    int lane15 = lane & 15;
    int khalf = lane >> 4;
    uint32_t A_loff = (uint32_t)((wm * 32 + lane15) * PITCH) * 4u + (uint32_t)khalf * 16u;
    int bnrow = wn * 32 + (lane >> 4) * 8 + (lane & 7);
    uint32_t B_loff = (uint32_t)(bnrow * PITCH) * 4u + (uint32_t)((lane >> 3) & 1) * 16u;

    float acc[2][4][4];
#pragma unroll
    for (int mt = 0; mt < 2; mt++)
#pragma unroll
        for (int nt = 0; nt < 4; nt++)
#pragma unroll
            for (int q = 0; q < 4; q++) acc[mt][nt][q] = 0.f;

    const int NK = MCOLS / KC;   // 16

    auto load_chunk = [&](int kc, int stg) {
        uint32_t sb = s_base + (uint32_t)stg * XSTG;
        int k0 = kc * KC;
#pragma unroll
        for (int i = 0; i < 2; i++) {
            int sl = tid + i * 256;
            int row = sl >> 3;
            int s = sl & 7;
            uint32_t so = (uint32_t)(row * PITCH + s * 4) * 4u;
            cp16(sb + so, Am + (size_t)(bm + row) * MCOLS + k0 + s * 8);
        }
#pragma unroll
        for (int i = 0; i < 4; i++) {
            int sl = tid + i * 256;
            int row = sl >> 3;
            int s = sl & 7;
            uint32_t so = (uint32_t)(row * PITCH + s * 4) * 4u;
            size_t gb = (size_t)(bn + row) * MCOLS + k0 + s * 8;
            cp16(sb + OFF_BH + so, Bh_g + gb);
            cp16(sb + OFF_BL + so, Bl_g + gb);
        }
        asm volatile("cp.async.commit_group;");
    };

    load_chunk(0, 0);

    for (int kc = 0; kc < NK; kc++) {
        if (kc + 1 < NK) {
            load_chunk(kc + 1, (kc + 1) & 1);
            asm volatile("cp.async.wait_group 1;");
        } else {
            asm volatile("cp.async.wait_group 0;");
        }
        __syncthreads();

        uint32_t sb = s_base + (uint32_t)(kc & 1) * XSTG;
        uint32_t sA_a = sb;
        uint32_t sBh_a = sb + OFF_BH;
        uint32_t sBl_a = sb + OFF_BL;

#pragma unroll
        for (int ks = 0; ks < 4; ks++) {
            uint32_t koff = (uint32_t)ks * 32u;
            uint32_t Bh[4][2], Bl[4][2];
#pragma unroll
            for (int ntp = 0; ntp < 2; ntp++) {
                uint32_t r[4];
                uint32_t off = B_loff + (uint32_t)(ntp * 16 * PITCH) * 4u + koff;
                ldsm4(r, sBh_a + off);
                Bh[2 * ntp][0] = r[0]; Bh[2 * ntp][1] = r[1];
                Bh[2 * ntp + 1][0] = r[2]; Bh[2 * ntp + 1][1] = r[3];
                ldsm4(r, sBl_a + off);
                Bl[2 * ntp][0] = r[0]; Bl[2 * ntp][1] = r[1];
                Bl[2 * ntp + 1][0] = r[2]; Bl[2 * ntp + 1][1] = r[3];
            }
#pragma unroll
            for (int mt = 0; mt < 2; mt++) {
                uint32_t off = A_loff + (uint32_t)(mt * 16 * PITCH) * 4u + koff;
                uint32_t Af[4];
                ldsm4(Af, sA_a + off);
#pragma unroll
                for (int nt = 0; nt < 4; nt++) {
                    mma_bf16(acc[mt][nt], Af, Bh[nt]);
                    mma_bf16(acc[mt][nt], Af, Bl[nt]);
                }
            }
        }
        __syncthreads();
    }

#pragma unroll
    for (int mt = 0; mt < 2; mt++) {
        int row = bm + wm * 32 + mt * 16 + g;
        float rc0 = rcnt[row];
        float rc1 = rcnt[row + 8];
#pragma unroll
        for (int nt = 0; nt < 4; nt++) {
            int col = bn + wn * 32 + nt * 8 + tig * 2;
            uint32_t lo;
            uint32_t hi = packsplit(acc[mt][nt][0] * rc0, acc[mt][nt][1] * rc0, lo);
            *reinterpret_cast<uint32_t*>(&xh[(size_t)row * DD + col]) = hi;
            *reinterpret_cast<uint32_t*>(&xl[(size_t)row * DD + col]) = lo;
            hi = packsplit(acc[mt][nt][2] * rc1, acc[mt][nt][3] * rc1, lo);
            *reinterpret_cast<uint32_t*>(&xh[(size_t)(row + 8) * DD + col]) = hi;
            *reinterpret_cast<uint32_t*>(&xl[(size_t)(row + 8) * DD + col]) = lo;
        }
    }
}

// ================= split-bf16 HMMA GEMM core (fp16 output) =================
__device__ __forceinline__ void gemm_core(
    const __nv_bfloat16* __restrict__ Ah_g, const __nv_bfloat16* __restrict__ Al_g,
    const __nv_bfloat16* __restrict__ Bh_g, const __nv_bfloat16* __restrict__ Bl_g,
    __half* __restrict__ C, int cstride, int bm, int bn, uint32_t* smem) {
    uint32_t* sAh = smem;
    uint32_t* sAl = smem + 128 * PITCH;
    uint32_t* sBh = smem + 2 * 128 * PITCH;
    uint32_t* sBl = smem + 3 * 128 * PITCH;

    int tid = threadIdx.x;
    int lane = tid & 31, wid = tid >> 5;
    int g = lane >> 2, tig = lane & 3;
    int wm = wid & 1, wn = wid >> 1;

    uint32_t sAh_a = (uint32_t)__cvta_generic_to_shared(sAh);
    uint32_t sAl_a = (uint32_t)__cvta_generic_to_shared(sAl);
    uint32_t sBh_a = (uint32_t)__cvta_generic_to_shared(sBh);
    uint32_t sBl_a = (uint32_t)__cvta_generic_to_shared(sBl);

    int lane15 = lane & 15;
    int khalf = lane >> 4;
    uint32_t A_loff = (uint32_t)((wm * 64 + lane15) * PITCH) * 4u + (uint32_t)khalf * 16u;
    int bnrow = wn * 32 + (lane >> 4) * 8 + (lane & 7);
    uint32_t B_loff = (uint32_t)(bnrow * PITCH) * 4u + (uint32_t)((lane >> 3) & 1) * 16u;

    float acc[4][4][4];
#pragma unroll
    for (int mt = 0; mt < 4; mt++)
#pragma unroll
        for (int nt = 0; nt < 4; nt++)
#pragma unroll
            for (int q = 0; q < 4; q++) acc[mt][nt][q] = 0.f;

    for (int k0 = 0; k0 < DD; k0 += KC) {
#pragma unroll
        for (int i = 0; i < 4; i++) {
            int sl = tid + i * 256;
            int row = sl >> 3;
            int s = sl & 7;
            uint32_t so = (uint32_t)(row * PITCH + s * 4) * 4u;
            size_t ga = (size_t)(bm + row) * DD + k0 + s * 8;
            size_t gb = (size_t)(bn + row) * DD + k0 + s * 8;
            cp16(sAh_a + so, Ah_g + ga);
            cp16(sAl_a + so, Al_g + ga);
            cp16(sBh_a + so, Bh_g + gb);
            cp16(sBl_a + so, Bl_g + gb);
        }
        asm volatile("cp.async.commit_group;");
        asm volatile("cp.async.wait_group 0;");
        __syncthreads();

#pragma unroll
        for (int ks = 0; ks < 4; ks++) {
            uint32_t koff = (uint32_t)ks * 32u;
            uint32_t Bh[4][2], Bl[4][2];
#pragma unroll
            for (int ntp = 0; ntp < 2; ntp++) {
                uint32_t r[4];
                uint32_t off = B_loff + (uint32_t)(ntp * 16 * PITCH) * 4u + koff;
                ldsm4(r, sBh_a + off);
                Bh[2 * ntp][0] = r[0]; Bh[2 * ntp][1] = r[1];
                Bh[2 * ntp + 1][0] = r[2]; Bh[2 * ntp + 1][1] = r[3];
                ldsm4(r, sBl_a + off);
                Bl[2 * ntp][0] = r[0]; Bl[2 * ntp][1] = r[1];
                Bl[2 * ntp + 1][0] = r[2]; Bl[2 * ntp + 1][1] = r[3];
            }
#pragma unroll
            for (int mt = 0; mt < 4; mt++) {
                uint32_t off = A_loff + (uint32_t)(mt * 16 * PITCH) * 4u + koff;
                uint32_t Ah[4], Al[4];
                ldsm4(Ah, sAh_a + off);
                ldsm4(Al, sAl_a + off);
#pragma unroll
                for (int nt = 0; nt < 4; nt++) {
                    mma_bf16(acc[mt][nt], Ah, Bh[nt]);
                    mma_bf16(acc[mt][nt], Al, Bh[nt]);
                    mma_bf16(acc[mt][nt], Ah, Bl[nt]);
                }
            }
        }
        __syncthreads();
    }

    // fp16 output (half traffic for agg gathers, 10-bit mantissa precision)
#pragma unroll
    for (int mt = 0; mt < 4; mt++) {
        int row = bm + wm * 64 + mt * 16 + g;
#pragma unroll
        for (int nt = 0; nt < 4; nt++) {
            int col = bn + wn * 32 + nt * 8 + tig * 2;
            *reinterpret_cast<uint32_t*>(&C[(size_t)row * cstride + col]) =
                packh2(acc[mt][nt][0], acc[mt][nt][1]);
            *reinterpret_cast<uint32_t*>(&C[(size_t)(row + 8) * cstride + col]) =
                packh2(acc[mt][nt][2], acc[mt][nt][3]);
        }
    }
}

// layer-0: C [NPAD][768] fp16
__global__ void __launch_bounds__(256, 2) gemm_mma2(
    const __nv_bfloat16* __restrict__ Ah_g, const __nv_bfloat16* __restrict__ Al_g,
    const __nv_bfloat16* __restrict__ Bh_g, const __nv_bfloat16* __restrict__ Bl_g,
    __half* __restrict__ C, int cstride) {
    extern __shared__ uint32_t smem[];
    gemm_core(Ah_g, Al_g, Bh_g, Bl_g, C, cstride, blockIdx.x * 128, blockIdx.y * 128, smem);
}

// batched over branches: z = branch; weight index = wbase + z (l-major layout)
__global__ void __launch_bounds__(256, 2) gemm_mma3(
    const __nv_bfloat16* __restrict__ Ah_base, const __nv_bfloat16* __restrict__ Al_base,
    const __nv_bfloat16* __restrict__ Wh_base, const __nv_bfloat16* __restrict__ Wl_base,
    __half* __restrict__ C_base, int wbase) {
    extern __shared__ uint32_t smem[];
    int z = blockIdx.z;
    gemm_core(Ah_base + (size_t)z * NPAD * DD, Al_base + (size_t)z * NPAD * DD,
              Wh_base + (size_t)(wbase + z) * DD * DD, Wl_base + (size_t)(wbase + z) * DD * DD,
              C_base + (size_t)z * NPAD * DD, DD, blockIdx.x * 128, blockIdx.y * 128, smem);
}

// ---------------- aggregation (fp16 h gathers; 1 node/block, 64 threads) --------
__device__ __forceinline__ float4 ld_hf4(const __half* __restrict__ h, size_t off) {
    uint2 p = *reinterpret_cast<const uint2*>(h + off);
    __half2 b0 = *reinterpret_cast<__half2*>(&p.x);
    __half2 b1 = *reinterpret_cast<__half2*>(&p.y);
    float2 f0 = __half22float2(b0);
    float2 f1 = __half22float2(b1);
    return make_float4(f0.x, f0.y, f1.x, f1.y);
}

__global__ void __launch_bounds__(64) agg_kernel(const __half* __restrict__ h, int hstride,
                           const int* __restrict__ src,
                           const float* __restrict__ nrm, const int* __restrict__ start,
                           const float* __restrict__ dinv, const float* __restrict__ bias,
                           float* __restrict__ out,
                           __nv_bfloat16* __restrict__ xh, __nv_bfloat16* __restrict__ xl,
                           int pack, int wf32) {
    int i = blockIdx.x;
    int t = threadIdx.x;
    int s = start[i];
    int e = start[i + 1];
    float4 a0 = make_float4(0.f, 0.f, 0.f, 0.f);
    float4 a1 = make_float4(0.f, 0.f, 0.f, 0.f);
    float4 a2 = make_float4(0.f, 0.f, 0.f, 0.f);
    float4 a3 = make_float4(0.f, 0.f, 0.f, 0.f);
    int k = s;
    for (; k + 7 < e; k += 8) {
        int r0 = src[k], r1 = src[k + 1], r2 = src[k + 2], r3 = src[k + 3];
        int r4 = src[k + 4], r5 = src[k + 5], r6 = src[k + 6], r7 = src[k + 7];
        float w0 = nrm[k], w1 = nrm[k + 1], w2 = nrm[k + 2], w3 = nrm[k + 3];
        float w4 = nrm[k + 4], w5 = nrm[k + 5], w6 = nrm[k + 6], w7 = nrm[k + 7];
        float4 v0 = ld_hf4(h, (size_t)r0 * hstride + t * 4);
        float4 v1 = ld_hf4(h, (size_t)r1 * hstride + t * 4);
        float4 v2 = ld_hf4(h, (size_t)r2 * hstride + t * 4);
        float4 v3 = ld_hf4(h, (size_t)r3 * hstride + t * 4);
        float4 v4 = ld_hf4(h, (size_t)r4 * hstride + t * 4);
        float4 v5 = ld_hf4(h, (size_t)r5 * hstride + t * 4);
        float4 v6 = ld_hf4(h, (size_t)r6 * hstride + t * 4);
        float4 v7 = ld_hf4(h, (size_t)r7 * hstride + t * 4);
        a0.x += w0 * v0.x; a0.y += w0 * v0.y; a0.z += w0 * v0.z; a0.w += w0 * v0.w;
        a1.x += w1 * v1.x; a1.y += w1 * v1.y; a1.z += w1 * v1.z; a1.w += w1 * v1.w;
        a2.x += w2 * v2.x; a2.y += w2 * v2.y; a2.z += w2 * v2.z; a2.w += w2 * v2.w;
        a3.x += w3 * v3.x; a3.y += w3 * v3.y; a3.z += w3 * v3.z; a3.w += w3 * v3.w;
        a0.x += w4 * v4.x; a0.y += w4 * v4.y; a0.z += w4 * v4.z; a0.w += w4 * v4.w;
        a1.x += w5 * v5.x; a1.y += w5 * v5.y; a1.z += w5 * v5.z; a1.w += w5 * v5.w;
        a2.x += w6 * v6.x; a2.y += w6 * v6.y; a2.z += w6 * v6.z; a2.w += w6 * v6.w;
        a3.x += w7 * v7.x; a3.y += w7 * v7.y; a3.z += w7 * v7.z; a3.w += w7 * v7.w;
    }
    for (; k < e; k++) {
        int r = src[k];
        float w = nrm[k];
        float4 v = ld_hf4(h, (size_t)r * hstride + t * 4);
        a0.x += w * v.x; a0.y += w * v.y; a0.z += w * v.z; a0.w += w * v.w;
    }
    float di = dinv[i];
    float sn = di * di;
    float4 hv = ld_hf4(h, (size_t)i * hstride + t * 4);
    float4 bv = *(const float4*)&bias[t * 4];
    float4 acc;
    acc.x = a0.x + a1.x + a2.x + a3.x + sn * hv.x + bv.x;
    acc.y = a0.y + a1.y + a2.y + a3.y + sn * hv.y + bv.y;
    acc.z = a0.z + a1.z + a2.z + a3.z + sn * hv.z + bv.z;
    acc.w = a0.w + a1.w + a2.w + a3.w + sn * hv.w + bv.w;
    if (wf32) *(float4*)&out[(size_t)i * DD + t * 4] = acc;
    if (pack) {
        float r0 = fmaxf(acc.x, 0.f), r1 = fmaxf(acc.y, 0.f);
        float r2 = fmaxf(acc.z, 0.f), r3 = fmaxf(acc.w, 0.f);
        uint32_t lo0, lo1;
        uint32_t hi0 = packsplit(r0, r1, lo0);
        uint32_t hi1 = packsplit(r2, r3, lo1);
        uint2 hp, lp;
        hp.x = hi0; hp.y = hi1;
        lp.x = lo0; lp.y = lo1;
        reinterpret_cast<uint2*>(xh)[(size_t)i * 64 + t] = hp;
        reinterpret_cast<uint2*>(xl)[(size_t)i * 64 + t] = lp;
    }
}

// ---------------- meta-path attention ----------------
__global__ void attn_kernel(const float* __restrict__ b0, const float* __restrict__ b1,
                            const float* __restrict__ b2, const float* __restrict__ watt,
                            float* __restrict__ out) {
    int i = blockIdx.x;
    int t = threadIdx.x;
    size_t off = (size_t)i * DD + t;
    float x0v = fmaxf(b0[off], 0.f);
    float x1v = fmaxf(b1[off], 0.f);
    float x2v = fmaxf(b2[off], 0.f);
    float w = watt[t];
    float s0 = x0v * w, s1 = x1v * w, s2 = x2v * w;
#pragma unroll
    for (int o = 16; o; o >>= 1) {
        s0 += __shfl_xor_sync(0xffffffffu, s0, o);
        s1 += __shfl_xor_sync(0xffffffffu, s1, o);
        s2 += __shfl_xor_sync(0xffffffffu, s2, o);
    }
    __shared__ float sm[3][8];
    __shared__ float sw[3];
    int wid = t >> 5, ln = t & 31;
    if (ln == 0) { sm[0][wid] = s0; sm[1][wid] = s1; sm[2][wid] = s2; }
    __syncthreads();
    if (t == 0) {
        float t0 = 0.f, t1 = 0.f, t2 = 0.f;
#pragma unroll
        for (int kk = 0; kk < 8; kk++) { t0 += sm[0][kk]; t1 += sm[1][kk]; t2 += sm[2][kk]; }
        float mx = fmaxf(t0, fmaxf(t1, t2));
        float e0 = expf(t0 - mx), e1 = expf(t1 - mx), e2 = expf(t2 - mx);
        float inv = 1.f / (e0 + e1 + e2);
        sw[0] = e0 * inv; sw[1] = e1 * inv; sw[2] = e2 * inv;
    }
    __syncthreads();
    out[off] = sw[0] * x0v + sw[1] * x1v + sw[2] * x2v;
}

// ---------------- launcher (serial schedule, layer-major batched GEMMs) ----------------
extern "C" void kernel_launch(void* const* d_in, const int* in_sizes, int n_in,
                              void* d_out, int out_size) {
    const float* init = (const float*)d_in[0];
    const int*   ei[3] = {(const int*)d_in[1], (const int*)d_in[2], (const int*)d_in[3]};
    const float* ea[3] = {(const float*)d_in[4], (const float*)d_in[5], (const float*)d_in[6]};
    const float* pW1 = (const float*)d_in[7];
    const float* pb1 = (const float*)d_in[8];
    const float* pW2 = (const float*)d_in[9];
    const float* pb2 = (const float*)d_in[10];
    const float* Wb[3] = {(const float*)d_in[11], (const float*)d_in[13], (const float*)d_in[15]};
    const float* bb[3] = {(const float*)d_in[12], (const float*)d_in[14], (const float*)d_in[16]};
    const float* watt = (const float*)d_in[17];
    float* out = (float*)d_out;

    float *colemb, *deg, *dinv, *nrm, *rcnt;
    float *br[3];
    int *hist, *cur, *start, *src, *bsum, *bbase;
    __half *h0, *hb;
    __nv_bfloat16 *x0h, *x0l, *xhb, *xlb, *Wh, *Wl, *mask, *colTh, *colTl;
    cudaGetSymbolAddress((void**)&colemb, g_colemb);
    cudaGetSymbolAddress((void**)&h0,     g_h0);
    cudaGetSymbolAddress((void**)&hb,     g_hb);
    cudaGetSymbolAddress((void**)&br[0],  g_br0);
    cudaGetSymbolAddress((void**)&br[1],  g_br1);
    cudaGetSymbolAddress((void**)&br[2],  g_br2);
    cudaGetSymbolAddress((void**)&deg,    g_deg);
    cudaGetSymbolAddress((void**)&dinv,   g_dinv);
    cudaGetSymbolAddress((void**)&hist,   g_hist);
    cudaGetSymbolAddress((void**)&cur,    g_cur);
    cudaGetSymbolAddress((void**)&start,  g_start);
    cudaGetSymbolAddress((void**)&bsum,   g_bsum);
    cudaGetSymbolAddress((void**)&bbase,  g_bbase);
    cudaGetSymbolAddress((void**)&src,    g_src);
    cudaGetSymbolAddress((void**)&nrm,    g_nrm);
    cudaGetSymbolAddress((void**)&rcnt,   g_rcnt);
    cudaGetSymbolAddress((void**)&mask,   g_mask);
    cudaGetSymbolAddress((void**)&colTh,  g_colTh);
    cudaGetSymbolAddress((void**)&colTl,  g_colTl);
    cudaGetSymbolAddress((void**)&x0h,    g_x0h);
    cudaGetSymbolAddress((void**)&x0l,    g_x0l);
    cudaGetSymbolAddress((void**)&xhb,    g_xhb);
    cudaGetSymbolAddress((void**)&xlb,    g_xlb);
    cudaGetSymbolAddress((void**)&Wh,     g_Wh);
    cudaGetSymbolAddress((void**)&Wl,     g_Wl);

    static int attr_set = 0;
    if (!attr_set) {
        cudaFuncSetAttribute(gemm_mma2, cudaFuncAttributeMaxDynamicSharedMemorySize, 73728);
        cudaFuncSetAttribute(gemm_mma3, cudaFuncAttributeMaxDynamicSharedMemorySize, 73728);
        cudaFuncSetAttribute(x0gemm, cudaFuncAttributeMaxDynamicSharedMemorySize, 2 * XSTG);
        attr_set = 1;
    }

    // ---- front end (x0 path)
    colemb_kernel<<<MCOLS, DD>>>(pW1, pb1, pW2, pb2, colemb);
    maskbuild_kernel<<<NNODES, 256>>>(init, mask, rcnt);
    colembT_kernel<<<dim3(32, 8), dim3(32, 8)>>>(colemb, colTh, colTl);
    x0gemm<<<dim3(314, 2), 256, 2 * XSTG>>>(mask, colTh, colTl, rcnt, x0h, x0l);
    wconv_kernel<<<dim3(8, 8, 9), dim3(32, 8)>>>(Wb[0], Wb[1], Wb[2], Wh, Wl);

    // ---- graph prep (all branches; fast 3-phase scan)
    branch_init<<<dim3(NB, 1, 3), 256>>>(deg, hist);
    edge_count<<<dim3(EB, 1, 3), 256>>>(ei[0], ei[1], ei[2], ea[0], ea[1], ea[2], deg, hist);
    dinv_kernel<<<dim3(NB, 1, 3), 256>>>(deg, dinv);
    scanP1<<<3 * NB, 256>>>(hist, bsum);
    scanP2<<<1, 256>>>(bsum, bbase, start);
    scanP3<<<3 * NB, 256>>>(hist, bbase, start, cur);
    scatter_kernel<<<dim3(EB, 1, 3), 256>>>(ei[0], ei[1], ei[2], ea[0], ea[1], ea[2],
                                            dinv, cur, src, nrm);

    // ---- layer-0 GEMM batched across branches (Wh l-major: w'=0,1,2 -> [768][256])
    gemm_mma2<<<dim3(157, 6), 256, 73728>>>(x0h, x0l, Wh, Wl, h0, 768);

    // ---- layer-major schedule: per-layer aggs, then one batched GEMM for all branches
    for (int b = 0; b < 3; b++)
        agg_kernel<<<NNODES, 64>>>(h0 + b * DD, 768, src + b * NEDGE, nrm + b * NEDGE,
                                   start + b * (NNODES + 1), dinv + b * NNODES, bb[b],
                                   br[b], xhb + (size_t)b * NPAD * DD,
                                   xlb + (size_t)b * NPAD * DD, 1, 0);
    gemm_mma3<<<dim3(157, 2, 3), 256, 73728>>>(xhb, xlb, Wh, Wl, hb, 3);
    for (int b = 0; b < 3; b++)
        agg_kernel<<<NNODES, 64>>>(hb + (size_t)b * NPAD * DD, DD, src + b * NEDGE,
                                   nrm + b * NEDGE, start + b * (NNODES + 1),
                                   dinv + b * NNODES, bb[b] + DD,
                                   br[b], xhb + (size_t)b * NPAD * DD,
                                   xlb + (size_t)b * NPAD * DD, 1, 0);
    gemm_mma3<<<dim3(157, 2, 3), 256, 73728>>>(xhb, xlb, Wh, Wl, hb, 6);
    for (int b = 0; b < 3; b++)
        agg_kernel<<<NNODES, 64>>>(hb + (size_t)b * NPAD * DD, DD, src + b * NEDGE,
                                   nrm + b * NEDGE, start + b * (NNODES + 1),
                                   dinv + b * NNODES, bb[b] + 2 * DD,
                                   br[b], xhb, xlb, 0, 1);

    attn_kernel<<<NNODES, 256>>>(br[0], br[1], br[2], watt, out);
}